// round 7
// baseline (speedup 1.0000x reference)
#include <cuda_runtime.h>
#include <math.h>
#include <stdint.h>

#define Nn   4096
#define Tt   2048
#define Dd   256
#define H1d  128
#define H2d  32
#define NHd  4
#define CAP  96
#define LRELU_ALPHA 0.2f

// ------------------------- scratch (__device__ globals) --------------------
__device__ float g_Wh_c[NHd * Nn * Dd];
__device__ float g_Wh_t[NHd * Tt * Dd];
__device__ float g_f_c[NHd * Nn], g_g_c[NHd * Nn];
__device__ float g_f_t[NHd * Tt], g_g_t[NHd * Tt];
__device__ int   g_nbr_c[Nn * CAP];
__device__ float g_val_c[Nn * CAP];
__device__ int   g_cnt_c[Nn];
__device__ int   g_nbr_t[Tt * CAP];
__device__ float g_val_t[Tt * CAP];
__device__ int   g_cnt_t[Tt];
__device__ float g_concept[Nn * Dd];
__device__ float g_gtext[Tt * Dd];
__device__ float g_ctext[Nn * Dd];
__device__ float g_tmp1[Nn * H1d];
__device__ float g_h1[Nn * H1d];
__device__ float g_tmp2a[Nn * H2d];
__device__ float g_tmp2b[Nn * H2d];
// hi/lo planes: A operands [M,K]; B operands [N,K]
__device__ float g_x_h[Nn * Dd],        g_x_l[Nn * Dd];
__device__ float g_tx_h[Tt * Dd],       g_tx_l[Tt * Dd];
__device__ float g_tfT_h[Nn * Tt],      g_tfT_l[Nn * Tt];      // [N, T]
__device__ float g_gatWT_h[NHd * Dd * Dd], g_gatWT_l[NHd * Dd * Dd];
__device__ float g_tWT_h[NHd * Dd * Dd],   g_tWT_l[NHd * Dd * Dd];
__device__ float g_fcWcT_h[NHd * Dd * Dd], g_fcWcT_l[NHd * Dd * Dd];
__device__ float g_fcWtT_h[NHd * Dd * Dd], g_fcWtT_l[NHd * Dd * Dd];
__device__ float g_fusWT_h[Dd * Dd],    g_fusWT_l[Dd * Dd];
__device__ float g_gc1WT_h[Dd * H1d],   g_gc1WT_l[Dd * H1d];
__device__ float g_hcatc_h[Nn * NHd * Dd], g_hcatc_l[Nn * NHd * Dd];
__device__ float g_hcatt_h[Tt * NHd * Dd], g_hcatt_l[Tt * NHd * Dd];
__device__ float g_gtextT_h[Tt * Dd],   g_gtextT_l[Tt * Dd];   // [D, T]
__device__ float g_fused_h[Nn * Dd],    g_fused_l[Nn * Dd];
__device__ float g_fusion_h[Nn * Dd],   g_fusion_l[Nn * Dd];
__device__ float g_mu_h[Nn * H2d],      g_mu_l[Nn * H2d];

// ------------------------- tf32 helpers ------------------------------------
__device__ __forceinline__ void tf32_split_u(float v, uint32_t& h, uint32_t& l) {
    asm("cvt.rna.tf32.f32 %0, %1;" : "=r"(h) : "f"(v));
    float r = v - __uint_as_float(h);
    asm("cvt.rna.tf32.f32 %0, %1;" : "=r"(l) : "f"(r));
}
__device__ __forceinline__ void split_store(float v, float* hp, float* lp, size_t idx) {
    uint32_t h, l; tf32_split_u(v, h, l);
    hp[idx] = __uint_as_float(h); lp[idx] = __uint_as_float(l);
}

#define MMA_TF32(c, a, b)                                                         \
    asm volatile(                                                                  \
        "mma.sync.aligned.m16n8k8.row.col.f32.tf32.tf32.f32 "                      \
        "{%0,%1,%2,%3},{%4,%5,%6,%7},{%8,%9},{%0,%1,%2,%3};"                       \
        : "+f"((c)[0]), "+f"((c)[1]), "+f"((c)[2]), "+f"((c)[3])                   \
        : "r"((a)[0]), "r"((a)[1]), "r"((a)[2]), "r"((a)[3]),                      \
          "r"((b)[0]), "r"((b)[1]))

#define LDSM4(r0, r1, r2, r3, addr)                                                \
    asm volatile("ldmatrix.sync.aligned.m8n8.x4.shared.b16 {%0,%1,%2,%3}, [%4];"   \
        : "=r"(r0), "=r"(r1), "=r"(r2), "=r"(r3) : "r"(addr))

__device__ __forceinline__ void cp16(void* sp, const void* gp) {
    uint32_t s = (uint32_t)__cvta_generic_to_shared(sp);
    asm volatile("cp.async.cg.shared.global [%0], [%1], 16;" :: "r"(s), "l"(gp));
}

// ------------------------- split (no transpose): x, t_x --------------------
struct SplitJob { const float* src; float* hi; float* lo; int n4; };
struct SplitJobs2 { SplitJob j[2]; };
__global__ void split_all_kernel(SplitJobs2 jobs) {
    SplitJob jb = jobs.j[blockIdx.y];
    const float4* src = (const float4*)jb.src;
    float4* hi = (float4*)jb.hi;
    float4* lo = (float4*)jb.lo;
    for (int i = blockIdx.x * blockDim.x + threadIdx.x; i < jb.n4;
         i += gridDim.x * blockDim.x) {
        float4 v = src[i];
        uint32_t h, l;
        float4 vh, vl;
        tf32_split_u(v.x, h, l); vh.x = __uint_as_float(h); vl.x = __uint_as_float(l);
        tf32_split_u(v.y, h, l); vh.y = __uint_as_float(h); vl.y = __uint_as_float(l);
        tf32_split_u(v.z, h, l); vh.z = __uint_as_float(h); vl.z = __uint_as_float(l);
        tf32_split_u(v.w, h, l); vh.w = __uint_as_float(h); vl.w = __uint_as_float(l);
        hi[i] = vh; lo[i] = vl;
    }
}

// ------------------------- transpose+split: [K,N] -> [N,K] hi/lo -----------
struct TJob { const float* src; float* hi; float* lo; int K; int N; int batch; };
struct TJobs7 { TJob j[7]; };

__device__ __forceinline__ void transpose_tile_body(const TJob& jb, int b) {
    size_t stride = (size_t)jb.K * jb.N;
    const float* src = jb.src + b * stride;
    float* hi = jb.hi + b * stride;
    float* lo = jb.lo + b * stride;
    __shared__ float th[32][33], tl[32][33];
    int ntn = jb.N / 32, ntk = jb.K / 32;
    for (int tile = blockIdx.x; tile < ntn * ntk; tile += gridDim.x) {
        int tk = tile / ntn, tn = tile - tk * ntn;
        int k0 = tk * 32, n0 = tn * 32;
        #pragma unroll
        for (int i = 0; i < 4; i++) {
            int k = threadIdx.y + i * 8;
            float v = src[(size_t)(k0 + k) * jb.N + n0 + threadIdx.x];
            uint32_t h, l; tf32_split_u(v, h, l);
            th[k][threadIdx.x] = __uint_as_float(h);
            tl[k][threadIdx.x] = __uint_as_float(l);
        }
        __syncthreads();
        #pragma unroll
        for (int i = 0; i < 4; i++) {
            int n = threadIdx.y + i * 8;
            hi[(size_t)(n0 + n) * jb.K + k0 + threadIdx.x] = th[threadIdx.x][n];
            lo[(size_t)(n0 + n) * jb.K + k0 + threadIdx.x] = tl[threadIdx.x][n];
        }
        __syncthreads();
    }
}
__global__ void transpose_split_kernel(TJobs7 jobs) {
    TJob jb = jobs.j[blockIdx.y];
    int b = blockIdx.z;
    if (b >= jb.batch) return;
    transpose_tile_body(jb, b);
}
__global__ void transpose_split_one_kernel(TJob jb) {
    transpose_tile_body(jb, 0);
}

// ------------------------- CSR build: two-pass warp-strip ------------------
__global__ void build_csr_kernel(const float* __restrict__ adj, int n,
                                 int* __restrict__ nbr, float* __restrict__ val,
                                 int* __restrict__ cnt) {
    int i = blockIdx.x;
    const float* row = adj + (size_t)i * n;
    int t = threadIdx.x, lane = t & 31, w = t >> 5;
    int strip = n >> 3;
    int s0 = w * strip;
    __shared__ int s_cnt[8];
    int my = 0;
    for (int b = s0; b < s0 + strip; b += 32) {
        bool p = row[b + lane] > 0.0f;
        unsigned m = __ballot_sync(0xffffffffu, p);
        my += __popc(m);
    }
    if (lane == 0) s_cnt[w] = my;
    __syncthreads();
    int off = 0;
    #pragma unroll
    for (int ww = 0; ww < 8; ww++) if (ww < w) off += s_cnt[ww];
    int tot = 0;
    #pragma unroll
    for (int ww = 0; ww < 8; ww++) tot += s_cnt[ww];
    for (int b = s0; b < s0 + strip; b += 32) {
        float v = row[b + lane];
        bool p = v > 0.0f;
        unsigned m = __ballot_sync(0xffffffffu, p);
        int pos = off + __popc(m & ((1u << lane) - 1u));
        if (p && pos < CAP) { nbr[i * CAP + pos] = b + lane; val[i * CAP + pos] = v; }
        off += __popc(m);
    }
    if (t == 0) cnt[i] = min(tot, CAP);
}

// ------------------------- tensor-core GEMM, LDSM, 2-stage -----------------
// C = A @ B^T (+bias); A planes [M,K], B planes [N,K], row-major.
// M%128==0, N%64==0, K%16==0. Batched over blockIdx.z.
#define BMt 128
#define BNt 64
#define BKt 16
#define SKt (BKt + 4)   // 20-float stride: LDSM-conflict-free

__global__ void __launch_bounds__(256) mma_gemm_kernel(
    const float* __restrict__ Ah, const float* __restrict__ Al,
    const float* __restrict__ Bh, const float* __restrict__ Bl,
    const float* __restrict__ bias, float* __restrict__ C,
    float* __restrict__ Ch, float* __restrict__ Cl,
    int M, int N, int K, size_t sA, size_t sB, size_t sC) {
    __shared__ float As[2][2][BMt][SKt];
    __shared__ float Bs[2][2][BNt][SKt];

    const float* Abp[2] = { Ah + (size_t)blockIdx.z * sA, Al + (size_t)blockIdx.z * sA };
    const float* Bbp[2] = { Bh + (size_t)blockIdx.z * sB, Bl + (size_t)blockIdx.z * sB };
    int bm = blockIdx.y * BMt, bn = blockIdx.x * BNt;
    int t = threadIdx.x, lane = t & 31, w = t >> 5;
    int wm = (w & 3) * 32, wn = (w >> 2) * 32;
    int gid = lane >> 2, tig = lane & 3;

    float acc[2][4][4] = {};

    uint32_t a_off[2], b_off[2];
    #pragma unroll
    for (int mt = 0; mt < 2; mt++)
        a_off[mt] = ((wm + mt * 16 + (lane & 15)) * SKt + (lane >> 4) * 4) * 4;
    #pragma unroll
    for (int pr = 0; pr < 2; pr++)
        b_off[pr] = ((wn + pr * 16 + (lane & 7) + ((lane & 16) ? 8 : 0)) * SKt +
                     ((lane & 8) ? 4 : 0)) * 4;

    auto load_tile = [&](int s, int k0) {
        #pragma unroll
        for (int p = 0; p < 2; p++) {
            #pragma unroll
            for (int j = 0; j < 2; j++) {
                int idx = t + j * 256;
                int row = idx >> 2;            // 0..127 (m)
                int col = (idx & 3) * 4;       // 0..12  (k)
                cp16(&As[s][p][row][col], Abp[p] + (size_t)(bm + row) * K + k0 + col);
            }
            {
                int row = t >> 2;              // 0..63 (n)
                int col = (t & 3) * 4;
                cp16(&Bs[s][p][row][col], Bbp[p] + (size_t)(bn + row) * K + k0 + col);
            }
        }
    };

    int nk = K / BKt;
    load_tile(0, 0);
    asm volatile("cp.async.commit_group;");

    for (int kt = 0; kt < nk; kt++) {
        int s = kt & 1;
        if (kt + 1 < nk) {
            load_tile(s ^ 1, (kt + 1) * BKt);
            asm volatile("cp.async.commit_group;");
            asm volatile("cp.async.wait_group 1;");
        } else {
            asm volatile("cp.async.wait_group 0;");
        }
        __syncthreads();

        uint32_t aB[2], bB[2];
        aB[0] = (uint32_t)__cvta_generic_to_shared(&As[s][0][0][0]);
        aB[1] = (uint32_t)__cvta_generic_to_shared(&As[s][1][0][0]);
        bB[0] = (uint32_t)__cvta_generic_to_shared(&Bs[s][0][0][0]);
        bB[1] = (uint32_t)__cvta_generic_to_shared(&Bs[s][1][0][0]);

        #pragma unroll
        for (int kk = 0; kk < BKt; kk += 8) {
            uint32_t ah[2][4], al[2][4], bh[4][2], bl[4][2];
            #pragma unroll
            for (int mt = 0; mt < 2; mt++) {
                LDSM4(ah[mt][0], ah[mt][1], ah[mt][2], ah[mt][3],
                      aB[0] + a_off[mt] + kk * 4);
                LDSM4(al[mt][0], al[mt][1], al[mt][2], al[mt][3],
                      aB[1] + a_off[mt] + kk * 4);
            }
            LDSM4(bh[0][0], bh[0][1], bh[1][0], bh[1][1], bB[0] + b_off[0] + kk * 4);
            LDSM4(bh[2][0], bh[2][1], bh[3][0], bh[3][1], bB[0] + b_off[1] + kk * 4);
            LDSM4(bl[0][0], bl[0][1], bl[1][0], bl[1][1], bB[1] + b_off[0] + kk * 4);
            LDSM4(bl[2][0], bl[2][1], bl[3][0], bl[3][1], bB[1] + b_off[1] + kk * 4);

            #pragma unroll
            for (int mt = 0; mt < 2; mt++)
                #pragma unroll
                for (int nt = 0; nt < 4; nt++) {
                    MMA_TF32(acc[mt][nt], al[mt], bh[nt]);
                    MMA_TF32(acc[mt][nt], ah[mt], bl[nt]);
                    MMA_TF32(acc[mt][nt], ah[mt], bh[nt]);
                }
        }
        __syncthreads();
    }

    float* Cb  = C  ? C  + (size_t)blockIdx.z * sC : nullptr;
    float* Chb = Ch ? Ch + (size_t)blockIdx.z * sC : nullptr;
    float* Clb = Cl ? Cl + (size_t)blockIdx.z * sC : nullptr;
    #pragma unroll
    for (int mt = 0; mt < 2; mt++) {
        int row0 = bm + wm + mt * 16 + gid;
        #pragma unroll
        for (int nt = 0; nt < 4; nt++) {
            int col = bn + wn + nt * 8 + tig * 2;
            float bx = bias ? bias[col] : 0.0f;
            float by = bias ? bias[col + 1] : 0.0f;
            float v00 = acc[mt][nt][0] + bx, v01 = acc[mt][nt][1] + by;
            float v10 = acc[mt][nt][2] + bx, v11 = acc[mt][nt][3] + by;
            size_t i0 = (size_t)row0 * N + col;
            size_t i1 = (size_t)(row0 + 8) * N + col;
            if (Cb) {
                *reinterpret_cast<float2*>(&Cb[i0]) = make_float2(v00, v01);
                *reinterpret_cast<float2*>(&Cb[i1]) = make_float2(v10, v11);
            }
            if (Chb) {
                uint32_t h, l;
                float2 h0, l0, h1, l1;
                tf32_split_u(v00, h, l); h0.x = __uint_as_float(h); l0.x = __uint_as_float(l);
                tf32_split_u(v01, h, l); h0.y = __uint_as_float(h); l0.y = __uint_as_float(l);
                tf32_split_u(v10, h, l); h1.x = __uint_as_float(h); l1.x = __uint_as_float(l);
                tf32_split_u(v11, h, l); h1.y = __uint_as_float(h); l1.y = __uint_as_float(l);
                *reinterpret_cast<float2*>(&Chb[i0]) = h0;
                *reinterpret_cast<float2*>(&Clb[i0]) = l0;
                *reinterpret_cast<float2*>(&Chb[i1]) = h1;
                *reinterpret_cast<float2*>(&Clb[i1]) = l1;
            }
        }
    }
}

// ------------------------- gc2 & gc3 fused SIMT GEMM -----------------------
__global__ void gc23_kernel(const float* __restrict__ A, const float* __restrict__ B2,
                            const float* __restrict__ B3, float* __restrict__ C2,
                            float* __restrict__ C3) {
    __shared__ __align__(16) float As[16][64];
    __shared__ __align__(16) float Bs[16][64];
    int bm = blockIdx.x * 64;
    int t = threadIdx.x, tx = t & 15, ty = t >> 4;
    float acc[4][4] = {};
    for (int k0 = 0; k0 < H1d; k0 += 16) {
        #pragma unroll
        for (int j = 0; j < 4; j++) {
            int li = t + j * 256;
            int r = li >> 4, c = li & 15;
            As[c][r] = A[(size_t)(bm + r) * H1d + k0 + c];
            int rb = li >> 6, cb = li & 63;
            Bs[rb][cb] = (cb < 32) ? B2[(k0 + rb) * H2d + cb]
                                   : B3[(k0 + rb) * H2d + cb - 32];
        }
        __syncthreads();
        #pragma unroll
        for (int k = 0; k < 16; k++) {
            float4 a4 = *reinterpret_cast<const float4*>(&As[k][ty << 2]);
            float4 b4 = *reinterpret_cast<const float4*>(&Bs[k][tx << 2]);
            float a[4] = {a4.x, a4.y, a4.z, a4.w};
            float b[4] = {b4.x, b4.y, b4.z, b4.w};
            #pragma unroll
            for (int u = 0; u < 4; u++)
                #pragma unroll
                for (int v = 0; v < 4; v++)
                    acc[u][v] += a[u] * b[v];
        }
        __syncthreads();
    }
    #pragma unroll
    for (int u = 0; u < 4; u++) {
        int row = bm + (ty << 2) + u;
        #pragma unroll
        for (int v = 0; v < 4; v++) {
            int col = (tx << 2) + v;
            if (col < 32) C2[(size_t)row * H2d + col] = acc[u][v];
            else          C3[(size_t)row * H2d + col - 32] = acc[u][v];
        }
    }
}

// ------------------------- f/g projections ---------------------------------
__global__ void fg_kernel(const float* __restrict__ Wh, const float* __restrict__ asrc,
                          const float* __restrict__ adst, float* __restrict__ f,
                          float* __restrict__ g, int n) {
    int gw = (blockIdx.x * blockDim.x + threadIdx.x) >> 5;
    int lane = threadIdx.x & 31;
    if (gw >= NHd * n) return;
    int h = gw / n, i = gw - h * n;
    const float* w  = Wh + ((size_t)h * n + i) * Dd;
    const float* as = asrc + h * Dd;
    const float* ad = adst + h * Dd;
    float accf = 0.0f, accg = 0.0f;
    #pragma unroll
    for (int c = 0; c < Dd / 32; c++) {
        float v = w[lane + 32 * c];
        accf += v * as[lane + 32 * c];
        accg += v * ad[lane + 32 * c];
    }
    #pragma unroll
    for (int o = 16; o; o >>= 1) {
        accf += __shfl_down_sync(0xffffffffu, accf, o);
        accg += __shfl_down_sync(0xffffffffu, accg, o);
    }
    if (lane == 0) { f[gw] = accf; g[gw] = accg; }
}

// ------------------------- warp-per-(i,h) GAT attention --------------------
__global__ void __launch_bounds__(256) gat_attn_warp_kernel(
    const float* __restrict__ Wh, const float* __restrict__ f,
    const float* __restrict__ g, const int* __restrict__ nbr,
    const int* __restrict__ cnt, float* __restrict__ hcat_h,
    float* __restrict__ hcat_l, int n) {
    int w = threadIdx.x >> 5, lane = threadIdx.x & 31;
    int gw = blockIdx.x * 8 + w;
    int i = gw >> 2, h = gw & 3;
    __shared__ int   sj[8][CAP];
    __shared__ float sw[8][CAP];
    int c = cnt[i];
    const int* jb = nbr + i * CAP;
    float fi = f[h * n + i];
    float m = -1e30f;
    for (int k = lane; k < c; k += 32) {
        int j = jb[k];
        sj[w][k] = j;
        float s = fi + g[h * n + j];
        s = (s >= 0.0f) ? s : LRELU_ALPHA * s;
        sw[w][k] = s;
        m = fmaxf(m, s);
    }
    #pragma unroll
    for (int o = 16; o; o >>= 1) m = fmaxf(m, __shfl_xor_sync(0xffffffffu, m, o));
    __syncwarp();
    float sum = 0.0f;
    for (int k = lane; k < c; k += 32) {
        float e = expf(sw[w][k] - m);
        sw[w][k] = e;
        sum += e;
    }
    #pragma unroll
    for (int o = 16; o; o >>= 1) sum += __shfl_xor_sync(0xffffffffu, sum, o);
    float dinv = 1.0f / sum;
    __syncwarp();
    const float* base = Wh + (size_t)h * n * Dd;
    float acc[8] = {};
    int k = 0;
    for (; k + 2 <= c; k += 2) {
        float w0 = sw[w][k], w1 = sw[w][k + 1];
        const float* r0 = base + (size_t)sj[w][k] * Dd + lane;
        const float* r1 = base + (size_t)sj[w][k + 1] * Dd + lane;
        #pragma unroll
        for (int ch = 0; ch < 8; ch++) {
            acc[ch] += w0 * __ldg(r0 + ch * 32);
            acc[ch] += w1 * __ldg(r1 + ch * 32);
        }
    }
    if (k < c) {
        float w0 = sw[w][k];
        const float* r0 = base + (size_t)sj[w][k] * Dd + lane;
        #pragma unroll
        for (int ch = 0; ch < 8; ch++) acc[ch] += w0 * __ldg(r0 + ch * 32);
    }
    size_t obase = (size_t)i * (NHd * Dd) + h * Dd + lane;
    #pragma unroll
    for (int ch = 0; ch < 8; ch++) {
        float v = acc[ch] * dinv;
        v = (v > 0.0f) ? v : expm1f(v);
        split_store(v, hcat_h, hcat_l, obase + ch * 32);
    }
}

// ------------------------- gated fusion elementwise ------------------------
__global__ void fuse_kernel(const float* __restrict__ a, const float* __restrict__ b,
                            float* __restrict__ out_h, float* __restrict__ out_l,
                            int total) {
    int idx = blockIdx.x * blockDim.x + threadIdx.x;
    if (idx < total) {
        float ca = a[idx], cb = b[idx];
        float z = 1.0f / (1.0f + expf(-(ca + cb)));
        split_store(z * ca + (1.0f - z) * cb, out_h, out_l, idx);
    }
}

// ------------------------- sparse adj @ X, optional ReLU -------------------
__global__ void spmm_kernel(const int* __restrict__ nbr, const float* __restrict__ val,
                            const int* __restrict__ cnt, const float* __restrict__ X,
                            float* __restrict__ Y, int ncols, int do_relu) {
    int i = blockIdx.x;
    int t = threadIdx.x;
    int c = cnt[i];
    const int* jb = nbr + i * CAP;
    const float* vb = val + i * CAP;
    float a0 = 0.0f, a1 = 0.0f, a2 = 0.0f, a3 = 0.0f;
    int k = 0;
    for (; k + 4 <= c; k += 4) {
        a0 += vb[k]     * __ldg(X + (size_t)jb[k]     * ncols + t);
        a1 += vb[k + 1] * __ldg(X + (size_t)jb[k + 1] * ncols + t);
        a2 += vb[k + 2] * __ldg(X + (size_t)jb[k + 2] * ncols + t);
        a3 += vb[k + 3] * __ldg(X + (size_t)jb[k + 3] * ncols + t);
    }
    for (; k < c; k++)
        a0 += vb[k] * __ldg(X + (size_t)jb[k] * ncols + t);
    float acc = (a0 + a1) + (a2 + a3);
    if (do_relu) acc = fmaxf(acc, 0.0f);
    Y[(size_t)i * ncols + t] = acc;
}

// ------------------------- fused mu/logvar spmm ----------------------------
__global__ void spmm2_kernel(const int* __restrict__ nbr, const float* __restrict__ val,
                             const int* __restrict__ cnt, const float* __restrict__ X2,
                             const float* __restrict__ X3, float* __restrict__ mu,
                             float* __restrict__ logvar, float* __restrict__ mu_h,
                             float* __restrict__ mu_l) {
    int i = blockIdx.x;
    int t = threadIdx.x;
    int sel = t >> 5, col = t & 31;
    const float* X = sel ? X3 : X2;
    int c = cnt[i];
    const int* jb = nbr + i * CAP;
    const float* vb = val + i * CAP;
    float a0 = 0.0f, a1 = 0.0f, a2 = 0.0f, a3 = 0.0f;
    int k = 0;
    for (; k + 4 <= c; k += 4) {
        a0 += vb[k]     * __ldg(X + (size_t)jb[k]     * H2d + col);
        a1 += vb[k + 1] * __ldg(X + (size_t)jb[k + 1] * H2d + col);
        a2 += vb[k + 2] * __ldg(X + (size_t)jb[k + 2] * H2d + col);
        a3 += vb[k + 3] * __ldg(X + (size_t)jb[k + 3] * H2d + col);
    }
    for (; k < c; k++)
        a0 += vb[k] * __ldg(X + (size_t)jb[k] * H2d + col);
    float v = (a0 + a1) + (a2 + a3);
    size_t idx = (size_t)i * H2d + col;
    if (sel == 0) {
        mu[idx] = v;
        split_store(v, mu_h, mu_l, idx);
    } else {
        logvar[idx] = v;
    }
}

// ------------------------- host-side launch helpers ------------------------
struct GemmArgs {
    const float *Ah, *Al, *Bh, *Bl, *bias;
    float *C, *Ch, *Cl;
};
static inline void run_nt(GemmArgs a, int M, int N, int K, int batch = 1,
                          size_t sA = 0, size_t sB = 0, size_t sC = 0) {
    dim3 grid(N / BNt, M / BMt, batch);
    mma_gemm_kernel<<<grid, 256>>>(a.Ah, a.Al, a.Bh, a.Bl, a.bias,
                                   a.C, a.Ch, a.Cl, M, N, K, sA, sB, sC);
}

#define SYM(p, s) cudaGetSymbolAddress((void**)&p, s)

extern "C" void kernel_launch(void* const* d_in, const int* in_sizes, int n_in,
                              void* d_out, int out_size) {
    const float* x        = (const float*)d_in[0];
    const float* adj      = (const float*)d_in[1];
    const float* t_x      = (const float*)d_in[2];
    const float* t_adj    = (const float*)d_in[3];
    const float* tfidf    = (const float*)d_in[4];
    const float* gat_W    = (const float*)d_in[5];
    const float* gat_asrc = (const float*)d_in[6];
    const float* gat_adst = (const float*)d_in[7];
    const float* gat_fcW  = (const float*)d_in[8];
    const float* gat_fcb  = (const float*)d_in[9];
    const float* t_W      = (const float*)d_in[10];
    const float* t_asrc   = (const float*)d_in[11];
    const float* t_adst   = (const float*)d_in[12];
    const float* t_fcW    = (const float*)d_in[13];
    const float* t_fcb    = (const float*)d_in[14];
    const float* fus_W    = (const float*)d_in[15];
    const float* fus_b    = (const float*)d_in[16];
    const float* gc1_W    = (const float*)d_in[17];
    const float* gc2_W    = (const float*)d_in[18];
    const float* gc3_W    = (const float*)d_in[19];

    float* out    = (float*)d_out;
    float* mu     = out + (size_t)Nn * Nn;
    float* logvar = mu + (size_t)Nn * H2d;

    float *Wh_c, *Wh_t, *f_c, *g_c, *f_t, *g_t, *val_c, *val_t;
    float *concept, *gtext, *ctext, *tmp1, *h1, *tmp2a, *tmp2b;
    int *nbr_c, *cnt_c, *nbr_t, *cnt_t;
    float *x_h, *x_l, *tx_h, *tx_l, *tfT_h, *tfT_l;
    float *gatWT_h, *gatWT_l, *tWT_h, *tWT_l, *fcWcT_h, *fcWcT_l, *fcWtT_h, *fcWtT_l;
    float *fusWT_h, *fusWT_l, *gc1WT_h, *gc1WT_l;
    float *hcatc_h, *hcatc_l, *hcatt_h, *hcatt_l, *gtextT_h, *gtextT_l;
    float *fused_h, *fused_l, *fusion_h, *fusion_l, *mu_h, *mu_l;
    SYM(Wh_c, g_Wh_c);  SYM(Wh_t, g_Wh_t);
    SYM(f_c, g_f_c);    SYM(g_c, g_g_c);   SYM(f_t, g_f_t);  SYM(g_t, g_g_t);
    SYM(nbr_c, g_nbr_c); SYM(val_c, g_val_c); SYM(cnt_c, g_cnt_c);
    SYM(nbr_t, g_nbr_t); SYM(val_t, g_val_t); SYM(cnt_t, g_cnt_t);
    SYM(concept, g_concept); SYM(gtext, g_gtext); SYM(ctext, g_ctext);
    SYM(tmp1, g_tmp1); SYM(h1, g_h1); SYM(tmp2a, g_tmp2a); SYM(tmp2b, g_tmp2b);
    SYM(x_h, g_x_h);   SYM(x_l, g_x_l);  SYM(tx_h, g_tx_h); SYM(tx_l, g_tx_l);
    SYM(tfT_h, g_tfT_h); SYM(tfT_l, g_tfT_l);
    SYM(gatWT_h, g_gatWT_h); SYM(gatWT_l, g_gatWT_l);
    SYM(tWT_h, g_tWT_h);     SYM(tWT_l, g_tWT_l);
    SYM(fcWcT_h, g_fcWcT_h); SYM(fcWcT_l, g_fcWcT_l);
    SYM(fcWtT_h, g_fcWtT_h); SYM(fcWtT_l, g_fcWtT_l);
    SYM(fusWT_h, g_fusWT_h); SYM(fusWT_l, g_fusWT_l);
    SYM(gc1WT_h, g_gc1WT_h); SYM(gc1WT_l, g_gc1WT_l);
    SYM(hcatc_h, g_hcatc_h); SYM(hcatc_l, g_hcatc_l);
    SYM(hcatt_h, g_hcatt_h); SYM(hcatt_l, g_hcatt_l);
    SYM(gtextT_h, g_gtextT_h); SYM(gtextT_l, g_gtextT_l);
    SYM(fused_h, g_fused_h); SYM(fused_l, g_fused_l);
    SYM(fusion_h, g_fusion_h); SYM(fusion_l, g_fusion_l);
    SYM(mu_h, g_mu_h); SYM(mu_l, g_mu_l);

    // 0a) split x, t_x (A operands, no transpose)
    {
        SplitJobs2 jobs;
        jobs.j[0] = { x,   x_h,  x_l,  Nn * Dd / 4 };
        jobs.j[1] = { t_x, tx_h, tx_l, Tt * Dd / 4 };
        split_all_kernel<<<dim3(160, 2), 256>>>(jobs);
    }
    // 0b) transpose+split weights -> [N,K] and tfidf -> [N,T]
    {
        TJobs7 jobs;
        jobs.j[0] = { gat_W,   gatWT_h, gatWT_l, Dd, Dd, NHd };
        jobs.j[1] = { t_W,     tWT_h,   tWT_l,   Dd, Dd, NHd };
        jobs.j[2] = { gat_fcW, fcWcT_h, fcWcT_l, NHd * Dd, Dd, 1 };
        jobs.j[3] = { t_fcW,   fcWtT_h, fcWtT_l, NHd * Dd, Dd, 1 };
        jobs.j[4] = { fus_W,   fusWT_h, fusWT_l, Dd, Dd, 1 };
        jobs.j[5] = { gc1_W,   gc1WT_h, gc1WT_l, Dd, H1d, 1 };
        jobs.j[6] = { tfidf,   tfT_h,   tfT_l,   Tt, Nn, 1 };
        transpose_split_kernel<<<dim3(256, 7, 4), dim3(32, 8)>>>(jobs);
    }

    // 1) adjacency -> CSR
    build_csr_kernel<<<Nn, 256>>>(adj, Nn, nbr_c, val_c, cnt_c);
    build_csr_kernel<<<Tt, 256>>>(t_adj, Tt, nbr_t, val_t, cnt_t);

    // 2) per-head Wh = x @ W[h]  (batched over heads)
    run_nt({x_h, x_l, gatWT_h, gatWT_l, nullptr, Wh_c, nullptr, nullptr},
           Nn, Dd, Dd, NHd, 0, (size_t)Dd * Dd, (size_t)Nn * Dd);
    run_nt({tx_h, tx_l, tWT_h, tWT_l, nullptr, Wh_t, nullptr, nullptr},
           Tt, Dd, Dd, NHd, 0, (size_t)Dd * Dd, (size_t)Tt * Dd);

    // 3) attention projections f,g
    fg_kernel<<<(NHd * Nn * 32 + 255) / 256, 256>>>(Wh_c, gat_asrc, gat_adst, f_c, g_c, Nn);
    fg_kernel<<<(NHd * Tt * 32 + 255) / 256, 256>>>(Wh_t, t_asrc, t_adst, f_t, g_t, Tt);

    // 4) sparse attention + aggregation + ELU -> hcat hi/lo planes
    gat_attn_warp_kernel<<<Nn * NHd / 8, 256>>>(Wh_c, f_c, g_c, nbr_c, cnt_c,
                                                hcatc_h, hcatc_l, Nn);
    gat_attn_warp_kernel<<<Tt * NHd / 8, 256>>>(Wh_t, f_t, g_t, nbr_t, cnt_t,
                                                hcatt_h, hcatt_l, Tt);

    // 5) output fc per graph (raw outputs)
    run_nt({hcatc_h, hcatc_l, fcWcT_h, fcWcT_l, gat_fcb, concept, nullptr, nullptr},
           Nn, Dd, NHd * Dd);
    run_nt({hcatt_h, hcatt_l, fcWtT_h, fcWtT_l, t_fcb, gtext, nullptr, nullptr},
           Tt, Dd, NHd * Dd);

    // 5b) transpose+split gtext [T,D] -> [D,T] planes (B operand for tfidf GEMM)
    transpose_split_one_kernel<<<128, dim3(32, 8)>>>(
        TJob{ gtext, gtextT_h, gtextT_l, Tt, Dd, 1 });

    // 6) c_text = tfidf^T @ gat_text   (A: tfT [N,T]; B: gtextT [D,T])
    run_nt({tfT_h, tfT_l, gtextT_h, gtextT_l, nullptr, ctext, nullptr, nullptr},
           Nn, Dd, Tt);

    // 7) gated fusion + fc
    fuse_kernel<<<(Nn * Dd + 255) / 256, 256>>>(concept, ctext, fused_h, fused_l, Nn * Dd);
    run_nt({fused_h, fused_l, fusWT_h, fusWT_l, fus_b, nullptr, fusion_h, fusion_l},
           Nn, Dd, Dd);

    // 8) GCN encoder
    run_nt({fusion_h, fusion_l, gc1WT_h, gc1WT_l, nullptr, tmp1, nullptr, nullptr},
           Nn, H1d, Dd);
    spmm_kernel<<<Nn, H1d>>>(nbr_c, val_c, cnt_c, tmp1, h1, H1d, 1);

    gc23_kernel<<<Nn / 64, 256>>>(h1, gc2_W, gc3_W, tmp2a, tmp2b);
    spmm2_kernel<<<Nn, 64>>>(nbr_c, val_c, cnt_c, tmp2a, tmp2b, mu, logvar, mu_h, mu_l);

    // 9) recon = mu @ mu^T  (mu planes [4096,32] serve as both A and B)
    run_nt({mu_h, mu_l, mu_h, mu_l, nullptr, out, nullptr, nullptr}, Nn, Nn, H2d);
}

// round 10
// speedup vs baseline: 1.1283x; 1.1283x over previous
#include <cuda_runtime.h>
#include <math.h>
#include <stdint.h>

#define Nn   4096
#define Tt   2048
#define Dd   256
#define H1d  128
#define H2d  32
#define NHd  4
#define CAP  96
#define LRELU_ALPHA 0.2f

// ------------------------- scratch (__device__ globals) --------------------
__device__ float g_Wh_c[NHd * Nn * Dd];
__device__ float g_Wh_t[NHd * Tt * Dd];
__device__ float g_f_c[NHd * Nn], g_g_c[NHd * Nn];
__device__ float g_f_t[NHd * Tt], g_g_t[NHd * Tt];
__device__ int   g_nbr_c[Nn * CAP];
__device__ float g_val_c[Nn * CAP];
__device__ int   g_cnt_c[Nn];
__device__ int   g_nbr_t[Tt * CAP];
__device__ float g_val_t[Tt * CAP];
__device__ int   g_cnt_t[Tt];
__device__ float g_concept[Nn * Dd];
__device__ float g_ctext[Nn * Dd];
__device__ float g_tmp1[Nn * H1d];
__device__ float g_h1[Nn * H1d];
__device__ float g_tmp2a[Nn * H2d];
__device__ float g_tmp2b[Nn * H2d];
// hi/lo planes: A operands [M,K]; B operands [K,N]  (NO transpose anywhere)
__device__ float g_x_h[Nn * Dd],        g_x_l[Nn * Dd];
__device__ float g_tx_h[Tt * Dd],       g_tx_l[Tt * Dd];
__device__ float g_tf_h[Tt * Nn],       g_tf_l[Tt * Nn];
__device__ float g_gatW_h[NHd * Dd * Dd], g_gatW_l[NHd * Dd * Dd];
__device__ float g_tW_h[NHd * Dd * Dd],   g_tW_l[NHd * Dd * Dd];
__device__ float g_fcWc_h[NHd * Dd * Dd], g_fcWc_l[NHd * Dd * Dd];
__device__ float g_fcWt_h[NHd * Dd * Dd], g_fcWt_l[NHd * Dd * Dd];
__device__ float g_fusW_h[Dd * Dd],     g_fusW_l[Dd * Dd];
__device__ float g_gc1W_h[Dd * H1d],    g_gc1W_l[Dd * H1d];
__device__ float g_hcatc_h[Nn * NHd * Dd], g_hcatc_l[Nn * NHd * Dd];
__device__ float g_hcatt_h[Tt * NHd * Dd], g_hcatt_l[Tt * NHd * Dd];
__device__ float g_gtext_h[Tt * Dd],    g_gtext_l[Tt * Dd];
__device__ float g_fused_h[Nn * Dd],    g_fused_l[Nn * Dd];
__device__ float g_fusion_h[Nn * Dd],   g_fusion_l[Nn * Dd];
__device__ float g_mu_h[Nn * H2d],      g_mu_l[Nn * H2d];

// ------------------------- tf32 helpers ------------------------------------
__device__ __forceinline__ void tf32_split_u(float v, uint32_t& h, uint32_t& l) {
    asm("cvt.rna.tf32.f32 %0, %1;" : "=r"(h) : "f"(v));
    float r = v - __uint_as_float(h);
    asm("cvt.rna.tf32.f32 %0, %1;" : "=r"(l) : "f"(r));
}
__device__ __forceinline__ void split_store(float v, float* hp, float* lp, size_t idx) {
    uint32_t h, l; tf32_split_u(v, h, l);
    hp[idx] = __uint_as_float(h); lp[idx] = __uint_as_float(l);
}

#define MMA_TF32(c, a, b)                                                         \
    asm volatile(                                                                  \
        "mma.sync.aligned.m16n8k8.row.col.f32.tf32.tf32.f32 "                      \
        "{%0,%1,%2,%3},{%4,%5,%6,%7},{%8,%9},{%0,%1,%2,%3};"                       \
        : "+f"((c)[0]), "+f"((c)[1]), "+f"((c)[2]), "+f"((c)[3])                   \
        : "r"((a)[0]), "r"((a)[1]), "r"((a)[2]), "r"((a)[3]),                      \
          "r"((b)[0]), "r"((b)[1]))

__device__ __forceinline__ void cp16(void* sp, const void* gp) {
    uint32_t s = (uint32_t)__cvta_generic_to_shared(sp);
    asm volatile("cp.async.cg.shared.global [%0], [%1], 16;" :: "r"(s), "l"(gp));
}

// ------------------------- split_all (harness inputs -> hi/lo, NO transpose)
struct SplitJob { const float* src; float* hi; float* lo; int n4; };
struct SplitJobs9 { SplitJob j[9]; };
__global__ void split_all_kernel(SplitJobs9 jobs) {
    SplitJob jb = jobs.j[blockIdx.y];
    const float4* src = (const float4*)jb.src;
    float4* hi = (float4*)jb.hi;
    float4* lo = (float4*)jb.lo;
    for (int i = blockIdx.x * blockDim.x + threadIdx.x; i < jb.n4;
         i += gridDim.x * blockDim.x) {
        float4 v = src[i];
        uint32_t h, l;
        float4 vh, vl;
        tf32_split_u(v.x, h, l); vh.x = __uint_as_float(h); vl.x = __uint_as_float(l);
        tf32_split_u(v.y, h, l); vh.y = __uint_as_float(h); vl.y = __uint_as_float(l);
        tf32_split_u(v.z, h, l); vh.z = __uint_as_float(h); vl.z = __uint_as_float(l);
        tf32_split_u(v.w, h, l); vh.w = __uint_as_float(h); vl.w = __uint_as_float(l);
        hi[i] = vh; lo[i] = vl;
    }
}

// ------------------------- merged CSR build (both graphs, one launch) ------
__global__ void build_csr2_kernel(const float* __restrict__ adj,
                                  const float* __restrict__ t_adj,
                                  int* __restrict__ nbr_c, float* __restrict__ val_c,
                                  int* __restrict__ cnt_c,
                                  int* __restrict__ nbr_t, float* __restrict__ val_t,
                                  int* __restrict__ cnt_t) {
    int bi = blockIdx.x;
    const float* row;
    int n, i;
    int* nbr; float* val; int* cnt;
    if (bi < Nn) {
        i = bi; n = Nn; row = adj + (size_t)i * Nn;
        nbr = nbr_c; val = val_c; cnt = cnt_c;
    } else {
        i = bi - Nn; n = Tt; row = t_adj + (size_t)i * Tt;
        nbr = nbr_t; val = val_t; cnt = cnt_t;
    }
    int t = threadIdx.x, lane = t & 31, w = t >> 5;
    int strip = n >> 3;
    int s0 = w * strip;
    __shared__ int s_cnt[8];
    int my = 0;
    for (int b = s0; b < s0 + strip; b += 32) {
        bool p = row[b + lane] > 0.0f;
        unsigned m = __ballot_sync(0xffffffffu, p);
        my += __popc(m);
    }
    if (lane == 0) s_cnt[w] = my;
    __syncthreads();
    int off = 0;
    #pragma unroll
    for (int ww = 0; ww < 8; ww++) if (ww < w) off += s_cnt[ww];
    int tot = 0;
    #pragma unroll
    for (int ww = 0; ww < 8; ww++) tot += s_cnt[ww];
    for (int b = s0; b < s0 + strip; b += 32) {
        float v = row[b + lane];
        bool p = v > 0.0f;
        unsigned m = __ballot_sync(0xffffffffu, p);
        int pos = off + __popc(m & ((1u << lane) - 1u));
        if (p && pos < CAP) { nbr[i * CAP + pos] = b + lane; val[i * CAP + pos] = v; }
        off += __popc(m);
    }
    if (t == 0) cnt[i] = min(tot, CAP);
}

// ------------------------- tensor-core GEMM on pre-split hi/lo -------------
// C = op(A) @ op(B) [+ bias]; operands given as tf32-hi/lo fp32 planes.
// op(A): TA ? A=[K,M] : A=[M,K]; op(B): TB ? B=[N,K] : B=[K,N] (row-major).
// M%128==0, N%64==0, K%16==0. Batched over blockIdx.z.
#define BMt 128
#define BNt 64
#define BKt 16

template <bool TA, bool TB>
__global__ void __launch_bounds__(256) mma_gemm_kernel(
    const float* __restrict__ Ah, const float* __restrict__ Al,
    const float* __restrict__ Bh, const float* __restrict__ Bl,
    const float* __restrict__ bias, float* __restrict__ C,
    float* __restrict__ Ch, float* __restrict__ Cl,
    int M, int N, int K, size_t sA, size_t sB, size_t sC) {
    constexpr int AR = TA ? BKt : BMt;
    constexpr int AC = TA ? (BMt + 8) : (BKt + 4);
    constexpr int BR = TB ? BNt : BKt;
    constexpr int BC = TB ? (BKt + 4) : (BNt + 8);
    __shared__ float As[2][2][AR][AC];   // [stage][plane][..][..]
    __shared__ float Bs[2][2][BR][BC];

    const float* Abp[2] = { Ah + (size_t)blockIdx.z * sA, Al + (size_t)blockIdx.z * sA };
    const float* Bbp[2] = { Bh + (size_t)blockIdx.z * sB, Bl + (size_t)blockIdx.z * sB };
    int bm = blockIdx.y * BMt, bn = blockIdx.x * BNt;
    int t = threadIdx.x, lane = t & 31, w = t >> 5;
    int wm = (w & 3) * 32, wn = (w >> 2) * 32;
    int gid = lane >> 2, tig = lane & 3;

    float acc[2][4][4] = {};

    auto load_tile = [&](int s, int k0) {
        #pragma unroll
        for (int p = 0; p < 2; p++) {
            if (!TA) {
                #pragma unroll
                for (int j = 0; j < 2; j++) {
                    int idx = t + j * 256;
                    int row = idx >> 2;
                    int col = (idx & 3) * 4;
                    cp16(&As[s][p][row][col], Abp[p] + (size_t)(bm + row) * K + k0 + col);
                }
            } else {
                #pragma unroll
                for (int j = 0; j < 2; j++) {
                    int idx = t + j * 256;
                    int row = idx >> 5;
                    int col = (idx & 31) * 4;
                    cp16(&As[s][p][row][col], Abp[p] + (size_t)(k0 + row) * M + bm + col);
                }
            }
            if (!TB) {
                int row = t >> 4;
                int col = (t & 15) * 4;
                cp16(&Bs[s][p][row][col], Bbp[p] + (size_t)(k0 + row) * N + bn + col);
            } else {
                int row = t >> 2;
                int col = (t & 3) * 4;
                cp16(&Bs[s][p][row][col], Bbp[p] + (size_t)(bn + row) * K + k0 + col);
            }
        }
    };

    auto Ae = [&](int s, int p, int k, int m) -> float {
        return TA ? As[s][p][k][m] : As[s][p][m][k];
    };
    auto Be = [&](int s, int p, int k, int nn) -> float {
        return TB ? Bs[s][p][nn][k] : Bs[s][p][k][nn];
    };

    int nk = K / BKt;
    load_tile(0, 0);
    asm volatile("cp.async.commit_group;");

    for (int kt = 0; kt < nk; kt++) {
        int s = kt & 1;
        if (kt + 1 < nk) {
            load_tile(s ^ 1, (kt + 1) * BKt);
            asm volatile("cp.async.commit_group;");
            asm volatile("cp.async.wait_group 1;");
        } else {
            asm volatile("cp.async.wait_group 0;");
        }
        __syncthreads();

        #pragma unroll
        for (int kk = 0; kk < BKt; kk += 8) {
            uint32_t ah[2][4], al[2][4], bh[4][2], bl[4][2];
            #pragma unroll
            for (int mt = 0; mt < 2; mt++) {
                int m0 = wm + mt * 16 + gid;
                ah[mt][0] = __float_as_uint(Ae(s, 0, kk + tig,     m0));
                ah[mt][1] = __float_as_uint(Ae(s, 0, kk + tig,     m0 + 8));
                ah[mt][2] = __float_as_uint(Ae(s, 0, kk + tig + 4, m0));
                ah[mt][3] = __float_as_uint(Ae(s, 0, kk + tig + 4, m0 + 8));
                al[mt][0] = __float_as_uint(Ae(s, 1, kk + tig,     m0));
                al[mt][1] = __float_as_uint(Ae(s, 1, kk + tig,     m0 + 8));
                al[mt][2] = __float_as_uint(Ae(s, 1, kk + tig + 4, m0));
                al[mt][3] = __float_as_uint(Ae(s, 1, kk + tig + 4, m0 + 8));
            }
            #pragma unroll
            for (int nt = 0; nt < 4; nt++) {
                int n0 = wn + nt * 8 + gid;
                bh[nt][0] = __float_as_uint(Be(s, 0, kk + tig,     n0));
                bh[nt][1] = __float_as_uint(Be(s, 0, kk + tig + 4, n0));
                bl[nt][0] = __float_as_uint(Be(s, 1, kk + tig,     n0));
                bl[nt][1] = __float_as_uint(Be(s, 1, kk + tig + 4, n0));
            }
            #pragma unroll
            for (int mt = 0; mt < 2; mt++)
                #pragma unroll
                for (int nt = 0; nt < 4; nt++) {
                    MMA_TF32(acc[mt][nt], al[mt], bh[nt]);
                    MMA_TF32(acc[mt][nt], ah[mt], bl[nt]);
                    MMA_TF32(acc[mt][nt], ah[mt], bh[nt]);
                }
        }
        __syncthreads();
    }

    float* Cb  = C  ? C  + (size_t)blockIdx.z * sC : nullptr;
    float* Chb = Ch ? Ch + (size_t)blockIdx.z * sC : nullptr;
    float* Clb = Cl ? Cl + (size_t)blockIdx.z * sC : nullptr;
    #pragma unroll
    for (int mt = 0; mt < 2; mt++) {
        int row0 = bm + wm + mt * 16 + gid;
        #pragma unroll
        for (int nt = 0; nt < 4; nt++) {
            int col = bn + wn + nt * 8 + tig * 2;
            float bx = bias ? bias[col] : 0.0f;
            float by = bias ? bias[col + 1] : 0.0f;
            float v00 = acc[mt][nt][0] + bx, v01 = acc[mt][nt][1] + by;
            float v10 = acc[mt][nt][2] + bx, v11 = acc[mt][nt][3] + by;
            size_t i0 = (size_t)row0 * N + col;
            size_t i1 = (size_t)(row0 + 8) * N + col;
            if (Cb) {
                *reinterpret_cast<float2*>(&Cb[i0]) = make_float2(v00, v01);
                *reinterpret_cast<float2*>(&Cb[i1]) = make_float2(v10, v11);
            }
            if (Chb) {
                uint32_t h, l;
                float2 h0, l0, h1, l1;
                tf32_split_u(v00, h, l); h0.x = __uint_as_float(h); l0.x = __uint_as_float(l);
                tf32_split_u(v01, h, l); h0.y = __uint_as_float(h); l0.y = __uint_as_float(l);
                tf32_split_u(v10, h, l); h1.x = __uint_as_float(h); l1.x = __uint_as_float(l);
                tf32_split_u(v11, h, l); h1.y = __uint_as_float(h); l1.y = __uint_as_float(l);
                *reinterpret_cast<float2*>(&Chb[i0]) = h0;
                *reinterpret_cast<float2*>(&Clb[i0]) = l0;
                *reinterpret_cast<float2*>(&Chb[i1]) = h1;
                *reinterpret_cast<float2*>(&Clb[i1]) = l1;
            }
        }
    }
}

// ------------------------- gc2 & gc3 fused SIMT GEMM -----------------------
__global__ void gc23_kernel(const float* __restrict__ A, const float* __restrict__ B2,
                            const float* __restrict__ B3, float* __restrict__ C2,
                            float* __restrict__ C3) {
    __shared__ __align__(16) float As[16][64];
    __shared__ __align__(16) float Bs[16][64];
    int bm = blockIdx.x * 64;
    int t = threadIdx.x, tx = t & 15, ty = t >> 4;
    float acc[4][4] = {};
    for (int k0 = 0; k0 < H1d; k0 += 16) {
        #pragma unroll
        for (int j = 0; j < 4; j++) {
            int li = t + j * 256;
            int r = li >> 4, c = li & 15;
            As[c][r] = A[(size_t)(bm + r) * H1d + k0 + c];
            int rb = li >> 6, cb = li & 63;
            Bs[rb][cb] = (cb < 32) ? B2[(k0 + rb) * H2d + cb]
                                   : B3[(k0 + rb) * H2d + cb - 32];
        }
        __syncthreads();
        #pragma unroll
        for (int k = 0; k < 16; k++) {
            float4 a4 = *reinterpret_cast<const float4*>(&As[k][ty << 2]);
            float4 b4 = *reinterpret_cast<const float4*>(&Bs[k][tx << 2]);
            float a[4] = {a4.x, a4.y, a4.z, a4.w};
            float b[4] = {b4.x, b4.y, b4.z, b4.w};
            #pragma unroll
            for (int u = 0; u < 4; u++)
                #pragma unroll
                for (int v = 0; v < 4; v++)
                    acc[u][v] += a[u] * b[v];
        }
        __syncthreads();
    }
    #pragma unroll
    for (int u = 0; u < 4; u++) {
        int row = bm + (ty << 2) + u;
        #pragma unroll
        for (int v = 0; v < 4; v++) {
            int col = (tx << 2) + v;
            if (col < 32) C2[(size_t)row * H2d + col] = acc[u][v];
            else          C3[(size_t)row * H2d + col - 32] = acc[u][v];
        }
    }
}

// ------------------------- merged f/g projections (both graphs) ------------
__global__ void fg2_kernel(const float* __restrict__ Wh_c, const float* __restrict__ asrc_c,
                           const float* __restrict__ adst_c, float* __restrict__ f_c,
                           float* __restrict__ g_c,
                           const float* __restrict__ Wh_t, const float* __restrict__ asrc_t,
                           const float* __restrict__ adst_t, float* __restrict__ f_t,
                           float* __restrict__ g_t) {
    int gw = (blockIdx.x * blockDim.x + threadIdx.x) >> 5;
    int lane = threadIdx.x & 31;
    const float* Wh; const float* asrc; const float* adst; float* f; float* g;
    int n;
    if (gw < NHd * Nn) {
        Wh = Wh_c; asrc = asrc_c; adst = adst_c; f = f_c; g = g_c; n = Nn;
    } else {
        gw -= NHd * Nn;
        if (gw >= NHd * Tt) return;
        Wh = Wh_t; asrc = asrc_t; adst = adst_t; f = f_t; g = g_t; n = Tt;
    }
    int h = gw / n, i = gw - h * n;
    const float* wp = Wh + ((size_t)h * n + i) * Dd;
    const float* as = asrc + h * Dd;
    const float* ad = adst + h * Dd;
    float accf = 0.0f, accg = 0.0f;
    #pragma unroll
    for (int c = 0; c < Dd / 32; c++) {
        float v = wp[lane + 32 * c];
        accf += v * as[lane + 32 * c];
        accg += v * ad[lane + 32 * c];
    }
    #pragma unroll
    for (int o = 16; o; o >>= 1) {
        accf += __shfl_down_sync(0xffffffffu, accf, o);
        accg += __shfl_down_sync(0xffffffffu, accg, o);
    }
    if (lane == 0) { f[gw] = accf; g[gw] = accg; }
}

// ------------------------- merged warp-per-(i,h) GAT attention -------------
__global__ void __launch_bounds__(256) gat_attn2_kernel(
    const float* __restrict__ Wh_c, const float* __restrict__ f_c,
    const float* __restrict__ g_c, const int* __restrict__ nbr_c,
    const int* __restrict__ cnt_c, float* __restrict__ hcatc_h,
    float* __restrict__ hcatc_l,
    const float* __restrict__ Wh_t, const float* __restrict__ f_t,
    const float* __restrict__ g_t, const int* __restrict__ nbr_t,
    const int* __restrict__ cnt_t, float* __restrict__ hcatt_h,
    float* __restrict__ hcatt_l) {
    int w = threadIdx.x >> 5, lane = threadIdx.x & 31;
    int gw = blockIdx.x * 8 + w;
    const float* Wh; const float* f; const float* g;
    const int* nbr; const int* cnt; float* hcat_h; float* hcat_l;
    int n;
    if (gw < Nn * NHd) {
        Wh = Wh_c; f = f_c; g = g_c; nbr = nbr_c; cnt = cnt_c;
        hcat_h = hcatc_h; hcat_l = hcatc_l; n = Nn;
    } else {
        gw -= Nn * NHd;
        Wh = Wh_t; f = f_t; g = g_t; nbr = nbr_t; cnt = cnt_t;
        hcat_h = hcatt_h; hcat_l = hcatt_l; n = Tt;
    }
    int i = gw >> 2, h = gw & 3;
    __shared__ int   sj[8][CAP];
    __shared__ float sw[8][CAP];
    int c = cnt[i];
    const int* jb = nbr + i * CAP;
    float fi = f[h * n + i];
    float m = -1e30f;
    for (int k = lane; k < c; k += 32) {
        int j = jb[k];
        sj[w][k] = j;
        float s = fi + g[h * n + j];
        s = (s >= 0.0f) ? s : LRELU_ALPHA * s;
        sw[w][k] = s;
        m = fmaxf(m, s);
    }
    #pragma unroll
    for (int o = 16; o; o >>= 1) m = fmaxf(m, __shfl_xor_sync(0xffffffffu, m, o));
    __syncwarp();
    float sum = 0.0f;
    for (int k = lane; k < c; k += 32) {
        float e = expf(sw[w][k] - m);
        sw[w][k] = e;
        sum += e;
    }
    #pragma unroll
    for (int o = 16; o; o >>= 1) sum += __shfl_xor_sync(0xffffffffu, sum, o);
    float dinv = 1.0f / sum;
    __syncwarp();
    const float* base = Wh + (size_t)h * n * Dd;
    float acc[8] = {};
    int k = 0;
    for (; k + 2 <= c; k += 2) {
        float w0 = sw[w][k], w1 = sw[w][k + 1];
        const float* r0 = base + (size_t)sj[w][k] * Dd + lane;
        const float* r1 = base + (size_t)sj[w][k + 1] * Dd + lane;
        #pragma unroll
        for (int ch = 0; ch < 8; ch++) {
            acc[ch] += w0 * __ldg(r0 + ch * 32);
            acc[ch] += w1 * __ldg(r1 + ch * 32);
        }
    }
    if (k < c) {
        float w0 = sw[w][k];
        const float* r0 = base + (size_t)sj[w][k] * Dd + lane;
        #pragma unroll
        for (int ch = 0; ch < 8; ch++) acc[ch] += w0 * __ldg(r0 + ch * 32);
    }
    size_t obase = (size_t)i * (NHd * Dd) + h * Dd + lane;
    #pragma unroll
    for (int ch = 0; ch < 8; ch++) {
        float v = acc[ch] * dinv;
        v = (v > 0.0f) ? v : expm1f(v);
        split_store(v, hcat_h, hcat_l, obase + ch * 32);
    }
}

// ------------------------- gated fusion elementwise ------------------------
__global__ void fuse_kernel(const float* __restrict__ a, const float* __restrict__ b,
                            float* __restrict__ out_h, float* __restrict__ out_l,
                            int total) {
    int idx = blockIdx.x * blockDim.x + threadIdx.x;
    if (idx < total) {
        float ca = a[idx], cb = b[idx];
        float z = 1.0f / (1.0f + expf(-(ca + cb)));
        split_store(z * ca + (1.0f - z) * cb, out_h, out_l, idx);
    }
}

// ------------------------- sparse adj @ X, optional ReLU -------------------
__global__ void spmm_kernel(const int* __restrict__ nbr, const float* __restrict__ val,
                            const int* __restrict__ cnt, const float* __restrict__ X,
                            float* __restrict__ Y, int ncols, int do_relu) {
    int i = blockIdx.x;
    int t = threadIdx.x;
    int c = cnt[i];
    const int* jb = nbr + i * CAP;
    const float* vb = val + i * CAP;
    float a0 = 0.0f, a1 = 0.0f, a2 = 0.0f, a3 = 0.0f;
    int k = 0;
    for (; k + 4 <= c; k += 4) {
        a0 += vb[k]     * __ldg(X + (size_t)jb[k]     * ncols + t);
        a1 += vb[k + 1] * __ldg(X + (size_t)jb[k + 1] * ncols + t);
        a2 += vb[k + 2] * __ldg(X + (size_t)jb[k + 2] * ncols + t);
        a3 += vb[k + 3] * __ldg(X + (size_t)jb[k + 3] * ncols + t);
    }
    for (; k < c; k++)
        a0 += vb[k] * __ldg(X + (size_t)jb[k] * ncols + t);
    float acc = (a0 + a1) + (a2 + a3);
    if (do_relu) acc = fmaxf(acc, 0.0f);
    Y[(size_t)i * ncols + t] = acc;
}

// ------------------------- fused mu/logvar spmm ----------------------------
__global__ void spmm2_kernel(const int* __restrict__ nbr, const float* __restrict__ val,
                             const int* __restrict__ cnt, const float* __restrict__ X2,
                             const float* __restrict__ X3, float* __restrict__ mu,
                             float* __restrict__ logvar, float* __restrict__ mu_h,
                             float* __restrict__ mu_l) {
    int i = blockIdx.x;
    int t = threadIdx.x;
    int sel = t >> 5, col = t & 31;
    const float* X = sel ? X3 : X2;
    int c = cnt[i];
    const int* jb = nbr + i * CAP;
    const float* vb = val + i * CAP;
    float a0 = 0.0f, a1 = 0.0f, a2 = 0.0f, a3 = 0.0f;
    int k = 0;
    for (; k + 4 <= c; k += 4) {
        a0 += vb[k]     * __ldg(X + (size_t)jb[k]     * H2d + col);
        a1 += vb[k + 1] * __ldg(X + (size_t)jb[k + 1] * H2d + col);
        a2 += vb[k + 2] * __ldg(X + (size_t)jb[k + 2] * H2d + col);
        a3 += vb[k + 3] * __ldg(X + (size_t)jb[k + 3] * H2d + col);
    }
    for (; k < c; k++)
        a0 += vb[k] * __ldg(X + (size_t)jb[k] * H2d + col);
    float v = (a0 + a1) + (a2 + a3);
    size_t idx = (size_t)i * H2d + col;
    if (sel == 0) {
        mu[idx] = v;
        split_store(v, mu_h, mu_l, idx);
    } else {
        logvar[idx] = v;
    }
}

// ------------------------- host-side launch helpers ------------------------
struct GemmArgs {
    const float *Ah, *Al, *Bh, *Bl, *bias;
    float *C, *Ch, *Cl;
};
static inline void run_nn(GemmArgs a, int M, int N, int K, int batch = 1,
                          size_t sA = 0, size_t sB = 0, size_t sC = 0) {
    dim3 grid(N / BNt, M / BMt, batch);
    mma_gemm_kernel<false, false><<<grid, 256>>>(a.Ah, a.Al, a.Bh, a.Bl, a.bias,
                                                 a.C, a.Ch, a.Cl, M, N, K, sA, sB, sC);
}
static inline void run_tn(GemmArgs a, int M, int N, int K) {
    dim3 grid(N / BNt, M / BMt, 1);
    mma_gemm_kernel<true, false><<<grid, 256>>>(a.Ah, a.Al, a.Bh, a.Bl, a.bias,
                                                a.C, a.Ch, a.Cl, M, N, K, 0, 0, 0);
}
static inline void run_nt(GemmArgs a, int M, int N, int K) {
    dim3 grid(N / BNt, M / BMt, 1);
    mma_gemm_kernel<false, true><<<grid, 256>>>(a.Ah, a.Al, a.Bh, a.Bl, a.bias,
                                                a.C, a.Ch, a.Cl, M, N, K, 0, 0, 0);
}

#define SYM(p, s) cudaGetSymbolAddress((void**)&p, s)

extern "C" void kernel_launch(void* const* d_in, const int* in_sizes, int n_in,
                              void* d_out, int out_size) {
    const float* x        = (const float*)d_in[0];
    const float* adj      = (const float*)d_in[1];
    const float* t_x      = (const float*)d_in[2];
    const float* t_adj    = (const float*)d_in[3];
    const float* tfidf    = (const float*)d_in[4];
    const float* gat_W    = (const float*)d_in[5];
    const float* gat_asrc = (const float*)d_in[6];
    const float* gat_adst = (const float*)d_in[7];
    const float* gat_fcW  = (const float*)d_in[8];
    const float* gat_fcb  = (const float*)d_in[9];
    const float* t_W      = (const float*)d_in[10];
    const float* t_asrc   = (const float*)d_in[11];
    const float* t_adst   = (const float*)d_in[12];
    const float* t_fcW    = (const float*)d_in[13];
    const float* t_fcb    = (const float*)d_in[14];
    const float* fus_W    = (const float*)d_in[15];
    const float* fus_b    = (const float*)d_in[16];
    const float* gc1_W    = (const float*)d_in[17];
    const float* gc2_W    = (const float*)d_in[18];
    const float* gc3_W    = (const float*)d_in[19];

    float* out    = (float*)d_out;
    float* mu     = out + (size_t)Nn * Nn;
    float* logvar = mu + (size_t)Nn * H2d;

    float *Wh_c, *Wh_t, *f_c, *g_c, *f_t, *g_t, *val_c, *val_t;
    float *concept, *ctext, *tmp1, *h1, *tmp2a, *tmp2b;
    int *nbr_c, *cnt_c, *nbr_t, *cnt_t;
    float *x_h, *x_l, *tx_h, *tx_l, *tf_h, *tf_l;
    float *gatW_h, *gatW_l, *tW_h, *tW_l, *fcWc_h, *fcWc_l, *fcWt_h, *fcWt_l;
    float *fusW_h, *fusW_l, *gc1W_h, *gc1W_l;
    float *hcatc_h, *hcatc_l, *hcatt_h, *hcatt_l, *gtext_h, *gtext_l;
    float *fused_h, *fused_l, *fusion_h, *fusion_l, *mu_h, *mu_l;
    SYM(Wh_c, g_Wh_c);  SYM(Wh_t, g_Wh_t);
    SYM(f_c, g_f_c);    SYM(g_c, g_g_c);   SYM(f_t, g_f_t);  SYM(g_t, g_g_t);
    SYM(nbr_c, g_nbr_c); SYM(val_c, g_val_c); SYM(cnt_c, g_cnt_c);
    SYM(nbr_t, g_nbr_t); SYM(val_t, g_val_t); SYM(cnt_t, g_cnt_t);
    SYM(concept, g_concept); SYM(ctext, g_ctext);
    SYM(tmp1, g_tmp1); SYM(h1, g_h1); SYM(tmp2a, g_tmp2a); SYM(tmp2b, g_tmp2b);
    SYM(x_h, g_x_h);   SYM(x_l, g_x_l);  SYM(tx_h, g_tx_h); SYM(tx_l, g_tx_l);
    SYM(tf_h, g_tf_h); SYM(tf_l, g_tf_l);
    SYM(gatW_h, g_gatW_h); SYM(gatW_l, g_gatW_l);
    SYM(tW_h, g_tW_h);     SYM(tW_l, g_tW_l);
    SYM(fcWc_h, g_fcWc_h); SYM(fcWc_l, g_fcWc_l);
    SYM(fcWt_h, g_fcWt_h); SYM(fcWt_l, g_fcWt_l);
    SYM(fusW_h, g_fusW_h); SYM(fusW_l, g_fusW_l);
    SYM(gc1W_h, g_gc1W_h); SYM(gc1W_l, g_gc1W_l);
    SYM(hcatc_h, g_hcatc_h); SYM(hcatc_l, g_hcatc_l);
    SYM(hcatt_h, g_hcatt_h); SYM(hcatt_l, g_hcatt_l);
    SYM(gtext_h, g_gtext_h); SYM(gtext_l, g_gtext_l);
    SYM(fused_h, g_fused_h); SYM(fused_l, g_fused_l);
    SYM(fusion_h, g_fusion_h); SYM(fusion_l, g_fusion_l);
    SYM(mu_h, g_mu_h); SYM(mu_l, g_mu_l);

    // 0) split ALL harness inputs into tf32 hi/lo planes, NO transpose
    //    (B operands stay [K,N] row-major exactly as the GEMM expects)
    {
        SplitJobs9 jobs;
        jobs.j[0] = { x,       x_h,    x_l,    Nn * Dd / 4 };
        jobs.j[1] = { t_x,     tx_h,   tx_l,   Tt * Dd / 4 };
        jobs.j[2] = { tfidf,   tf_h,   tf_l,   Tt * Nn / 4 };
        jobs.j[3] = { gat_W,   gatW_h, gatW_l, NHd * Dd * Dd / 4 };
        jobs.j[4] = { t_W,     tW_h,   tW_l,   NHd * Dd * Dd / 4 };
        jobs.j[5] = { gat_fcW, fcWc_h, fcWc_l, NHd * Dd * Dd / 4 };
        jobs.j[6] = { t_fcW,   fcWt_h, fcWt_l, NHd * Dd * Dd / 4 };
        jobs.j[7] = { fus_W,   fusW_h, fusW_l, Dd * Dd / 4 };
        jobs.j[8] = { gc1_W,   gc1W_h, gc1W_l, Dd * H1d / 4 };
        split_all_kernel<<<dim3(512, 9), 256>>>(jobs);
    }

    // 1) both adjacencies -> CSR (one launch)
    build_csr2_kernel<<<Nn + Tt, 256>>>(adj, t_adj, nbr_c, val_c, cnt_c,
                                        nbr_t, val_t, cnt_t);

    // 2) per-head Wh = x @ W[h]  (batched over heads)
    run_nn({x_h, x_l, gatW_h, gatW_l, nullptr, Wh_c, nullptr, nullptr},
           Nn, Dd, Dd, NHd, 0, (size_t)Dd * Dd, (size_t)Nn * Dd);
    run_nn({tx_h, tx_l, tW_h, tW_l, nullptr, Wh_t, nullptr, nullptr},
           Tt, Dd, Dd, NHd, 0, (size_t)Dd * Dd, (size_t)Tt * Dd);

    // 3) attention projections f,g (both graphs, one launch)
    {
        int warps = NHd * (Nn + Tt);
        fg2_kernel<<<(warps * 32 + 255) / 256, 256>>>(
            Wh_c, gat_asrc, gat_adst, f_c, g_c,
            Wh_t, t_asrc, t_adst, f_t, g_t);
    }

    // 4) sparse attention + aggregation + ELU (both graphs, one launch)
    gat_attn2_kernel<<<(Nn + Tt) * NHd / 8, 256>>>(
        Wh_c, f_c, g_c, nbr_c, cnt_c, hcatc_h, hcatc_l,
        Wh_t, f_t, g_t, nbr_t, cnt_t, hcatt_h, hcatt_l);

    // 5) output fc per graph
    run_nn({hcatc_h, hcatc_l, fcWc_h, fcWc_l, gat_fcb, concept, nullptr, nullptr},
           Nn, Dd, NHd * Dd);
    run_nn({hcatt_h, hcatt_l, fcWt_h, fcWt_l, t_fcb, nullptr, gtext_h, gtext_l},
           Tt, Dd, NHd * Dd);

    // 6) c_text = tfidf^T @ gat_text  (A^T path; B = gtext planes [T,D])
    run_tn({tf_h, tf_l, gtext_h, gtext_l, nullptr, ctext, nullptr, nullptr},
           Nn, Dd, Tt);

    // 7) gated fusion + fc
    fuse_kernel<<<(Nn * Dd + 255) / 256, 256>>>(concept, ctext, fused_h, fused_l, Nn * Dd);
    run_nn({fused_h, fused_l, fusW_h, fusW_l, fus_b, nullptr, fusion_h, fusion_l},
           Nn, Dd, Dd);

    // 8) GCN encoder
    run_nn({fusion_h, fusion_l, gc1W_h, gc1W_l, nullptr, tmp1, nullptr, nullptr},
           Nn, H1d, Dd);
    spmm_kernel<<<Nn, H1d>>>(nbr_c, val_c, cnt_c, tmp1, h1, H1d, 1);

    gc23_kernel<<<Nn / 64, 256>>>(h1, gc2_W, gc3_W, tmp2a, tmp2b);
    spmm2_kernel<<<Nn, 64>>>(nbr_c, val_c, cnt_c, tmp2a, tmp2b, mu, logvar, mu_h, mu_l);

    // 9) recon = mu @ mu^T  (mu planes [4096,32] serve as A [M,K] and B [N,K])
    run_nt({mu_h, mu_l, mu_h, mu_l, nullptr, out, nullptr, nullptr}, Nn, Nn, H2d);
}

// round 11
// speedup vs baseline: 1.2637x; 1.1201x over previous
#include <cuda_runtime.h>
#include <math.h>
#include <stdint.h>

#define Nn   4096
#define Tt   2048
#define Dd   256
#define H1d  128
#define H2d  32
#define NHd  4
#define CAP  96
#define LRELU_ALPHA 0.2f

// ------------------------- scratch (__device__ globals) --------------------
__device__ float g_Wh_c[NHd * Nn * Dd];
__device__ float g_Wh_t[NHd * Tt * Dd];
__device__ float g_f_c[NHd * Nn], g_g_c[NHd * Nn];
__device__ float g_f_t[NHd * Tt], g_g_t[NHd * Tt];
__device__ int   g_nbr_c[Nn * CAP];
__device__ float g_val_c[Nn * CAP];
__device__ int   g_cnt_c[Nn];
__device__ int   g_nbr_t[Tt * CAP];
__device__ float g_val_t[Tt * CAP];
__device__ int   g_cnt_t[Tt];
__device__ float g_tmp1[Nn * H1d];
__device__ float g_h1[Nn * H1d];
__device__ float g_tmp2a[Nn * H2d];
__device__ float g_tmp2b[Nn * H2d];
// split-K partial buffers
__device__ float g_P0[2 * Nn * Dd];   // fc_c partials
__device__ float g_P1[4 * Tt * Dd];   // fc_t partials
__device__ float g_P2[4 * Nn * Dd];   // tfidf partials
// hi/lo planes: A operands [M,K]; B operands [K,N]
__device__ float g_x_h[Nn * Dd],        g_x_l[Nn * Dd];
__device__ float g_tx_h[Tt * Dd],       g_tx_l[Tt * Dd];
__device__ float g_tf_h[Tt * Nn],       g_tf_l[Tt * Nn];
__device__ float g_gatW_h[NHd * Dd * Dd], g_gatW_l[NHd * Dd * Dd];
__device__ float g_tW_h[NHd * Dd * Dd],   g_tW_l[NHd * Dd * Dd];
__device__ float g_fcWc_h[NHd * Dd * Dd], g_fcWc_l[NHd * Dd * Dd];
__device__ float g_fcWt_h[NHd * Dd * Dd], g_fcWt_l[NHd * Dd * Dd];
__device__ float g_fusW_h[Dd * Dd],     g_fusW_l[Dd * Dd];
__device__ float g_gc1W_h[Dd * H1d],    g_gc1W_l[Dd * H1d];
__device__ float g_hcatc_h[Nn * NHd * Dd], g_hcatc_l[Nn * NHd * Dd];
__device__ float g_hcatt_h[Tt * NHd * Dd], g_hcatt_l[Tt * NHd * Dd];
__device__ float g_gtext_h[Tt * Dd],    g_gtext_l[Tt * Dd];
__device__ float g_fused_h[Nn * Dd],    g_fused_l[Nn * Dd];
__device__ float g_fusion_h[Nn * Dd],   g_fusion_l[Nn * Dd];
__device__ float g_mu_h[Nn * H2d],      g_mu_l[Nn * H2d];

// ------------------------- tf32 helpers ------------------------------------
__device__ __forceinline__ void tf32_split_u(float v, uint32_t& h, uint32_t& l) {
    asm("cvt.rna.tf32.f32 %0, %1;" : "=r"(h) : "f"(v));
    float r = v - __uint_as_float(h);
    asm("cvt.rna.tf32.f32 %0, %1;" : "=r"(l) : "f"(r));
}
__device__ __forceinline__ void split_store(float v, float* hp, float* lp, size_t idx) {
    uint32_t h, l; tf32_split_u(v, h, l);
    hp[idx] = __uint_as_float(h); lp[idx] = __uint_as_float(l);
}

#define MMA_TF32(c, a, b)                                                         \
    asm volatile(                                                                  \
        "mma.sync.aligned.m16n8k8.row.col.f32.tf32.tf32.f32 "                      \
        "{%0,%1,%2,%3},{%4,%5,%6,%7},{%8,%9},{%0,%1,%2,%3};"                       \
        : "+f"((c)[0]), "+f"((c)[1]), "+f"((c)[2]), "+f"((c)[3])                   \
        : "r"((a)[0]), "r"((a)[1]), "r"((a)[2]), "r"((a)[3]),                      \
          "r"((b)[0]), "r"((b)[1]))

__device__ __forceinline__ void cp16(void* sp, const void* gp) {
    uint32_t s = (uint32_t)__cvta_generic_to_shared(sp);
    asm volatile("cp.async.cg.shared.global [%0], [%1], 16;" :: "r"(s), "l"(gp));
}

// ------------------------- split_all (harness inputs -> hi/lo) -------------
struct SplitJob { const float* src; float* hi; float* lo; int n4; };
struct SplitJobs9 { SplitJob j[9]; };
__global__ void split_all_kernel(SplitJobs9 jobs) {
    SplitJob jb = jobs.j[blockIdx.y];
    const float4* src = (const float4*)jb.src;
    float4* hi = (float4*)jb.hi;
    float4* lo = (float4*)jb.lo;
    for (int i = blockIdx.x * blockDim.x + threadIdx.x; i < jb.n4;
         i += gridDim.x * blockDim.x) {
        float4 v = src[i];
        uint32_t h, l;
        float4 vh, vl;
        tf32_split_u(v.x, h, l); vh.x = __uint_as_float(h); vl.x = __uint_as_float(l);
        tf32_split_u(v.y, h, l); vh.y = __uint_as_float(h); vl.y = __uint_as_float(l);
        tf32_split_u(v.z, h, l); vh.z = __uint_as_float(h); vl.z = __uint_as_float(l);
        tf32_split_u(v.w, h, l); vh.w = __uint_as_float(h); vl.w = __uint_as_float(l);
        hi[i] = vh; lo[i] = vl;
    }
}

// ------------------------- merged CSR build (both graphs) ------------------
__global__ void build_csr2_kernel(const float* __restrict__ adj,
                                  const float* __restrict__ t_adj,
                                  int* __restrict__ nbr_c, float* __restrict__ val_c,
                                  int* __restrict__ cnt_c,
                                  int* __restrict__ nbr_t, float* __restrict__ val_t,
                                  int* __restrict__ cnt_t) {
    int bi = blockIdx.x;
    const float* row;
    int n, i;
    int* nbr; float* val; int* cnt;
    if (bi < Nn) {
        i = bi; n = Nn; row = adj + (size_t)i * Nn;
        nbr = nbr_c; val = val_c; cnt = cnt_c;
    } else {
        i = bi - Nn; n = Tt; row = t_adj + (size_t)i * Tt;
        nbr = nbr_t; val = val_t; cnt = cnt_t;
    }
    int t = threadIdx.x, lane = t & 31, w = t >> 5;
    int strip = n >> 3;
    int s0 = w * strip;
    __shared__ int s_cnt[8];
    int my = 0;
    for (int b = s0; b < s0 + strip; b += 32) {
        bool p = row[b + lane] > 0.0f;
        unsigned m = __ballot_sync(0xffffffffu, p);
        my += __popc(m);
    }
    if (lane == 0) s_cnt[w] = my;
    __syncthreads();
    int off = 0;
    #pragma unroll
    for (int ww = 0; ww < 8; ww++) if (ww < w) off += s_cnt[ww];
    int tot = 0;
    #pragma unroll
    for (int ww = 0; ww < 8; ww++) tot += s_cnt[ww];
    for (int b = s0; b < s0 + strip; b += 32) {
        float v = row[b + lane];
        bool p = v > 0.0f;
        unsigned m = __ballot_sync(0xffffffffu, p);
        int pos = off + __popc(m & ((1u << lane) - 1u));
        if (p && pos < CAP) { nbr[i * CAP + pos] = b + lane; val[i * CAP + pos] = v; }
        off += __popc(m);
    }
    if (t == 0) cnt[i] = min(tot, CAP);
}

// ------------------------- tensor-core GEMM (hi/lo planes, z-strided) ------
// C = op(A) @ op(B) [+ bias]; op per TA/TB; lda/ldb are row strides (elements).
// blockIdx.z indexes EITHER a batch item OR a K-chunk: operand/output offsets
// advance by sA/sB/sC elements per z. K is the per-launch k-extent (chunk).
#define BMt 128
#define BNt 64
#define BKt 16

template <bool TA, bool TB>
__global__ void __launch_bounds__(256) mma_gemm_kernel(
    const float* __restrict__ Ah, const float* __restrict__ Al,
    const float* __restrict__ Bh, const float* __restrict__ Bl,
    const float* __restrict__ bias, float* __restrict__ C,
    float* __restrict__ Ch, float* __restrict__ Cl,
    int M, int N, int K, int lda, int ldb,
    size_t sA, size_t sB, size_t sC) {
    constexpr int AR = TA ? BKt : BMt;
    constexpr int AC = TA ? (BMt + 8) : (BKt + 4);
    constexpr int BR = TB ? BNt : BKt;
    constexpr int BC = TB ? (BKt + 4) : (BNt + 8);
    __shared__ float As[2][2][AR][AC];
    __shared__ float Bs[2][2][BR][BC];

    const float* Abp[2] = { Ah + (size_t)blockIdx.z * sA, Al + (size_t)blockIdx.z * sA };
    const float* Bbp[2] = { Bh + (size_t)blockIdx.z * sB, Bl + (size_t)blockIdx.z * sB };
    int bm = blockIdx.y * BMt, bn = blockIdx.x * BNt;
    int t = threadIdx.x, lane = t & 31, w = t >> 5;
    int wm = (w & 3) * 32, wn = (w >> 2) * 32;
    int gid = lane >> 2, tig = lane & 3;

    float acc[2][4][4] = {};

    auto load_tile = [&](int s, int k0) {
        #pragma unroll
        for (int p = 0; p < 2; p++) {
            if (!TA) {
                #pragma unroll
                for (int j = 0; j < 2; j++) {
                    int idx = t + j * 256;
                    int row = idx >> 2;
                    int col = (idx & 3) * 4;
                    cp16(&As[s][p][row][col], Abp[p] + (size_t)(bm + row) * lda + k0 + col);
                }
            } else {
                #pragma unroll
                for (int j = 0; j < 2; j++) {
                    int idx = t + j * 256;
                    int row = idx >> 5;
                    int col = (idx & 31) * 4;
                    cp16(&As[s][p][row][col], Abp[p] + (size_t)(k0 + row) * lda + bm + col);
                }
            }
            if (!TB) {
                int row = t >> 4;
                int col = (t & 15) * 4;
                cp16(&Bs[s][p][row][col], Bbp[p] + (size_t)(k0 + row) * ldb + bn + col);
            } else {
                int row = t >> 2;
                int col = (t & 3) * 4;
                cp16(&Bs[s][p][row][col], Bbp[p] + (size_t)(bn + row) * ldb + k0 + col);
            }
        }
    };

    auto Ae = [&](int s, int p, int k, int m) -> float {
        return TA ? As[s][p][k][m] : As[s][p][m][k];
    };
    auto Be = [&](int s, int p, int k, int nn) -> float {
        return TB ? Bs[s][p][nn][k] : Bs[s][p][k][nn];
    };

    int nk = K / BKt;
    load_tile(0, 0);
    asm volatile("cp.async.commit_group;");

    for (int kt = 0; kt < nk; kt++) {
        int s = kt & 1;
        if (kt + 1 < nk) {
            load_tile(s ^ 1, (kt + 1) * BKt);
            asm volatile("cp.async.commit_group;");
            asm volatile("cp.async.wait_group 1;");
        } else {
            asm volatile("cp.async.wait_group 0;");
        }
        __syncthreads();

        #pragma unroll
        for (int kk = 0; kk < BKt; kk += 8) {
            uint32_t ah[2][4], al[2][4], bh[4][2], bl[4][2];
            #pragma unroll
            for (int mt = 0; mt < 2; mt++) {
                int m0 = wm + mt * 16 + gid;
                ah[mt][0] = __float_as_uint(Ae(s, 0, kk + tig,     m0));
                ah[mt][1] = __float_as_uint(Ae(s, 0, kk + tig,     m0 + 8));
                ah[mt][2] = __float_as_uint(Ae(s, 0, kk + tig + 4, m0));
                ah[mt][3] = __float_as_uint(Ae(s, 0, kk + tig + 4, m0 + 8));
                al[mt][0] = __float_as_uint(Ae(s, 1, kk + tig,     m0));
                al[mt][1] = __float_as_uint(Ae(s, 1, kk + tig,     m0 + 8));
                al[mt][2] = __float_as_uint(Ae(s, 1, kk + tig + 4, m0));
                al[mt][3] = __float_as_uint(Ae(s, 1, kk + tig + 4, m0 + 8));
            }
            #pragma unroll
            for (int nt = 0; nt < 4; nt++) {
                int n0 = wn + nt * 8 + gid;
                bh[nt][0] = __float_as_uint(Be(s, 0, kk + tig,     n0));
                bh[nt][1] = __float_as_uint(Be(s, 0, kk + tig + 4, n0));
                bl[nt][0] = __float_as_uint(Be(s, 1, kk + tig,     n0));
                bl[nt][1] = __float_as_uint(Be(s, 1, kk + tig + 4, n0));
            }
            #pragma unroll
            for (int mt = 0; mt < 2; mt++)
                #pragma unroll
                for (int nt = 0; nt < 4; nt++) {
                    MMA_TF32(acc[mt][nt], al[mt], bh[nt]);
                    MMA_TF32(acc[mt][nt], ah[mt], bl[nt]);
                    MMA_TF32(acc[mt][nt], ah[mt], bh[nt]);
                }
        }
        __syncthreads();
    }

    float* Cb  = C  ? C  + (size_t)blockIdx.z * sC : nullptr;
    float* Chb = Ch ? Ch + (size_t)blockIdx.z * sC : nullptr;
    float* Clb = Cl ? Cl + (size_t)blockIdx.z * sC : nullptr;
    #pragma unroll
    for (int mt = 0; mt < 2; mt++) {
        int row0 = bm + wm + mt * 16 + gid;
        #pragma unroll
        for (int nt = 0; nt < 4; nt++) {
            int col = bn + wn + nt * 8 + tig * 2;
            float bx = bias ? bias[col] : 0.0f;
            float by = bias ? bias[col + 1] : 0.0f;
            float v00 = acc[mt][nt][0] + bx, v01 = acc[mt][nt][1] + by;
            float v10 = acc[mt][nt][2] + bx, v11 = acc[mt][nt][3] + by;
            size_t i0 = (size_t)row0 * N + col;
            size_t i1 = (size_t)(row0 + 8) * N + col;
            if (Cb) {
                *reinterpret_cast<float2*>(&Cb[i0]) = make_float2(v00, v01);
                *reinterpret_cast<float2*>(&Cb[i1]) = make_float2(v10, v11);
            }
            if (Chb) {
                uint32_t h, l;
                float2 h0, l0, h1, l1;
                tf32_split_u(v00, h, l); h0.x = __uint_as_float(h); l0.x = __uint_as_float(l);
                tf32_split_u(v01, h, l); h0.y = __uint_as_float(h); l0.y = __uint_as_float(l);
                tf32_split_u(v10, h, l); h1.x = __uint_as_float(h); l1.x = __uint_as_float(l);
                tf32_split_u(v11, h, l); h1.y = __uint_as_float(h); l1.y = __uint_as_float(l);
                *reinterpret_cast<float2*>(&Chb[i0]) = h0;
                *reinterpret_cast<float2*>(&Clb[i0]) = l0;
                *reinterpret_cast<float2*>(&Chb[i1]) = h1;
                *reinterpret_cast<float2*>(&Clb[i1]) = l1;
            }
        }
    }
}

// ------------------------- split-K reduce: 4 partials -> split planes ------
__global__ void reduce4_split_kernel(const float* __restrict__ P,
                                     const float* __restrict__ bias,
                                     float* __restrict__ oh, float* __restrict__ ol,
                                     int MN4, int Ncols4) {
    int i = blockIdx.x * blockDim.x + threadIdx.x;
    if (i >= MN4) return;
    const float4* p = (const float4*)P;
    float4 a = p[i], b = p[i + MN4], c = p[i + 2 * MN4], d = p[i + 3 * MN4];
    float4 bv = ((const float4*)bias)[i % Ncols4];
    size_t base = (size_t)i * 4;
    split_store((a.x + b.x) + (c.x + d.x) + bv.x, oh, ol, base);
    split_store((a.y + b.y) + (c.y + d.y) + bv.y, oh, ol, base + 1);
    split_store((a.z + b.z) + (c.z + d.z) + bv.z, oh, ol, base + 2);
    split_store((a.w + b.w) + (c.w + d.w) + bv.w, oh, ol, base + 3);
}

// ------------- fused reduce (fc_c 2 partials + bias; tfidf 4 partials) -----
// concept = P0a+P0b+bias; ctext = sum(P2); z = sigmoid(c+t); fused -> hi/lo
__global__ void fuse_reduce_kernel(const float* __restrict__ P0,
                                   const float* __restrict__ P2,
                                   const float* __restrict__ bias,
                                   float* __restrict__ oh, float* __restrict__ ol,
                                   int MN4, int Ncols4) {
    int i = blockIdx.x * blockDim.x + threadIdx.x;
    if (i >= MN4) return;
    const float4* p0 = (const float4*)P0;
    const float4* p2 = (const float4*)P2;
    float4 a = p0[i], b = p0[i + MN4];
    float4 c0 = p2[i], c1 = p2[i + MN4], c2 = p2[i + 2 * MN4], c3 = p2[i + 3 * MN4];
    float4 bv = ((const float4*)bias)[i % Ncols4];
    float con[4] = { a.x + b.x + bv.x, a.y + b.y + bv.y,
                     a.z + b.z + bv.z, a.w + b.w + bv.w };
    float ct[4] = { (c0.x + c1.x) + (c2.x + c3.x), (c0.y + c1.y) + (c2.y + c3.y),
                    (c0.z + c1.z) + (c2.z + c3.z), (c0.w + c1.w) + (c2.w + c3.w) };
    size_t base = (size_t)i * 4;
    #pragma unroll
    for (int u = 0; u < 4; u++) {
        float z = 1.0f / (1.0f + expf(-(con[u] + ct[u])));
        split_store(z * con[u] + (1.0f - z) * ct[u], oh, ol, base + u);
    }
}

// ------------------------- gc2 & gc3 fused SIMT GEMM -----------------------
__global__ void gc23_kernel(const float* __restrict__ A, const float* __restrict__ B2,
                            const float* __restrict__ B3, float* __restrict__ C2,
                            float* __restrict__ C3) {
    __shared__ __align__(16) float As[16][64];
    __shared__ __align__(16) float Bs[16][64];
    int bm = blockIdx.x * 64;
    int t = threadIdx.x, tx = t & 15, ty = t >> 4;
    float acc[4][4] = {};
    for (int k0 = 0; k0 < H1d; k0 += 16) {
        #pragma unroll
        for (int j = 0; j < 4; j++) {
            int li = t + j * 256;
            int r = li >> 4, c = li & 15;
            As[c][r] = A[(size_t)(bm + r) * H1d + k0 + c];
            int rb = li >> 6, cb = li & 63;
            Bs[rb][cb] = (cb < 32) ? B2[(k0 + rb) * H2d + cb]
                                   : B3[(k0 + rb) * H2d + cb - 32];
        }
        __syncthreads();
        #pragma unroll
        for (int k = 0; k < 16; k++) {
            float4 a4 = *reinterpret_cast<const float4*>(&As[k][ty << 2]);
            float4 b4 = *reinterpret_cast<const float4*>(&Bs[k][tx << 2]);
            float a[4] = {a4.x, a4.y, a4.z, a4.w};
            float b[4] = {b4.x, b4.y, b4.z, b4.w};
            #pragma unroll
            for (int u = 0; u < 4; u++)
                #pragma unroll
                for (int v = 0; v < 4; v++)
                    acc[u][v] += a[u] * b[v];
        }
        __syncthreads();
    }
    #pragma unroll
    for (int u = 0; u < 4; u++) {
        int row = bm + (ty << 2) + u;
        #pragma unroll
        for (int v = 0; v < 4; v++) {
            int col = (tx << 2) + v;
            if (col < 32) C2[(size_t)row * H2d + col] = acc[u][v];
            else          C3[(size_t)row * H2d + col - 32] = acc[u][v];
        }
    }
}

// ------------------------- merged f/g projections --------------------------
__global__ void fg2_kernel(const float* __restrict__ Wh_c, const float* __restrict__ asrc_c,
                           const float* __restrict__ adst_c, float* __restrict__ f_c,
                           float* __restrict__ g_c,
                           const float* __restrict__ Wh_t, const float* __restrict__ asrc_t,
                           const float* __restrict__ adst_t, float* __restrict__ f_t,
                           float* __restrict__ g_t) {
    int gw = (blockIdx.x * blockDim.x + threadIdx.x) >> 5;
    int lane = threadIdx.x & 31;
    const float* Wh; const float* asrc; const float* adst; float* f; float* g;
    int n;
    if (gw < NHd * Nn) {
        Wh = Wh_c; asrc = asrc_c; adst = adst_c; f = f_c; g = g_c; n = Nn;
    } else {
        gw -= NHd * Nn;
        if (gw >= NHd * Tt) return;
        Wh = Wh_t; asrc = asrc_t; adst = adst_t; f = f_t; g = g_t; n = Tt;
    }
    int h = gw / n, i = gw - h * n;
    const float* wp = Wh + ((size_t)h * n + i) * Dd;
    const float* as = asrc + h * Dd;
    const float* ad = adst + h * Dd;
    float accf = 0.0f, accg = 0.0f;
    #pragma unroll
    for (int c = 0; c < Dd / 32; c++) {
        float v = wp[lane + 32 * c];
        accf += v * as[lane + 32 * c];
        accg += v * ad[lane + 32 * c];
    }
    #pragma unroll
    for (int o = 16; o; o >>= 1) {
        accf += __shfl_down_sync(0xffffffffu, accf, o);
        accg += __shfl_down_sync(0xffffffffu, accg, o);
    }
    if (lane == 0) { f[gw] = accf; g[gw] = accg; }
}

// ------------------------- merged warp-per-(i,h) GAT attention -------------
__global__ void __launch_bounds__(256) gat_attn2_kernel(
    const float* __restrict__ Wh_c, const float* __restrict__ f_c,
    const float* __restrict__ g_c, const int* __restrict__ nbr_c,
    const int* __restrict__ cnt_c, float* __restrict__ hcatc_h,
    float* __restrict__ hcatc_l,
    const float* __restrict__ Wh_t, const float* __restrict__ f_t,
    const float* __restrict__ g_t, const int* __restrict__ nbr_t,
    const int* __restrict__ cnt_t, float* __restrict__ hcatt_h,
    float* __restrict__ hcatt_l) {
    int w = threadIdx.x >> 5, lane = threadIdx.x & 31;
    int gw = blockIdx.x * 8 + w;
    const float* Wh; const float* f; const float* g;
    const int* nbr; const int* cnt; float* hcat_h; float* hcat_l;
    int n;
    if (gw < Nn * NHd) {
        Wh = Wh_c; f = f_c; g = g_c; nbr = nbr_c; cnt = cnt_c;
        hcat_h = hcatc_h; hcat_l = hcatc_l; n = Nn;
    } else {
        gw -= Nn * NHd;
        Wh = Wh_t; f = f_t; g = g_t; nbr = nbr_t; cnt = cnt_t;
        hcat_h = hcatt_h; hcat_l = hcatt_l; n = Tt;
    }
    int i = gw >> 2, h = gw & 3;
    __shared__ int   sj[8][CAP];
    __shared__ float sw[8][CAP];
    int c = cnt[i];
    const int* jb = nbr + i * CAP;
    float fi = f[h * n + i];
    float m = -1e30f;
    for (int k = lane; k < c; k += 32) {
        int j = jb[k];
        sj[w][k] = j;
        float s = fi + g[h * n + j];
        s = (s >= 0.0f) ? s : LRELU_ALPHA * s;
        sw[w][k] = s;
        m = fmaxf(m, s);
    }
    #pragma unroll
    for (int o = 16; o; o >>= 1) m = fmaxf(m, __shfl_xor_sync(0xffffffffu, m, o));
    __syncwarp();
    float sum = 0.0f;
    for (int k = lane; k < c; k += 32) {
        float e = expf(sw[w][k] - m);
        sw[w][k] = e;
        sum += e;
    }
    #pragma unroll
    for (int o = 16; o; o >>= 1) sum += __shfl_xor_sync(0xffffffffu, sum, o);
    float dinv = 1.0f / sum;
    __syncwarp();
    const float* base = Wh + (size_t)h * n * Dd;
    float acc[8] = {};
    int k = 0;
    for (; k + 2 <= c; k += 2) {
        float w0 = sw[w][k], w1 = sw[w][k + 1];
        const float* r0 = base + (size_t)sj[w][k] * Dd + lane;
        const float* r1 = base + (size_t)sj[w][k + 1] * Dd + lane;
        #pragma unroll
        for (int ch = 0; ch < 8; ch++) {
            acc[ch] += w0 * __ldg(r0 + ch * 32);
            acc[ch] += w1 * __ldg(r1 + ch * 32);
        }
    }
    if (k < c) {
        float w0 = sw[w][k];
        const float* r0 = base + (size_t)sj[w][k] * Dd + lane;
        #pragma unroll
        for (int ch = 0; ch < 8; ch++) acc[ch] += w0 * __ldg(r0 + ch * 32);
    }
    size_t obase = (size_t)i * (NHd * Dd) + h * Dd + lane;
    #pragma unroll
    for (int ch = 0; ch < 8; ch++) {
        float v = acc[ch] * dinv;
        v = (v > 0.0f) ? v : expm1f(v);
        split_store(v, hcat_h, hcat_l, obase + ch * 32);
    }
}

// ------------------------- sparse adj @ X, optional ReLU -------------------
__global__ void spmm_kernel(const int* __restrict__ nbr, const float* __restrict__ val,
                            const int* __restrict__ cnt, const float* __restrict__ X,
                            float* __restrict__ Y, int ncols, int do_relu) {
    int i = blockIdx.x;
    int t = threadIdx.x;
    int c = cnt[i];
    const int* jb = nbr + i * CAP;
    const float* vb = val + i * CAP;
    float a0 = 0.0f, a1 = 0.0f, a2 = 0.0f, a3 = 0.0f;
    int k = 0;
    for (; k + 4 <= c; k += 4) {
        a0 += vb[k]     * __ldg(X + (size_t)jb[k]     * ncols + t);
        a1 += vb[k + 1] * __ldg(X + (size_t)jb[k + 1] * ncols + t);
        a2 += vb[k + 2] * __ldg(X + (size_t)jb[k + 2] * ncols + t);
        a3 += vb[k + 3] * __ldg(X + (size_t)jb[k + 3] * ncols + t);
    }
    for (; k < c; k++)
        a0 += vb[k] * __ldg(X + (size_t)jb[k] * ncols + t);
    float acc = (a0 + a1) + (a2 + a3);
    if (do_relu) acc = fmaxf(acc, 0.0f);
    Y[(size_t)i * ncols + t] = acc;
}

// ------------------------- fused mu/logvar spmm ----------------------------
__global__ void spmm2_kernel(const int* __restrict__ nbr, const float* __restrict__ val,
                             const int* __restrict__ cnt, const float* __restrict__ X2,
                             const float* __restrict__ X3, float* __restrict__ mu,
                             float* __restrict__ logvar, float* __restrict__ mu_h,
                             float* __restrict__ mu_l) {
    int i = blockIdx.x;
    int t = threadIdx.x;
    int sel = t >> 5, col = t & 31;
    const float* X = sel ? X3 : X2;
    int c = cnt[i];
    const int* jb = nbr + i * CAP;
    const float* vb = val + i * CAP;
    float a0 = 0.0f, a1 = 0.0f, a2 = 0.0f, a3 = 0.0f;
    int k = 0;
    for (; k + 4 <= c; k += 4) {
        a0 += vb[k]     * __ldg(X + (size_t)jb[k]     * H2d + col);
        a1 += vb[k + 1] * __ldg(X + (size_t)jb[k + 1] * H2d + col);
        a2 += vb[k + 2] * __ldg(X + (size_t)jb[k + 2] * H2d + col);
        a3 += vb[k + 3] * __ldg(X + (size_t)jb[k + 3] * H2d + col);
    }
    for (; k < c; k++)
        a0 += vb[k] * __ldg(X + (size_t)jb[k] * H2d + col);
    float v = (a0 + a1) + (a2 + a3);
    size_t idx = (size_t)i * H2d + col;
    if (sel == 0) {
        mu[idx] = v;
        split_store(v, mu_h, mu_l, idx);
    } else {
        logvar[idx] = v;
    }
}

// ------------------------- host-side launch helpers ------------------------
struct GemmArgs {
    const float *Ah, *Al, *Bh, *Bl, *bias;
    float *C, *Ch, *Cl;
};
static inline void run_nn(GemmArgs a, int M, int N, int K, int lda, int ldb,
                          int nz = 1, size_t sA = 0, size_t sB = 0, size_t sC = 0) {
    dim3 grid(N / BNt, M / BMt, nz);
    mma_gemm_kernel<false, false><<<grid, 256>>>(a.Ah, a.Al, a.Bh, a.Bl, a.bias,
                                                 a.C, a.Ch, a.Cl, M, N, K, lda, ldb,
                                                 sA, sB, sC);
}
static inline void run_tn(GemmArgs a, int M, int N, int K, int lda, int ldb,
                          int nz = 1, size_t sA = 0, size_t sB = 0, size_t sC = 0) {
    dim3 grid(N / BNt, M / BMt, nz);
    mma_gemm_kernel<true, false><<<grid, 256>>>(a.Ah, a.Al, a.Bh, a.Bl, a.bias,
                                                a.C, a.Ch, a.Cl, M, N, K, lda, ldb,
                                                sA, sB, sC);
}
static inline void run_nt(GemmArgs a, int M, int N, int K, int lda, int ldb) {
    dim3 grid(N / BNt, M / BMt, 1);
    mma_gemm_kernel<false, true><<<grid, 256>>>(a.Ah, a.Al, a.Bh, a.Bl, a.bias,
                                                a.C, a.Ch, a.Cl, M, N, K, lda, ldb,
                                                0, 0, 0);
}

#define SYM(p, s) cudaGetSymbolAddress((void**)&p, s)

extern "C" void kernel_launch(void* const* d_in, const int* in_sizes, int n_in,
                              void* d_out, int out_size) {
    const float* x        = (const float*)d_in[0];
    const float* adj      = (const float*)d_in[1];
    const float* t_x      = (const float*)d_in[2];
    const float* t_adj    = (const float*)d_in[3];
    const float* tfidf    = (const float*)d_in[4];
    const float* gat_W    = (const float*)d_in[5];
    const float* gat_asrc = (const float*)d_in[6];
    const float* gat_adst = (const float*)d_in[7];
    const float* gat_fcW  = (const float*)d_in[8];
    const float* gat_fcb  = (const float*)d_in[9];
    const float* t_W      = (const float*)d_in[10];
    const float* t_asrc   = (const float*)d_in[11];
    const float* t_adst   = (const float*)d_in[12];
    const float* t_fcW    = (const float*)d_in[13];
    const float* t_fcb    = (const float*)d_in[14];
    const float* fus_W    = (const float*)d_in[15];
    const float* fus_b    = (const float*)d_in[16];
    const float* gc1_W    = (const float*)d_in[17];
    const float* gc2_W    = (const float*)d_in[18];
    const float* gc3_W    = (const float*)d_in[19];

    float* out    = (float*)d_out;
    float* mu     = out + (size_t)Nn * Nn;
    float* logvar = mu + (size_t)Nn * H2d;

    float *Wh_c, *Wh_t, *f_c, *g_c, *f_t, *g_t, *val_c, *val_t;
    float *tmp1, *h1, *tmp2a, *tmp2b, *P0, *P1, *P2;
    int *nbr_c, *cnt_c, *nbr_t, *cnt_t;
    float *x_h, *x_l, *tx_h, *tx_l, *tf_h, *tf_l;
    float *gatW_h, *gatW_l, *tW_h, *tW_l, *fcWc_h, *fcWc_l, *fcWt_h, *fcWt_l;
    float *fusW_h, *fusW_l, *gc1W_h, *gc1W_l;
    float *hcatc_h, *hcatc_l, *hcatt_h, *hcatt_l, *gtext_h, *gtext_l;
    float *fused_h, *fused_l, *fusion_h, *fusion_l, *mu_h, *mu_l;
    SYM(Wh_c, g_Wh_c);  SYM(Wh_t, g_Wh_t);
    SYM(f_c, g_f_c);    SYM(g_c, g_g_c);   SYM(f_t, g_f_t);  SYM(g_t, g_g_t);
    SYM(nbr_c, g_nbr_c); SYM(val_c, g_val_c); SYM(cnt_c, g_cnt_c);
    SYM(nbr_t, g_nbr_t); SYM(val_t, g_val_t); SYM(cnt_t, g_cnt_t);
    SYM(tmp1, g_tmp1); SYM(h1, g_h1); SYM(tmp2a, g_tmp2a); SYM(tmp2b, g_tmp2b);
    SYM(P0, g_P0); SYM(P1, g_P1); SYM(P2, g_P2);
    SYM(x_h, g_x_h);   SYM(x_l, g_x_l);  SYM(tx_h, g_tx_h); SYM(tx_l, g_tx_l);
    SYM(tf_h, g_tf_h); SYM(tf_l, g_tf_l);
    SYM(gatW_h, g_gatW_h); SYM(gatW_l, g_gatW_l);
    SYM(tW_h, g_tW_h);     SYM(tW_l, g_tW_l);
    SYM(fcWc_h, g_fcWc_h); SYM(fcWc_l, g_fcWc_l);
    SYM(fcWt_h, g_fcWt_h); SYM(fcWt_l, g_fcWt_l);
    SYM(fusW_h, g_fusW_h); SYM(fusW_l, g_fusW_l);
    SYM(gc1W_h, g_gc1W_h); SYM(gc1W_l, g_gc1W_l);
    SYM(hcatc_h, g_hcatc_h); SYM(hcatc_l, g_hcatc_l);
    SYM(hcatt_h, g_hcatt_h); SYM(hcatt_l, g_hcatt_l);
    SYM(gtext_h, g_gtext_h); SYM(gtext_l, g_gtext_l);
    SYM(fused_h, g_fused_h); SYM(fused_l, g_fused_l);
    SYM(fusion_h, g_fusion_h); SYM(fusion_l, g_fusion_l);
    SYM(mu_h, g_mu_h); SYM(mu_l, g_mu_l);

    // 0) split ALL harness inputs into tf32 hi/lo planes (no transpose)
    {
        SplitJobs9 jobs;
        jobs.j[0] = { x,       x_h,    x_l,    Nn * Dd / 4 };
        jobs.j[1] = { t_x,     tx_h,   tx_l,   Tt * Dd / 4 };
        jobs.j[2] = { tfidf,   tf_h,   tf_l,   Tt * Nn / 4 };
        jobs.j[3] = { gat_W,   gatW_h, gatW_l, NHd * Dd * Dd / 4 };
        jobs.j[4] = { t_W,     tW_h,   tW_l,   NHd * Dd * Dd / 4 };
        jobs.j[5] = { gat_fcW, fcWc_h, fcWc_l, NHd * Dd * Dd / 4 };
        jobs.j[6] = { t_fcW,   fcWt_h, fcWt_l, NHd * Dd * Dd / 4 };
        jobs.j[7] = { fus_W,   fusW_h, fusW_l, Dd * Dd / 4 };
        jobs.j[8] = { gc1_W,   gc1W_h, gc1W_l, Dd * H1d / 4 };
        split_all_kernel<<<dim3(512, 9), 256>>>(jobs);
    }

    // 1) both adjacencies -> CSR (one launch)
    build_csr2_kernel<<<Nn + Tt, 256>>>(adj, t_adj, nbr_c, val_c, cnt_c,
                                        nbr_t, val_t, cnt_t);

    // 2) per-head Wh = x @ W[h]  (z = head)
    run_nn({x_h, x_l, gatW_h, gatW_l, nullptr, Wh_c, nullptr, nullptr},
           Nn, Dd, Dd, Dd, Dd, NHd, 0, (size_t)Dd * Dd, (size_t)Nn * Dd);
    run_nn({tx_h, tx_l, tW_h, tW_l, nullptr, Wh_t, nullptr, nullptr},
           Tt, Dd, Dd, Dd, Dd, NHd, 0, (size_t)Dd * Dd, (size_t)Tt * Dd);

    // 3) attention projections f,g (both graphs)
    {
        int warps = NHd * (Nn + Tt);
        fg2_kernel<<<(warps * 32 + 255) / 256, 256>>>(
            Wh_c, gat_asrc, gat_adst, f_c, g_c,
            Wh_t, t_asrc, t_adst, f_t, g_t);
    }

    // 4) sparse attention + aggregation + ELU (both graphs)
    gat_attn2_kernel<<<(Nn + Tt) * NHd / 8, 256>>>(
        Wh_c, f_c, g_c, nbr_c, cnt_c, hcatc_h, hcatc_l,
        Wh_t, f_t, g_t, nbr_t, cnt_t, hcatt_h, hcatt_l);

    // 5) output fc per graph — split-K into partials (z = k-chunk)
    //    fc_c: K=1024 -> 2 x 512; fc_t: K=1024 -> 4 x 256
    run_nn({hcatc_h, hcatc_l, fcWc_h, fcWc_l, nullptr, P0, nullptr, nullptr},
           Nn, Dd, 512, NHd * Dd, Dd, 2, 512, (size_t)512 * Dd, (size_t)Nn * Dd);
    run_nn({hcatt_h, hcatt_l, fcWt_h, fcWt_l, nullptr, P1, nullptr, nullptr},
           Tt, Dd, 256, NHd * Dd, Dd, 4, 256, (size_t)256 * Dd, (size_t)Tt * Dd);

    // 5b) reduce fc_t partials -> gtext hi/lo (+bias)
    reduce4_split_kernel<<<(Tt * Dd / 4 + 255) / 256, 256>>>(
        P1, t_fcb, gtext_h, gtext_l, Tt * Dd / 4, Dd / 4);

    // 6) c_text = tfidf^T @ gat_text — split-K: K=2048 -> 4 x 512
    run_tn({tf_h, tf_l, gtext_h, gtext_l, nullptr, P2, nullptr, nullptr},
           Nn, Dd, 512, Nn, Dd, 4, (size_t)512 * Nn, (size_t)512 * Dd, (size_t)Nn * Dd);

    // 7) fused reduce: concept(P0)+bias, ctext(P2), sigmoid gate -> fused hi/lo
    fuse_reduce_kernel<<<(Nn * Dd / 4 + 255) / 256, 256>>>(
        P0, P2, gat_fcb, fused_h, fused_l, Nn * Dd / 4, Dd / 4);

    // 7b) fusion = fused @ fus_W + fus_b  (split epilogue)
    run_nn({fused_h, fused_l, fusW_h, fusW_l, fus_b, nullptr, fusion_h, fusion_l},
           Nn, Dd, Dd, Dd, Dd);

    // 8) GCN encoder
    run_nn({fusion_h, fusion_l, gc1W_h, gc1W_l, nullptr, tmp1, nullptr, nullptr},
           Nn, H1d, Dd, Dd, H1d);
    spmm_kernel<<<Nn, H1d>>>(nbr_c, val_c, cnt_c, tmp1, h1, H1d, 1);

    gc23_kernel<<<Nn / 64, 256>>>(h1, gc2_W, gc3_W, tmp2a, tmp2b);
    spmm2_kernel<<<Nn, 64>>>(nbr_c, val_c, cnt_c, tmp2a, tmp2b, mu, logvar, mu_h, mu_l);

    // 9) recon = mu @ mu^T
    run_nt({mu_h, mu_l, mu_h, mu_l, nullptr, out, nullptr, nullptr},
           Nn, Nn, H2d, H2d, H2d);
}

// round 12
// speedup vs baseline: 1.2746x; 1.0086x over previous
#include <cuda_runtime.h>
#include <math.h>
#include <stdint.h>

#define Nn   4096
#define Tt   2048
#define Dd   256
#define H1d  128
#define H2d  32
#define NHd  4
#define CAP  96
#define LRELU_ALPHA 0.2f

// ------------------------- scratch (__device__ globals) --------------------
__device__ float g_Wh_c[NHd * Nn * Dd];
__device__ float g_Wh_t[NHd * Tt * Dd];
__device__ float g_f_c[NHd * Nn], g_g_c[NHd * Nn];
__device__ float g_f_t[NHd * Tt], g_g_t[NHd * Tt];
__device__ int   g_nbr_c[Nn * CAP];
__device__ float g_val_c[Nn * CAP];
__device__ int   g_cnt_c[Nn];
__device__ int   g_nbr_t[Tt * CAP];
__device__ float g_val_t[Tt * CAP];
__device__ int   g_cnt_t[Tt];
__device__ float g_tmp1[Nn * H1d];
__device__ float g_h1[Nn * H1d];
__device__ float g_tmp2a[Nn * H2d];
__device__ float g_tmp2b[Nn * H2d];
// split-K partial buffers
__device__ float g_P0[2 * Nn * Dd];
__device__ float g_P1[4 * Tt * Dd];
__device__ float g_P2[4 * Nn * Dd];
// hi/lo planes: A operands [M,K]; B operands [K,N]
__device__ float g_x_h[Nn * Dd],        g_x_l[Nn * Dd];
__device__ float g_tx_h[Tt * Dd],       g_tx_l[Tt * Dd];
__device__ float g_tf_h[Tt * Nn],       g_tf_l[Tt * Nn];
__device__ float g_gatW_h[NHd * Dd * Dd], g_gatW_l[NHd * Dd * Dd];
__device__ float g_tW_h[NHd * Dd * Dd],   g_tW_l[NHd * Dd * Dd];
__device__ float g_fcWc_h[NHd * Dd * Dd], g_fcWc_l[NHd * Dd * Dd];
__device__ float g_fcWt_h[NHd * Dd * Dd], g_fcWt_l[NHd * Dd * Dd];
__device__ float g_fusW_h[Dd * Dd],     g_fusW_l[Dd * Dd];
__device__ float g_gc1W_h[Dd * H1d],    g_gc1W_l[Dd * H1d];
__device__ float g_hcatc_h[Nn * NHd * Dd], g_hcatc_l[Nn * NHd * Dd];
__device__ float g_hcatt_h[Tt * NHd * Dd], g_hcatt_l[Tt * NHd * Dd];
__device__ float g_gtext_h[Tt * Dd],    g_gtext_l[Tt * Dd];
__device__ float g_fused_h[Nn * Dd],    g_fused_l[Nn * Dd];
__device__ float g_fusion_h[Nn * Dd],   g_fusion_l[Nn * Dd];
__device__ float g_mu_h[Nn * H2d],      g_mu_l[Nn * H2d];

// ------------------------- tf32 helpers ------------------------------------
__device__ __forceinline__ void tf32_split_u(float v, uint32_t& h, uint32_t& l) {
    asm("cvt.rna.tf32.f32 %0, %1;" : "=r"(h) : "f"(v));
    float r = v - __uint_as_float(h);
    asm("cvt.rna.tf32.f32 %0, %1;" : "=r"(l) : "f"(r));
}
__device__ __forceinline__ void split_store(float v, float* hp, float* lp, size_t idx) {
    uint32_t h, l; tf32_split_u(v, h, l);
    hp[idx] = __uint_as_float(h); lp[idx] = __uint_as_float(l);
}

#define MMA_TF32(c, a, b)                                                         \
    asm volatile(                                                                  \
        "mma.sync.aligned.m16n8k8.row.col.f32.tf32.tf32.f32 "                      \
        "{%0,%1,%2,%3},{%4,%5,%6,%7},{%8,%9},{%0,%1,%2,%3};"                       \
        : "+f"((c)[0]), "+f"((c)[1]), "+f"((c)[2]), "+f"((c)[3])                   \
        : "r"((a)[0]), "r"((a)[1]), "r"((a)[2]), "r"((a)[3]),                      \
          "r"((b)[0]), "r"((b)[1]))

__device__ __forceinline__ void cp16(void* sp, const void* gp) {
    uint32_t s = (uint32_t)__cvta_generic_to_shared(sp);
    asm volatile("cp.async.cg.shared.global [%0], [%1], 16;" :: "r"(s), "l"(gp));
}

// ------------------------- split_all (harness inputs -> hi/lo) -------------
struct SplitJob { const float* src; float* hi; float* lo; int n4; };
struct SplitJobs9 { SplitJob j[9]; };
__global__ void split_all_kernel(SplitJobs9 jobs) {
    SplitJob jb = jobs.j[blockIdx.y];
    const float4* src = (const float4*)jb.src;
    float4* hi = (float4*)jb.hi;
    float4* lo = (float4*)jb.lo;
    for (int i = blockIdx.x * blockDim.x + threadIdx.x; i < jb.n4;
         i += gridDim.x * blockDim.x) {
        float4 v = src[i];
        uint32_t h, l;
        float4 vh, vl;
        tf32_split_u(v.x, h, l); vh.x = __uint_as_float(h); vl.x = __uint_as_float(l);
        tf32_split_u(v.y, h, l); vh.y = __uint_as_float(h); vl.y = __uint_as_float(l);
        tf32_split_u(v.z, h, l); vh.z = __uint_as_float(h); vl.z = __uint_as_float(l);
        tf32_split_u(v.w, h, l); vh.w = __uint_as_float(h); vl.w = __uint_as_float(l);
        hi[i] = vh; lo[i] = vl;
    }
}

// ------------------------- merged CSR build (both graphs) ------------------
__global__ void build_csr2_kernel(const float* __restrict__ adj,
                                  const float* __restrict__ t_adj,
                                  int* __restrict__ nbr_c, float* __restrict__ val_c,
                                  int* __restrict__ cnt_c,
                                  int* __restrict__ nbr_t, float* __restrict__ val_t,
                                  int* __restrict__ cnt_t) {
    int bi = blockIdx.x;
    const float* row;
    int n, i;
    int* nbr; float* val; int* cnt;
    if (bi < Nn) {
        i = bi; n = Nn; row = adj + (size_t)i * Nn;
        nbr = nbr_c; val = val_c; cnt = cnt_c;
    } else {
        i = bi - Nn; n = Tt; row = t_adj + (size_t)i * Tt;
        nbr = nbr_t; val = val_t; cnt = cnt_t;
    }
    int t = threadIdx.x, lane = t & 31, w = t >> 5;
    int strip = n >> 3;
    int s0 = w * strip;
    __shared__ int s_cnt[8];
    int my = 0;
    for (int b = s0; b < s0 + strip; b += 32) {
        bool p = row[b + lane] > 0.0f;
        unsigned m = __ballot_sync(0xffffffffu, p);
        my += __popc(m);
    }
    if (lane == 0) s_cnt[w] = my;
    __syncthreads();
    int off = 0;
    #pragma unroll
    for (int ww = 0; ww < 8; ww++) if (ww < w) off += s_cnt[ww];
    int tot = 0;
    #pragma unroll
    for (int ww = 0; ww < 8; ww++) tot += s_cnt[ww];
    for (int b = s0; b < s0 + strip; b += 32) {
        float v = row[b + lane];
        bool p = v > 0.0f;
        unsigned m = __ballot_sync(0xffffffffu, p);
        int pos = off + __popc(m & ((1u << lane) - 1u));
        if (p && pos < CAP) { nbr[i * CAP + pos] = b + lane; val[i * CAP + pos] = v; }
        off += __popc(m);
    }
    if (t == 0) cnt[i] = min(tot, CAP);
}

// ------------------------- GEMM core (shared by both entry points) ---------
#define BMt 128
#define BNt 64
#define BKt 16

struct ZJob {
    const float *Ah, *Al, *Bh, *Bl;
    float *C, *Ch, *Cl;
    const float* bias;
    int M, N, K, lda, ldb;
};
struct ZJobs8 { ZJob z[8]; };

template <bool TA, bool TB>
__device__ __forceinline__ void gemm_body(
    const float* __restrict__ Ah, const float* __restrict__ Al,
    const float* __restrict__ Bh, const float* __restrict__ Bl,
    const float* __restrict__ bias, float* __restrict__ C,
    float* __restrict__ Ch, float* __restrict__ Cl,
    int M, int N, int K, int lda, int ldb, int bm, int bn) {
    constexpr int AR = TA ? BKt : BMt;
    constexpr int AC = TA ? (BMt + 8) : (BKt + 4);
    constexpr int BR = TB ? BNt : BKt;
    constexpr int BC = TB ? (BKt + 4) : (BNt + 8);
    __shared__ float As[2][2][AR][AC];
    __shared__ float Bs[2][2][BR][BC];

    const float* Abp[2] = { Ah, Al };
    const float* Bbp[2] = { Bh, Bl };
    int t = threadIdx.x, lane = t & 31, w = t >> 5;
    int wm = (w & 3) * 32, wn = (w >> 2) * 32;
    int gid = lane >> 2, tig = lane & 3;

    float acc[2][4][4] = {};

    auto load_tile = [&](int s, int k0) {
        #pragma unroll
        for (int p = 0; p < 2; p++) {
            if (!TA) {
                #pragma unroll
                for (int j = 0; j < 2; j++) {
                    int idx = t + j * 256;
                    int row = idx >> 2;
                    int col = (idx & 3) * 4;
                    cp16(&As[s][p][row][col], Abp[p] + (size_t)(bm + row) * lda + k0 + col);
                }
            } else {
                #pragma unroll
                for (int j = 0; j < 2; j++) {
                    int idx = t + j * 256;
                    int row = idx >> 5;
                    int col = (idx & 31) * 4;
                    cp16(&As[s][p][row][col], Abp[p] + (size_t)(k0 + row) * lda + bm + col);
                }
            }
            if (!TB) {
                int row = t >> 4;
                int col = (t & 15) * 4;
                cp16(&Bs[s][p][row][col], Bbp[p] + (size_t)(k0 + row) * ldb + bn + col);
            } else {
                int row = t >> 2;
                int col = (t & 3) * 4;
                cp16(&Bs[s][p][row][col], Bbp[p] + (size_t)(bn + row) * ldb + k0 + col);
            }
        }
    };

    auto Ae = [&](int s, int p, int k, int m) -> float {
        return TA ? As[s][p][k][m] : As[s][p][m][k];
    };
    auto Be = [&](int s, int p, int k, int nn) -> float {
        return TB ? Bs[s][p][nn][k] : Bs[s][p][k][nn];
    };

    int nk = K / BKt;
    load_tile(0, 0);
    asm volatile("cp.async.commit_group;");

    for (int kt = 0; kt < nk; kt++) {
        int s = kt & 1;
        if (kt + 1 < nk) {
            load_tile(s ^ 1, (kt + 1) * BKt);
            asm volatile("cp.async.commit_group;");
            asm volatile("cp.async.wait_group 1;");
        } else {
            asm volatile("cp.async.wait_group 0;");
        }
        __syncthreads();

        #pragma unroll
        for (int kk = 0; kk < BKt; kk += 8) {
            uint32_t ah[2][4], al[2][4], bh[4][2], bl[4][2];
            #pragma unroll
            for (int mt = 0; mt < 2; mt++) {
                int m0 = wm + mt * 16 + gid;
                ah[mt][0] = __float_as_uint(Ae(s, 0, kk + tig,     m0));
                ah[mt][1] = __float_as_uint(Ae(s, 0, kk + tig,     m0 + 8));
                ah[mt][2] = __float_as_uint(Ae(s, 0, kk + tig + 4, m0));
                ah[mt][3] = __float_as_uint(Ae(s, 0, kk + tig + 4, m0 + 8));
                al[mt][0] = __float_as_uint(Ae(s, 1, kk + tig,     m0));
                al[mt][1] = __float_as_uint(Ae(s, 1, kk + tig,     m0 + 8));
                al[mt][2] = __float_as_uint(Ae(s, 1, kk + tig + 4, m0));
                al[mt][3] = __float_as_uint(Ae(s, 1, kk + tig + 4, m0 + 8));
            }
            #pragma unroll
            for (int nt = 0; nt < 4; nt++) {
                int n0 = wn + nt * 8 + gid;
                bh[nt][0] = __float_as_uint(Be(s, 0, kk + tig,     n0));
                bh[nt][1] = __float_as_uint(Be(s, 0, kk + tig + 4, n0));
                bl[nt][0] = __float_as_uint(Be(s, 1, kk + tig,     n0));
                bl[nt][1] = __float_as_uint(Be(s, 1, kk + tig + 4, n0));
            }
            #pragma unroll
            for (int mt = 0; mt < 2; mt++)
                #pragma unroll
                for (int nt = 0; nt < 4; nt++) {
                    MMA_TF32(acc[mt][nt], al[mt], bh[nt]);
                    MMA_TF32(acc[mt][nt], ah[mt], bl[nt]);
                    MMA_TF32(acc[mt][nt], ah[mt], bh[nt]);
                }
        }
        __syncthreads();
    }

    #pragma unroll
    for (int mt = 0; mt < 2; mt++) {
        int row0 = bm + wm + mt * 16 + gid;
        #pragma unroll
        for (int nt = 0; nt < 4; nt++) {
            int col = bn + wn + nt * 8 + tig * 2;
            float bx = bias ? bias[col] : 0.0f;
            float by = bias ? bias[col + 1] : 0.0f;
            float v00 = acc[mt][nt][0] + bx, v01 = acc[mt][nt][1] + by;
            float v10 = acc[mt][nt][2] + bx, v11 = acc[mt][nt][3] + by;
            size_t i0 = (size_t)row0 * N + col;
            size_t i1 = (size_t)(row0 + 8) * N + col;
            if (C) {
                *reinterpret_cast<float2*>(&C[i0]) = make_float2(v00, v01);
                *reinterpret_cast<float2*>(&C[i1]) = make_float2(v10, v11);
            }
            if (Ch) {
                uint32_t h, l;
                float2 h0, l0, h1, l1;
                tf32_split_u(v00, h, l); h0.x = __uint_as_float(h); l0.x = __uint_as_float(l);
                tf32_split_u(v01, h, l); h0.y = __uint_as_float(h); l0.y = __uint_as_float(l);
                tf32_split_u(v10, h, l); h1.x = __uint_as_float(h); l1.x = __uint_as_float(l);
                tf32_split_u(v11, h, l); h1.y = __uint_as_float(h); l1.y = __uint_as_float(l);
                *reinterpret_cast<float2*>(&Ch[i0]) = h0;
                *reinterpret_cast<float2*>(&Cl[i0]) = l0;
                *reinterpret_cast<float2*>(&Ch[i1]) = h1;
                *reinterpret_cast<float2*>(&Cl[i1]) = l1;
            }
        }
    }
}

// single-job entry (tn / nt / nn with z-strides)
template <bool TA, bool TB>
__global__ void __launch_bounds__(256) mma_gemm_kernel(
    const float* __restrict__ Ah, const float* __restrict__ Al,
    const float* __restrict__ Bh, const float* __restrict__ Bl,
    const float* __restrict__ bias, float* __restrict__ C,
    float* __restrict__ Ch, float* __restrict__ Cl,
    int M, int N, int K, int lda, int ldb,
    size_t sA, size_t sB, size_t sC) {
    gemm_body<TA, TB>(Ah + (size_t)blockIdx.z * sA, Al + (size_t)blockIdx.z * sA,
                      Bh + (size_t)blockIdx.z * sB, Bl + (size_t)blockIdx.z * sB,
                      bias,
                      C  ? C  + (size_t)blockIdx.z * sC : nullptr,
                      Ch ? Ch + (size_t)blockIdx.z * sC : nullptr,
                      Cl ? Cl + (size_t)blockIdx.z * sC : nullptr,
                      M, N, K, lda, ldb,
                      blockIdx.y * BMt, blockIdx.x * BNt);
}

// multi-job entry: blockIdx.z selects descriptor; oversized blocks exit early
__global__ void __launch_bounds__(256) mma_gemm_jobs_kernel(ZJobs8 jobs) {
    ZJob j = jobs.z[blockIdx.z];
    int bm = blockIdx.y * BMt, bn = blockIdx.x * BNt;
    if (bm >= j.M || bn >= j.N) return;
    gemm_body<false, false>(j.Ah, j.Al, j.Bh, j.Bl, j.bias, j.C, j.Ch, j.Cl,
                            j.M, j.N, j.K, j.lda, j.ldb, bm, bn);
}

// ------------------------- split-K reduce: 4 partials -> split planes ------
__global__ void reduce4_split_kernel(const float* __restrict__ P,
                                     const float* __restrict__ bias,
                                     float* __restrict__ oh, float* __restrict__ ol,
                                     int MN4, int Ncols4) {
    int i = blockIdx.x * blockDim.x + threadIdx.x;
    if (i >= MN4) return;
    const float4* p = (const float4*)P;
    float4 a = p[i], b = p[i + MN4], c = p[i + 2 * MN4], d = p[i + 3 * MN4];
    float4 bv = ((const float4*)bias)[i % Ncols4];
    size_t base = (size_t)i * 4;
    split_store((a.x + b.x) + (c.x + d.x) + bv.x, oh, ol, base);
    split_store((a.y + b.y) + (c.y + d.y) + bv.y, oh, ol, base + 1);
    split_store((a.z + b.z) + (c.z + d.z) + bv.z, oh, ol, base + 2);
    split_store((a.w + b.w) + (c.w + d.w) + bv.w, oh, ol, base + 3);
}

// ------------- fused reduce (fc_c 2 partials + bias; tfidf 4 partials) -----
__global__ void fuse_reduce_kernel(const float* __restrict__ P0,
                                   const float* __restrict__ P2,
                                   const float* __restrict__ bias,
                                   float* __restrict__ oh, float* __restrict__ ol,
                                   int MN4, int Ncols4) {
    int i = blockIdx.x * blockDim.x + threadIdx.x;
    if (i >= MN4) return;
    const float4* p0 = (const float4*)P0;
    const float4* p2 = (const float4*)P2;
    float4 a = p0[i], b = p0[i + MN4];
    float4 c0 = p2[i], c1 = p2[i + MN4], c2 = p2[i + 2 * MN4], c3 = p2[i + 3 * MN4];
    float4 bv = ((const float4*)bias)[i % Ncols4];
    float con[4] = { a.x + b.x + bv.x, a.y + b.y + bv.y,
                     a.z + b.z + bv.z, a.w + b.w + bv.w };
    float ct[4] = { (c0.x + c1.x) + (c2.x + c3.x), (c0.y + c1.y) + (c2.y + c3.y),
                    (c0.z + c1.z) + (c2.z + c3.z), (c0.w + c1.w) + (c2.w + c3.w) };
    size_t base = (size_t)i * 4;
    #pragma unroll
    for (int u = 0; u < 4; u++) {
        float z = 1.0f / (1.0f + expf(-(con[u] + ct[u])));
        split_store(z * con[u] + (1.0f - z) * ct[u], oh, ol, base + u);
    }
}

// ------------------------- gc2 & gc3 fused SIMT GEMM -----------------------
__global__ void gc23_kernel(const float* __restrict__ A, const float* __restrict__ B2,
                            const float* __restrict__ B3, float* __restrict__ C2,
                            float* __restrict__ C3) {
    __shared__ __align__(16) float As[16][64];
    __shared__ __align__(16) float Bs[16][64];
    int bm = blockIdx.x * 64;
    int t = threadIdx.x, tx = t & 15, ty = t >> 4;
    float acc[4][4] = {};
    for (int k0 = 0; k0 < H1d; k0 += 16) {
        #pragma unroll
        for (int j = 0; j < 4; j++) {
            int li = t + j * 256;
            int r = li >> 4, c = li & 15;
            As[c][r] = A[(size_t)(bm + r) * H1d + k0 + c];
            int rb = li >> 6, cb = li & 63;
            Bs[rb][cb] = (cb < 32) ? B2[(k0 + rb) * H2d + cb]
                                   : B3[(k0 + rb) * H2d + cb - 32];
        }
        __syncthreads();
        #pragma unroll
        for (int k = 0; k < 16; k++) {
            float4 a4 = *reinterpret_cast<const float4*>(&As[k][ty << 2]);
            float4 b4 = *reinterpret_cast<const float4*>(&Bs[k][tx << 2]);
            float a[4] = {a4.x, a4.y, a4.z, a4.w};
            float b[4] = {b4.x, b4.y, b4.z, b4.w};
            #pragma unroll
            for (int u = 0; u < 4; u++)
                #pragma unroll
                for (int v = 0; v < 4; v++)
                    acc[u][v] += a[u] * b[v];
        }
        __syncthreads();
    }
    #pragma unroll
    for (int u = 0; u < 4; u++) {
        int row = bm + (ty << 2) + u;
        #pragma unroll
        for (int v = 0; v < 4; v++) {
            int col = (tx << 2) + v;
            if (col < 32) C2[(size_t)row * H2d + col] = acc[u][v];
            else          C3[(size_t)row * H2d + col - 32] = acc[u][v];
        }
    }
}

// ------------------------- merged f/g projections --------------------------
__global__ void fg2_kernel(const float* __restrict__ Wh_c, const float* __restrict__ asrc_c,
                           const float* __restrict__ adst_c, float* __restrict__ f_c,
                           float* __restrict__ g_c,
                           const float* __restrict__ Wh_t, const float* __restrict__ asrc_t,
                           const float* __restrict__ adst_t, float* __restrict__ f_t,
                           float* __restrict__ g_t) {
    int gw = (blockIdx.x * blockDim.x + threadIdx.x) >> 5;
    int lane = threadIdx.x & 31;
    const float* Wh; const float* asrc; const float* adst; float* f; float* g;
    int n;
    if (gw < NHd * Nn) {
        Wh = Wh_c; asrc = asrc_c; adst = adst_c; f = f_c; g = g_c; n = Nn;
    } else {
        gw -= NHd * Nn;
        if (gw >= NHd * Tt) return;
        Wh = Wh_t; asrc = asrc_t; adst = adst_t; f = f_t; g = g_t; n = Tt;
    }
    int h = gw / n, i = gw - h * n;
    const float* wp = Wh + ((size_t)h * n + i) * Dd;
    const float* as = asrc + h * Dd;
    const float* ad = adst + h * Dd;
    float accf = 0.0f, accg = 0.0f;
    #pragma unroll
    for (int c = 0; c < Dd / 32; c++) {
        float v = wp[lane + 32 * c];
        accf += v * as[lane + 32 * c];
        accg += v * ad[lane + 32 * c];
    }
    #pragma unroll
    for (int o = 16; o; o >>= 1) {
        accf += __shfl_down_sync(0xffffffffu, accf, o);
        accg += __shfl_down_sync(0xffffffffu, accg, o);
    }
    if (lane == 0) { f[gw] = accf; g[gw] = accg; }
}

// ------------------------- merged warp-per-(i,h) GAT attention -------------
__global__ void __launch_bounds__(256) gat_attn2_kernel(
    const float* __restrict__ Wh_c, const float* __restrict__ f_c,
    const float* __restrict__ g_c, const int* __restrict__ nbr_c,
    const int* __restrict__ cnt_c, float* __restrict__ hcatc_h,
    float* __restrict__ hcatc_l,
    const float* __restrict__ Wh_t, const float* __restrict__ f_t,
    const float* __restrict__ g_t, const int* __restrict__ nbr_t,
    const int* __restrict__ cnt_t, float* __restrict__ hcatt_h,
    float* __restrict__ hcatt_l) {
    int w = threadIdx.x >> 5, lane = threadIdx.x & 31;
    int gw = blockIdx.x * 8 + w;
    const float* Wh; const float* f; const float* g;
    const int* nbr; const int* cnt; float* hcat_h; float* hcat_l;
    int n;
    if (gw < Nn * NHd) {
        Wh = Wh_c; f = f_c; g = g_c; nbr = nbr_c; cnt = cnt_c;
        hcat_h = hcatc_h; hcat_l = hcatc_l; n = Nn;
    } else {
        gw -= Nn * NHd;
        Wh = Wh_t; f = f_t; g = g_t; nbr = nbr_t; cnt = cnt_t;
        hcat_h = hcatt_h; hcat_l = hcatt_l; n = Tt;
    }
    int i = gw >> 2, h = gw & 3;
    __shared__ int   sj[8][CAP];
    __shared__ float sw[8][CAP];
    int c = cnt[i];
    const int* jb = nbr + i * CAP;
    float fi = f[h * n + i];
    float m = -1e30f;
    for (int k = lane; k < c; k += 32) {
        int j = jb[k];
        sj[w][k] = j;
        float s = fi + g[h * n + j];
        s = (s >= 0.0f) ? s : LRELU_ALPHA * s;
        sw[w][k] = s;
        m = fmaxf(m, s);
    }
    #pragma unroll
    for (int o = 16; o; o >>= 1) m = fmaxf(m, __shfl_xor_sync(0xffffffffu, m, o));
    __syncwarp();
    float sum = 0.0f;
    for (int k = lane; k < c; k += 32) {
        float e = expf(sw[w][k] - m);
        sw[w][k] = e;
        sum += e;
    }
    #pragma unroll
    for (int o = 16; o; o >>= 1) sum += __shfl_xor_sync(0xffffffffu, sum, o);
    float dinv = 1.0f / sum;
    __syncwarp();
    const float* base = Wh + (size_t)h * n * Dd;
    float acc[8] = {};
    int k = 0;
    for (; k + 2 <= c; k += 2) {
        float w0 = sw[w][k], w1 = sw[w][k + 1];
        const float* r0 = base + (size_t)sj[w][k] * Dd + lane;
        const float* r1 = base + (size_t)sj[w][k + 1] * Dd + lane;
        #pragma unroll
        for (int ch = 0; ch < 8; ch++) {
            acc[ch] += w0 * __ldg(r0 + ch * 32);
            acc[ch] += w1 * __ldg(r1 + ch * 32);
        }
    }
    if (k < c) {
        float w0 = sw[w][k];
        const float* r0 = base + (size_t)sj[w][k] * Dd + lane;
        #pragma unroll
        for (int ch = 0; ch < 8; ch++) acc[ch] += w0 * __ldg(r0 + ch * 32);
    }
    size_t obase = (size_t)i * (NHd * Dd) + h * Dd + lane;
    #pragma unroll
    for (int ch = 0; ch < 8; ch++) {
        float v = acc[ch] * dinv;
        v = (v > 0.0f) ? v : expm1f(v);
        split_store(v, hcat_h, hcat_l, obase + ch * 32);
    }
}

// ------------------------- sparse adj @ X, optional ReLU -------------------
__global__ void spmm_kernel(const int* __restrict__ nbr, const float* __restrict__ val,
                            const int* __restrict__ cnt, const float* __restrict__ X,
                            float* __restrict__ Y, int ncols, int do_relu) {
    int i = blockIdx.x;
    int t = threadIdx.x;
    int c = cnt[i];
    const int* jb = nbr + i * CAP;
    const float* vb = val + i * CAP;
    float a0 = 0.0f, a1 = 0.0f, a2 = 0.0f, a3 = 0.0f;
    int k = 0;
    for (; k + 4 <= c; k += 4) {
        a0 += vb[k]     * __ldg(X + (size_t)jb[k]     * ncols + t);
        a1 += vb[k + 1] * __ldg(X + (size_t)jb[k + 1] * ncols + t);
        a2 += vb[k + 2] * __ldg(X + (size_t)jb[k + 2] * ncols + t);
        a3 += vb[k + 3] * __ldg(X + (size_t)jb[k + 3] * ncols + t);
    }
    for (; k < c; k++)
        a0 += vb[k] * __ldg(X + (size_t)jb[k] * ncols + t);
    float acc = (a0 + a1) + (a2 + a3);
    if (do_relu) acc = fmaxf(acc, 0.0f);
    Y[(size_t)i * ncols + t] = acc;
}

// ------------------------- fused mu/logvar spmm ----------------------------
__global__ void spmm2_kernel(const int* __restrict__ nbr, const float* __restrict__ val,
                             const int* __restrict__ cnt, const float* __restrict__ X2,
                             const float* __restrict__ X3, float* __restrict__ mu,
                             float* __restrict__ logvar, float* __restrict__ mu_h,
                             float* __restrict__ mu_l) {
    int i = blockIdx.x;
    int t = threadIdx.x;
    int sel = t >> 5, col = t & 31;
    const float* X = sel ? X3 : X2;
    int c = cnt[i];
    const int* jb = nbr + i * CAP;
    const float* vb = val + i * CAP;
    float a0 = 0.0f, a1 = 0.0f, a2 = 0.0f, a3 = 0.0f;
    int k = 0;
    for (; k + 4 <= c; k += 4) {
        a0 += vb[k]     * __ldg(X + (size_t)jb[k]     * H2d + col);
        a1 += vb[k + 1] * __ldg(X + (size_t)jb[k + 1] * H2d + col);
        a2 += vb[k + 2] * __ldg(X + (size_t)jb[k + 2] * H2d + col);
        a3 += vb[k + 3] * __ldg(X + (size_t)jb[k + 3] * H2d + col);
    }
    for (; k < c; k++)
        a0 += vb[k] * __ldg(X + (size_t)jb[k] * H2d + col);
    float v = (a0 + a1) + (a2 + a3);
    size_t idx = (size_t)i * H2d + col;
    if (sel == 0) {
        mu[idx] = v;
        split_store(v, mu_h, mu_l, idx);
    } else {
        logvar[idx] = v;
    }
}

// ------------------------- host-side launch helpers ------------------------
struct GemmArgs {
    const float *Ah, *Al, *Bh, *Bl, *bias;
    float *C, *Ch, *Cl;
};
static inline void run_nn(GemmArgs a, int M, int N, int K, int lda, int ldb,
                          int nz = 1, size_t sA = 0, size_t sB = 0, size_t sC = 0) {
    dim3 grid(N / BNt, M / BMt, nz);
    mma_gemm_kernel<false, false><<<grid, 256>>>(a.Ah, a.Al, a.Bh, a.Bl, a.bias,
                                                 a.C, a.Ch, a.Cl, M, N, K, lda, ldb,
                                                 sA, sB, sC);
}
static inline void run_tn(GemmArgs a, int M, int N, int K, int lda, int ldb,
                          int nz = 1, size_t sA = 0, size_t sB = 0, size_t sC = 0) {
    dim3 grid(N / BNt, M / BMt, nz);
    mma_gemm_kernel<true, false><<<grid, 256>>>(a.Ah, a.Al, a.Bh, a.Bl, a.bias,
                                                a.C, a.Ch, a.Cl, M, N, K, lda, ldb,
                                                sA, sB, sC);
}
static inline void run_nt(GemmArgs a, int M, int N, int K, int lda, int ldb) {
    dim3 grid(N / BNt, M / BMt, 1);
    mma_gemm_kernel<false, true><<<grid, 256>>>(a.Ah, a.Al, a.Bh, a.Bl, a.bias,
                                                a.C, a.Ch, a.Cl, M, N, K, lda, ldb,
                                                0, 0, 0);
}

#define SYM(p, s) cudaGetSymbolAddress((void**)&p, s)

extern "C" void kernel_launch(void* const* d_in, const int* in_sizes, int n_in,
                              void* d_out, int out_size) {
    const float* x        = (const float*)d_in[0];
    const float* adj      = (const float*)d_in[1];
    const float* t_x      = (const float*)d_in[2];
    const float* t_adj    = (const float*)d_in[3];
    const float* tfidf    = (const float*)d_in[4];
    const float* gat_W    = (const float*)d_in[5];
    const float* gat_asrc = (const float*)d_in[6];
    const float* gat_adst = (const float*)d_in[7];
    const float* gat_fcW  = (const float*)d_in[8];
    const float* gat_fcb  = (const float*)d_in[9];
    const float* t_W      = (const float*)d_in[10];
    const float* t_asrc   = (const float*)d_in[11];
    const float* t_adst   = (const float*)d_in[12];
    const float* t_fcW    = (const float*)d_in[13];
    const float* t_fcb    = (const float*)d_in[14];
    const float* fus_W    = (const float*)d_in[15];
    const float* fus_b    = (const float*)d_in[16];
    const float* gc1_W    = (const float*)d_in[17];
    const float* gc2_W    = (const float*)d_in[18];
    const float* gc3_W    = (const float*)d_in[19];

    float* out    = (float*)d_out;
    float* mu     = out + (size_t)Nn * Nn;
    float* logvar = mu + (size_t)Nn * H2d;

    float *Wh_c, *Wh_t, *f_c, *g_c, *f_t, *g_t, *val_c, *val_t;
    float *tmp1, *h1, *tmp2a, *tmp2b, *P0, *P1, *P2;
    int *nbr_c, *cnt_c, *nbr_t, *cnt_t;
    float *x_h, *x_l, *tx_h, *tx_l, *tf_h, *tf_l;
    float *gatW_h, *gatW_l, *tW_h, *tW_l, *fcWc_h, *fcWc_l, *fcWt_h, *fcWt_l;
    float *fusW_h, *fusW_l, *gc1W_h, *gc1W_l;
    float *hcatc_h, *hcatc_l, *hcatt_h, *hcatt_l, *gtext_h, *gtext_l;
    float *fused_h, *fused_l, *fusion_h, *fusion_l, *mu_h, *mu_l;
    SYM(Wh_c, g_Wh_c);  SYM(Wh_t, g_Wh_t);
    SYM(f_c, g_f_c);    SYM(g_c, g_g_c);   SYM(f_t, g_f_t);  SYM(g_t, g_g_t);
    SYM(nbr_c, g_nbr_c); SYM(val_c, g_val_c); SYM(cnt_c, g_cnt_c);
    SYM(nbr_t, g_nbr_t); SYM(val_t, g_val_t); SYM(cnt_t, g_cnt_t);
    SYM(tmp1, g_tmp1); SYM(h1, g_h1); SYM(tmp2a, g_tmp2a); SYM(tmp2b, g_tmp2b);
    SYM(P0, g_P0); SYM(P1, g_P1); SYM(P2, g_P2);
    SYM(x_h, g_x_h);   SYM(x_l, g_x_l);  SYM(tx_h, g_tx_h); SYM(tx_l, g_tx_l);
    SYM(tf_h, g_tf_h); SYM(tf_l, g_tf_l);
    SYM(gatW_h, g_gatW_h); SYM(gatW_l, g_gatW_l);
    SYM(tW_h, g_tW_h);     SYM(tW_l, g_tW_l);
    SYM(fcWc_h, g_fcWc_h); SYM(fcWc_l, g_fcWc_l);
    SYM(fcWt_h, g_fcWt_h); SYM(fcWt_l, g_fcWt_l);
    SYM(fusW_h, g_fusW_h); SYM(fusW_l, g_fusW_l);
    SYM(gc1W_h, g_gc1W_h); SYM(gc1W_l, g_gc1W_l);
    SYM(hcatc_h, g_hcatc_h); SYM(hcatc_l, g_hcatc_l);
    SYM(hcatt_h, g_hcatt_h); SYM(hcatt_l, g_hcatt_l);
    SYM(gtext_h, g_gtext_h); SYM(gtext_l, g_gtext_l);
    SYM(fused_h, g_fused_h); SYM(fused_l, g_fused_l);
    SYM(fusion_h, g_fusion_h); SYM(fusion_l, g_fusion_l);
    SYM(mu_h, g_mu_h); SYM(mu_l, g_mu_l);

    // 0) split ALL harness inputs into tf32 hi/lo planes (no transpose)
    {
        SplitJobs9 jobs;
        jobs.j[0] = { x,       x_h,    x_l,    Nn * Dd / 4 };
        jobs.j[1] = { t_x,     tx_h,   tx_l,   Tt * Dd / 4 };
        jobs.j[2] = { tfidf,   tf_h,   tf_l,   Tt * Nn / 4 };
        jobs.j[3] = { gat_W,   gatW_h, gatW_l, NHd * Dd * Dd / 4 };
        jobs.j[4] = { t_W,     tW_h,   tW_l,   NHd * Dd * Dd / 4 };
        jobs.j[5] = { gat_fcW, fcWc_h, fcWc_l, NHd * Dd * Dd / 4 };
        jobs.j[6] = { t_fcW,   fcWt_h, fcWt_l, NHd * Dd * Dd / 4 };
        jobs.j[7] = { fus_W,   fusW_h, fusW_l, Dd * Dd / 4 };
        jobs.j[8] = { gc1_W,   gc1W_h, gc1W_l, Dd * H1d / 4 };
        split_all_kernel<<<dim3(512, 9), 256>>>(jobs);
    }

    // 1) both adjacencies -> CSR (one launch)
    build_csr2_kernel<<<Nn + Tt, 256>>>(adj, t_adj, nbr_c, val_c, cnt_c,
                                        nbr_t, val_t, cnt_t);

    // 2) per-head Wh for BOTH graphs in ONE launch (8 z-jobs)
    {
        ZJobs8 jb;
        for (int h = 0; h < NHd; h++) {
            jb.z[h] = { x_h, x_l,
                        gatW_h + (size_t)h * Dd * Dd, gatW_l + (size_t)h * Dd * Dd,
                        Wh_c + (size_t)h * Nn * Dd, nullptr, nullptr, nullptr,
                        Nn, Dd, Dd, Dd, Dd };
            jb.z[NHd + h] = { tx_h, tx_l,
                        tW_h + (size_t)h * Dd * Dd, tW_l + (size_t)h * Dd * Dd,
                        Wh_t + (size_t)h * Tt * Dd, nullptr, nullptr, nullptr,
                        Tt, Dd, Dd, Dd, Dd };
        }
        mma_gemm_jobs_kernel<<<dim3(Dd / BNt, Nn / BMt, 8), 256>>>(jb);
    }

    // 3) attention projections f,g (both graphs)
    {
        int warps = NHd * (Nn + Tt);
        fg2_kernel<<<(warps * 32 + 255) / 256, 256>>>(
            Wh_c, gat_asrc, gat_adst, f_c, g_c,
            Wh_t, t_asrc, t_adst, f_t, g_t);
    }

    // 4) sparse attention + aggregation + ELU (both graphs)
    gat_attn2_kernel<<<(Nn + Tt) * NHd / 8, 256>>>(
        Wh_c, f_c, g_c, nbr_c, cnt_c, hcatc_h, hcatc_l,
        Wh_t, f_t, g_t, nbr_t, cnt_t, hcatt_h, hcatt_l);

    // 5) both fc GEMMs, split-K, ONE launch (6 z-jobs)
    {
        ZJobs8 jb;
        for (int c = 0; c < 2; c++)
            jb.z[c] = { hcatc_h + (size_t)c * 512, hcatc_l + (size_t)c * 512,
                        fcWc_h + (size_t)c * 512 * Dd, fcWc_l + (size_t)c * 512 * Dd,
                        P0 + (size_t)c * Nn * Dd, nullptr, nullptr, nullptr,
                        Nn, Dd, 512, NHd * Dd, Dd };
        for (int c = 0; c < 4; c++)
            jb.z[2 + c] = { hcatt_h + (size_t)c * 256, hcatt_l + (size_t)c * 256,
                        fcWt_h + (size_t)c * 256 * Dd, fcWt_l + (size_t)c * 256 * Dd,
                        P1 + (size_t)c * Tt * Dd, nullptr, nullptr, nullptr,
                        Tt, Dd, 256, NHd * Dd, Dd };
        for (int c = 6; c < 8; c++) jb.z[c] = jb.z[0];  // unused
        mma_gemm_jobs_kernel<<<dim3(Dd / BNt, Nn / BMt, 6), 256>>>(jb);
    }

    // 5b) reduce fc_t partials -> gtext hi/lo (+bias)
    reduce4_split_kernel<<<(Tt * Dd / 4 + 255) / 256, 256>>>(
        P1, t_fcb, gtext_h, gtext_l, Tt * Dd / 4, Dd / 4);

    // 6) c_text = tfidf^T @ gat_text — split-K: K=2048 -> 4 x 512
    run_tn({tf_h, tf_l, gtext_h, gtext_l, nullptr, P2, nullptr, nullptr},
           Nn, Dd, 512, Nn, Dd, 4, (size_t)512 * Nn, (size_t)512 * Dd, (size_t)Nn * Dd);

    // 7) fused reduce: concept(P0)+bias, ctext(P2), sigmoid gate -> fused hi/lo
    fuse_reduce_kernel<<<(Nn * Dd / 4 + 255) / 256, 256>>>(
        P0, P2, gat_fcb, fused_h, fused_l, Nn * Dd / 4, Dd / 4);

    // 7b) fusion = fused @ fus_W + fus_b  (split epilogue)
    run_nn({fused_h, fused_l, fusW_h, fusW_l, fus_b, nullptr, fusion_h, fusion_l},
           Nn, Dd, Dd, Dd, Dd);

    // 8) GCN encoder
    run_nn({fusion_h, fusion_l, gc1W_h, gc1W_l, nullptr, tmp1, nullptr, nullptr},
           Nn, H1d, Dd, Dd, H1d);
    spmm_kernel<<<Nn, H1d>>>(nbr_c, val_c, cnt_c, tmp1, h1, H1d, 1);

    gc23_kernel<<<Nn / 64, 256>>>(h1, gc2_W, gc3_W, tmp2a, tmp2b);
    spmm2_kernel<<<Nn, 64>>>(nbr_c, val_c, cnt_c, tmp2a, tmp2b, mu, logvar, mu_h, mu_l);

    // 9) recon = mu @ mu^T
    run_nt({mu_h, mu_l, mu_h, mu_l, nullptr, out, nullptr, nullptr},
           Nn, Nn, H2d, H2d, H2d);
}

// round 13
// speedup vs baseline: 1.3326x; 1.0456x over previous
#include <cuda_runtime.h>
#include <math.h>
#include <stdint.h>

#define Nn   4096
#define Tt   2048
#define Dd   256
#define H1d  128
#define H2d  32
#define NHd  4
#define CAP  96
#define LRELU_ALPHA 0.2f

// ------------------------- scratch (__device__ globals) --------------------
__device__ float g_Wh_c[NHd * Nn * Dd];
__device__ float g_Wh_t[NHd * Tt * Dd];
__device__ float g_f_c[NHd * Nn], g_g_c[NHd * Nn];
__device__ float g_f_t[NHd * Tt], g_g_t[NHd * Tt];
__device__ int   g_nbr_c[Nn * CAP];
__device__ float g_val_c[Nn * CAP];
__device__ int   g_cnt_c[Nn];
__device__ int   g_nbr_t[Tt * CAP];
__device__ float g_val_t[Tt * CAP];
__device__ int   g_cnt_t[Tt];
__device__ float g_tmp1[Nn * H1d];
__device__ float g_h1[Nn * H1d];
__device__ float g_tmp2a[Nn * H2d];
__device__ float g_tmp2b[Nn * H2d];
// split-K partial buffers
__device__ float g_P0[2 * Nn * Dd];
__device__ float g_P1[4 * Tt * Dd];
__device__ float g_P2[4 * Nn * Dd];
// hi/lo planes (weights + intermediates only; big A operands stay raw)
__device__ float g_gatW_h[NHd * Dd * Dd], g_gatW_l[NHd * Dd * Dd];
__device__ float g_tW_h[NHd * Dd * Dd],   g_tW_l[NHd * Dd * Dd];
__device__ float g_fcWc_h[NHd * Dd * Dd], g_fcWc_l[NHd * Dd * Dd];
__device__ float g_fcWt_h[NHd * Dd * Dd], g_fcWt_l[NHd * Dd * Dd];
__device__ float g_fusW_h[Dd * Dd],     g_fusW_l[Dd * Dd];
__device__ float g_gc1W_h[Dd * H1d],    g_gc1W_l[Dd * H1d];
__device__ float g_hcatc_h[Nn * NHd * Dd], g_hcatc_l[Nn * NHd * Dd];
__device__ float g_hcatt_h[Tt * NHd * Dd], g_hcatt_l[Tt * NHd * Dd];
__device__ float g_gtext_h[Tt * Dd],    g_gtext_l[Tt * Dd];
__device__ float g_fused_h[Nn * Dd],    g_fused_l[Nn * Dd];
__device__ float g_fusion_h[Nn * Dd],   g_fusion_l[Nn * Dd];
__device__ float g_mu_h[Nn * H2d],      g_mu_l[Nn * H2d];

// ------------------------- tf32 helpers ------------------------------------
__device__ __forceinline__ void tf32_split_u(float v, uint32_t& h, uint32_t& l) {
    asm("cvt.rna.tf32.f32 %0, %1;" : "=r"(h) : "f"(v));
    float r = v - __uint_as_float(h);
    asm("cvt.rna.tf32.f32 %0, %1;" : "=r"(l) : "f"(r));
}
__device__ __forceinline__ void split_store(float v, float* hp, float* lp, size_t idx) {
    uint32_t h, l; tf32_split_u(v, h, l);
    hp[idx] = __uint_as_float(h); lp[idx] = __uint_as_float(l);
}

#define MMA_TF32(c, a, b)                                                         \
    asm volatile(                                                                  \
        "mma.sync.aligned.m16n8k8.row.col.f32.tf32.tf32.f32 "                      \
        "{%0,%1,%2,%3},{%4,%5,%6,%7},{%8,%9},{%0,%1,%2,%3};"                       \
        : "+f"((c)[0]), "+f"((c)[1]), "+f"((c)[2]), "+f"((c)[3])                   \
        : "r"((a)[0]), "r"((a)[1]), "r"((a)[2]), "r"((a)[3]),                      \
          "r"((b)[0]), "r"((b)[1]))

__device__ __forceinline__ void cp16(void* sp, const void* gp) {
    uint32_t s = (uint32_t)__cvta_generic_to_shared(sp);
    asm volatile("cp.async.cg.shared.global [%0], [%1], 16;" :: "r"(s), "l"(gp));
}

// ------------------------- split_all (weights -> hi/lo) --------------------
struct SplitJob { const float* src; float* hi; float* lo; int n4; };
struct SplitJobs6 { SplitJob j[6]; };
__global__ void split_all_kernel(SplitJobs6 jobs) {
    SplitJob jb = jobs.j[blockIdx.y];
    const float4* src = (const float4*)jb.src;
    float4* hi = (float4*)jb.hi;
    float4* lo = (float4*)jb.lo;
    for (int i = blockIdx.x * blockDim.x + threadIdx.x; i < jb.n4;
         i += gridDim.x * blockDim.x) {
        float4 v = src[i];
        uint32_t h, l;
        float4 vh, vl;
        tf32_split_u(v.x, h, l); vh.x = __uint_as_float(h); vl.x = __uint_as_float(l);
        tf32_split_u(v.y, h, l); vh.y = __uint_as_float(h); vl.y = __uint_as_float(l);
        tf32_split_u(v.z, h, l); vh.z = __uint_as_float(h); vl.z = __uint_as_float(l);
        tf32_split_u(v.w, h, l); vh.w = __uint_as_float(h); vl.w = __uint_as_float(l);
        hi[i] = vh; lo[i] = vl;
    }
}

// ------------------------- merged CSR build (both graphs) ------------------
__global__ void build_csr2_kernel(const float* __restrict__ adj,
                                  const float* __restrict__ t_adj,
                                  int* __restrict__ nbr_c, float* __restrict__ val_c,
                                  int* __restrict__ cnt_c,
                                  int* __restrict__ nbr_t, float* __restrict__ val_t,
                                  int* __restrict__ cnt_t) {
    int bi = blockIdx.x;
    const float* row;
    int n, i;
    int* nbr; float* val; int* cnt;
    if (bi < Nn) {
        i = bi; n = Nn; row = adj + (size_t)i * Nn;
        nbr = nbr_c; val = val_c; cnt = cnt_c;
    } else {
        i = bi - Nn; n = Tt; row = t_adj + (size_t)i * Tt;
        nbr = nbr_t; val = val_t; cnt = cnt_t;
    }
    int t = threadIdx.x, lane = t & 31, w = t >> 5;
    int strip = n >> 3;
    int s0 = w * strip;
    __shared__ int s_cnt[8];
    int my = 0;
    for (int b = s0; b < s0 + strip; b += 32) {
        bool p = row[b + lane] > 0.0f;
        unsigned m = __ballot_sync(0xffffffffu, p);
        my += __popc(m);
    }
    if (lane == 0) s_cnt[w] = my;
    __syncthreads();
    int off = 0;
    #pragma unroll
    for (int ww = 0; ww < 8; ww++) if (ww < w) off += s_cnt[ww];
    int tot = 0;
    #pragma unroll
    for (int ww = 0; ww < 8; ww++) tot += s_cnt[ww];
    for (int b = s0; b < s0 + strip; b += 32) {
        float v = row[b + lane];
        bool p = v > 0.0f;
        unsigned m = __ballot_sync(0xffffffffu, p);
        int pos = off + __popc(m & ((1u << lane) - 1u));
        if (p && pos < CAP) { nbr[i * CAP + pos] = b + lane; val[i * CAP + pos] = v; }
        off += __popc(m);
    }
    if (t == 0) cnt[i] = min(tot, CAP);
}

// ------------------------- GEMM core ---------------------------------------
// RA: A given as RAW fp32 (single plane, split at fragment load time).
#define BMt 128
#define BNt 64
#define BKt 16

struct ZJob {
    const float *Ah, *Al, *Bh, *Bl;
    float *C, *Ch, *Cl;
    const float* bias;
    int M, N, K, lda, ldb;
};
struct ZJobs8 { ZJob z[8]; };

template <bool TA, bool TB, bool RA>
__device__ __forceinline__ void gemm_body(
    const float* __restrict__ Ah, const float* __restrict__ Al,
    const float* __restrict__ Bh, const float* __restrict__ Bl,
    const float* __restrict__ bias, float* __restrict__ C,
    float* __restrict__ Ch, float* __restrict__ Cl,
    int M, int N, int K, int lda, int ldb, int bm, int bn) {
    constexpr int PA = RA ? 1 : 2;
    constexpr int AR = TA ? BKt : BMt;
    constexpr int AC = TA ? (BMt + 8) : (BKt + 4);
    constexpr int BR = TB ? BNt : BKt;
    constexpr int BC = TB ? (BKt + 4) : (BNt + 8);
    __shared__ float As[2][PA][AR][AC];
    __shared__ float Bs[2][2][BR][BC];

    const float* Abp[PA];
    Abp[0] = Ah;
    if (!RA) Abp[PA - 1] = Al;   // PA==2 => index 1
    const float* Bbp[2] = { Bh, Bl };
    int t = threadIdx.x, lane = t & 31, w = t >> 5;
    int wm = (w & 3) * 32, wn = (w >> 2) * 32;
    int gid = lane >> 2, tig = lane & 3;

    float acc[2][4][4] = {};

    auto load_tile = [&](int s, int k0) {
        #pragma unroll
        for (int p = 0; p < PA; p++) {
            if (!TA) {
                #pragma unroll
                for (int j = 0; j < 2; j++) {
                    int idx = t + j * 256;
                    int row = idx >> 2;
                    int col = (idx & 3) * 4;
                    cp16(&As[s][p][row][col], Abp[p] + (size_t)(bm + row) * lda + k0 + col);
                }
            } else {
                #pragma unroll
                for (int j = 0; j < 2; j++) {
                    int idx = t + j * 256;
                    int row = idx >> 5;
                    int col = (idx & 31) * 4;
                    cp16(&As[s][p][row][col], Abp[p] + (size_t)(k0 + row) * lda + bm + col);
                }
            }
        }
        #pragma unroll
        for (int p = 0; p < 2; p++) {
            if (!TB) {
                int row = t >> 4;
                int col = (t & 15) * 4;
                cp16(&Bs[s][p][row][col], Bbp[p] + (size_t)(k0 + row) * ldb + bn + col);
            } else {
                int row = t >> 2;
                int col = (t & 3) * 4;
                cp16(&Bs[s][p][row][col], Bbp[p] + (size_t)(bn + row) * ldb + k0 + col);
            }
        }
    };

    auto Ae = [&](int s, int p, int k, int m) -> float {
        return TA ? As[s][p][k][m] : As[s][p][m][k];
    };
    auto Be = [&](int s, int p, int k, int nn) -> float {
        return TB ? Bs[s][p][nn][k] : Bs[s][p][k][nn];
    };

    int nk = K / BKt;
    load_tile(0, 0);
    asm volatile("cp.async.commit_group;");

    for (int kt = 0; kt < nk; kt++) {
        int s = kt & 1;
        if (kt + 1 < nk) {
            load_tile(s ^ 1, (kt + 1) * BKt);
            asm volatile("cp.async.commit_group;");
            asm volatile("cp.async.wait_group 1;");
        } else {
            asm volatile("cp.async.wait_group 0;");
        }
        __syncthreads();

        #pragma unroll
        for (int kk = 0; kk < BKt; kk += 8) {
            uint32_t ah[2][4], al[2][4], bh[4][2], bl[4][2];
            #pragma unroll
            for (int mt = 0; mt < 2; mt++) {
                int m0 = wm + mt * 16 + gid;
                if (RA) {
                    tf32_split_u(Ae(s, 0, kk + tig,     m0),     ah[mt][0], al[mt][0]);
                    tf32_split_u(Ae(s, 0, kk + tig,     m0 + 8), ah[mt][1], al[mt][1]);
                    tf32_split_u(Ae(s, 0, kk + tig + 4, m0),     ah[mt][2], al[mt][2]);
                    tf32_split_u(Ae(s, 0, kk + tig + 4, m0 + 8), ah[mt][3], al[mt][3]);
                } else {
                    ah[mt][0] = __float_as_uint(Ae(s, 0, kk + tig,     m0));
                    ah[mt][1] = __float_as_uint(Ae(s, 0, kk + tig,     m0 + 8));
                    ah[mt][2] = __float_as_uint(Ae(s, 0, kk + tig + 4, m0));
                    ah[mt][3] = __float_as_uint(Ae(s, 0, kk + tig + 4, m0 + 8));
                    al[mt][0] = __float_as_uint(Ae(s, PA - 1, kk + tig,     m0));
                    al[mt][1] = __float_as_uint(Ae(s, PA - 1, kk + tig,     m0 + 8));
                    al[mt][2] = __float_as_uint(Ae(s, PA - 1, kk + tig + 4, m0));
                    al[mt][3] = __float_as_uint(Ae(s, PA - 1, kk + tig + 4, m0 + 8));
                }
            }
            #pragma unroll
            for (int nt = 0; nt < 4; nt++) {
                int n0 = wn + nt * 8 + gid;
                bh[nt][0] = __float_as_uint(Be(s, 0, kk + tig,     n0));
                bh[nt][1] = __float_as_uint(Be(s, 0, kk + tig + 4, n0));
                bl[nt][0] = __float_as_uint(Be(s, 1, kk + tig,     n0));
                bl[nt][1] = __float_as_uint(Be(s, 1, kk + tig + 4, n0));
            }
            #pragma unroll
            for (int mt = 0; mt < 2; mt++)
                #pragma unroll
                for (int nt = 0; nt < 4; nt++) {
                    MMA_TF32(acc[mt][nt], al[mt], bh[nt]);
                    MMA_TF32(acc[mt][nt], ah[mt], bl[nt]);
                    MMA_TF32(acc[mt][nt], ah[mt], bh[nt]);
                }
        }
        __syncthreads();
    }

    #pragma unroll
    for (int mt = 0; mt < 2; mt++) {
        int row0 = bm + wm + mt * 16 + gid;
        #pragma unroll
        for (int nt = 0; nt < 4; nt++) {
            int col = bn + wn + nt * 8 + tig * 2;
            float bx = bias ? bias[col] : 0.0f;
            float by = bias ? bias[col + 1] : 0.0f;
            float v00 = acc[mt][nt][0] + bx, v01 = acc[mt][nt][1] + by;
            float v10 = acc[mt][nt][2] + bx, v11 = acc[mt][nt][3] + by;
            size_t i0 = (size_t)row0 * N + col;
            size_t i1 = (size_t)(row0 + 8) * N + col;
            if (C) {
                *reinterpret_cast<float2*>(&C[i0]) = make_float2(v00, v01);
                *reinterpret_cast<float2*>(&C[i1]) = make_float2(v10, v11);
            }
            if (Ch) {
                uint32_t h, l;
                float2 h0, l0, h1, l1;
                tf32_split_u(v00, h, l); h0.x = __uint_as_float(h); l0.x = __uint_as_float(l);
                tf32_split_u(v01, h, l); h0.y = __uint_as_float(h); l0.y = __uint_as_float(l);
                tf32_split_u(v10, h, l); h1.x = __uint_as_float(h); l1.x = __uint_as_float(l);
                tf32_split_u(v11, h, l); h1.y = __uint_as_float(h); l1.y = __uint_as_float(l);
                *reinterpret_cast<float2*>(&Ch[i0]) = h0;
                *reinterpret_cast<float2*>(&Cl[i0]) = l0;
                *reinterpret_cast<float2*>(&Ch[i1]) = h1;
                *reinterpret_cast<float2*>(&Cl[i1]) = l1;
            }
        }
    }
}

// single-job entry
template <bool TA, bool TB, bool RA>
__global__ void __launch_bounds__(256) mma_gemm_kernel(
    const float* __restrict__ Ah, const float* __restrict__ Al,
    const float* __restrict__ Bh, const float* __restrict__ Bl,
    const float* __restrict__ bias, float* __restrict__ C,
    float* __restrict__ Ch, float* __restrict__ Cl,
    int M, int N, int K, int lda, int ldb,
    size_t sA, size_t sB, size_t sC) {
    gemm_body<TA, TB, RA>(
        Ah + (size_t)blockIdx.z * sA, Al ? Al + (size_t)blockIdx.z * sA : nullptr,
        Bh + (size_t)blockIdx.z * sB, Bl + (size_t)blockIdx.z * sB,
        bias,
        C  ? C  + (size_t)blockIdx.z * sC : nullptr,
        Ch ? Ch + (size_t)blockIdx.z * sC : nullptr,
        Cl ? Cl + (size_t)blockIdx.z * sC : nullptr,
        M, N, K, lda, ldb,
        blockIdx.y * BMt, blockIdx.x * BNt);
}

// multi-job entry
template <bool RA>
__global__ void __launch_bounds__(256) mma_gemm_jobs_kernel(ZJobs8 jobs) {
    ZJob j = jobs.z[blockIdx.z];
    int bm = blockIdx.y * BMt, bn = blockIdx.x * BNt;
    if (bm >= j.M || bn >= j.N) return;
    gemm_body<false, false, RA>(j.Ah, j.Al, j.Bh, j.Bl, j.bias, j.C, j.Ch, j.Cl,
                                j.M, j.N, j.K, j.lda, j.ldb, bm, bn);
}

// ------------------------- split-K reduce: 4 partials -> split planes ------
__global__ void reduce4_split_kernel(const float* __restrict__ P,
                                     const float* __restrict__ bias,
                                     float* __restrict__ oh, float* __restrict__ ol,
                                     int MN4, int Ncols4) {
    int i = blockIdx.x * blockDim.x + threadIdx.x;
    if (i >= MN4) return;
    const float4* p = (const float4*)P;
    float4 a = p[i], b = p[i + MN4], c = p[i + 2 * MN4], d = p[i + 3 * MN4];
    float4 bv = ((const float4*)bias)[i % Ncols4];
    size_t base = (size_t)i * 4;
    split_store((a.x + b.x) + (c.x + d.x) + bv.x, oh, ol, base);
    split_store((a.y + b.y) + (c.y + d.y) + bv.y, oh, ol, base + 1);
    split_store((a.z + b.z) + (c.z + d.z) + bv.z, oh, ol, base + 2);
    split_store((a.w + b.w) + (c.w + d.w) + bv.w, oh, ol, base + 3);
}

// ------------- fused reduce (fc_c 2 partials + bias; tfidf 4 partials) -----
__global__ void fuse_reduce_kernel(const float* __restrict__ P0,
                                   const float* __restrict__ P2,
                                   const float* __restrict__ bias,
                                   float* __restrict__ oh, float* __restrict__ ol,
                                   int MN4, int Ncols4) {
    int i = blockIdx.x * blockDim.x + threadIdx.x;
    if (i >= MN4) return;
    const float4* p0 = (const float4*)P0;
    const float4* p2 = (const float4*)P2;
    float4 a = p0[i], b = p0[i + MN4];
    float4 c0 = p2[i], c1 = p2[i + MN4], c2 = p2[i + 2 * MN4], c3 = p2[i + 3 * MN4];
    float4 bv = ((const float4*)bias)[i % Ncols4];
    float con[4] = { a.x + b.x + bv.x, a.y + b.y + bv.y,
                     a.z + b.z + bv.z, a.w + b.w + bv.w };
    float ct[4] = { (c0.x + c1.x) + (c2.x + c3.x), (c0.y + c1.y) + (c2.y + c3.y),
                    (c0.z + c1.z) + (c2.z + c3.z), (c0.w + c1.w) + (c2.w + c3.w) };
    size_t base = (size_t)i * 4;
    #pragma unroll
    for (int u = 0; u < 4; u++) {
        float z = 1.0f / (1.0f + expf(-(con[u] + ct[u])));
        split_store(z * con[u] + (1.0f - z) * ct[u], oh, ol, base + u);
    }
}

// ------------------------- gc2 & gc3 fused SIMT GEMM -----------------------
__global__ void gc23_kernel(const float* __restrict__ A, const float* __restrict__ B2,
                            const float* __restrict__ B3, float* __restrict__ C2,
                            float* __restrict__ C3) {
    __shared__ __align__(16) float As[16][64];
    __shared__ __align__(16) float Bs[16][64];
    int bm = blockIdx.x * 64;
    int t = threadIdx.x, tx = t & 15, ty = t >> 4;
    float acc[4][4] = {};
    for (int k0 = 0; k0 < H1d; k0 += 16) {
        #pragma unroll
        for (int j = 0; j < 4; j++) {
            int li = t + j * 256;
            int r = li >> 4, c = li & 15;
            As[c][r] = A[(size_t)(bm + r) * H1d + k0 + c];
            int rb = li >> 6, cb = li & 63;
            Bs[rb][cb] = (cb < 32) ? B2[(k0 + rb) * H2d + cb]
                                   : B3[(k0 + rb) * H2d + cb - 32];
        }
        __syncthreads();
        #pragma unroll
        for (int k = 0; k < 16; k++) {
            float4 a4 = *reinterpret_cast<const float4*>(&As[k][ty << 2]);
            float4 b4 = *reinterpret_cast<const float4*>(&Bs[k][tx << 2]);
            float a[4] = {a4.x, a4.y, a4.z, a4.w};
            float b[4] = {b4.x, b4.y, b4.z, b4.w};
            #pragma unroll
            for (int u = 0; u < 4; u++)
                #pragma unroll
                for (int v = 0; v < 4; v++)
                    acc[u][v] += a[u] * b[v];
        }
        __syncthreads();
    }
    #pragma unroll
    for (int u = 0; u < 4; u++) {
        int row = bm + (ty << 2) + u;
        #pragma unroll
        for (int v = 0; v < 4; v++) {
            int col = (tx << 2) + v;
            if (col < 32) C2[(size_t)row * H2d + col] = acc[u][v];
            else          C3[(size_t)row * H2d + col - 32] = acc[u][v];
        }
    }
}

// ------------------------- merged f/g projections --------------------------
__global__ void fg2_kernel(const float* __restrict__ Wh_c, const float* __restrict__ asrc_c,
                           const float* __restrict__ adst_c, float* __restrict__ f_c,
                           float* __restrict__ g_c,
                           const float* __restrict__ Wh_t, const float* __restrict__ asrc_t,
                           const float* __restrict__ adst_t, float* __restrict__ f_t,
                           float* __restrict__ g_t) {
    int gw = (blockIdx.x * blockDim.x + threadIdx.x) >> 5;
    int lane = threadIdx.x & 31;
    const float* Wh; const float* asrc; const float* adst; float* f; float* g;
    int n;
    if (gw < NHd * Nn) {
        Wh = Wh_c; asrc = asrc_c; adst = adst_c; f = f_c; g = g_c; n = Nn;
    } else {
        gw -= NHd * Nn;
        if (gw >= NHd * Tt) return;
        Wh = Wh_t; asrc = asrc_t; adst = adst_t; f = f_t; g = g_t; n = Tt;
    }
    int h = gw / n, i = gw - h * n;
    const float* wp = Wh + ((size_t)h * n + i) * Dd;
    const float* as = asrc + h * Dd;
    const float* ad = adst + h * Dd;
    float accf = 0.0f, accg = 0.0f;
    #pragma unroll
    for (int c = 0; c < Dd / 32; c++) {
        float v = wp[lane + 32 * c];
        accf += v * as[lane + 32 * c];
        accg += v * ad[lane + 32 * c];
    }
    #pragma unroll
    for (int o = 16; o; o >>= 1) {
        accf += __shfl_down_sync(0xffffffffu, accf, o);
        accg += __shfl_down_sync(0xffffffffu, accg, o);
    }
    if (lane == 0) { f[gw] = accf; g[gw] = accg; }
}

// ------------------------- merged warp-per-(i,h) GAT attention -------------
__global__ void __launch_bounds__(256) gat_attn2_kernel(
    const float* __restrict__ Wh_c, const float* __restrict__ f_c,
    const float* __restrict__ g_c, const int* __restrict__ nbr_c,
    const int* __restrict__ cnt_c, float* __restrict__ hcatc_h,
    float* __restrict__ hcatc_l,
    const float* __restrict__ Wh_t, const float* __restrict__ f_t,
    const float* __restrict__ g_t, const int* __restrict__ nbr_t,
    const int* __restrict__ cnt_t, float* __restrict__ hcatt_h,
    float* __restrict__ hcatt_l) {
    int w = threadIdx.x >> 5, lane = threadIdx.x & 31;
    int gw = blockIdx.x * 8 + w;
    const float* Wh; const float* f; const float* g;
    const int* nbr; const int* cnt; float* hcat_h; float* hcat_l;
    int n;
    if (gw < Nn * NHd) {
        Wh = Wh_c; f = f_c; g = g_c; nbr = nbr_c; cnt = cnt_c;
        hcat_h = hcatc_h; hcat_l = hcatc_l; n = Nn;
    } else {
        gw -= Nn * NHd;
        Wh = Wh_t; f = f_t; g = g_t; nbr = nbr_t; cnt = cnt_t;
        hcat_h = hcatt_h; hcat_l = hcatt_l; n = Tt;
    }
    int i = gw >> 2, h = gw & 3;
    __shared__ int   sj[8][CAP];
    __shared__ float sw[8][CAP];
    int c = cnt[i];
    const int* jb = nbr + i * CAP;
    float fi = f[h * n + i];
    float m = -1e30f;
    for (int k = lane; k < c; k += 32) {
        int j = jb[k];
        sj[w][k] = j;
        float s = fi + g[h * n + j];
        s = (s >= 0.0f) ? s : LRELU_ALPHA * s;
        sw[w][k] = s;
        m = fmaxf(m, s);
    }
    #pragma unroll
    for (int o = 16; o; o >>= 1) m = fmaxf(m, __shfl_xor_sync(0xffffffffu, m, o));
    __syncwarp();
    float sum = 0.0f;
    for (int k = lane; k < c; k += 32) {
        float e = expf(sw[w][k] - m);
        sw[w][k] = e;
        sum += e;
    }
    #pragma unroll
    for (int o = 16; o; o >>= 1) sum += __shfl_xor_sync(0xffffffffu, sum, o);
    float dinv = 1.0f / sum;
    __syncwarp();
    const float* base = Wh + (size_t)h * n * Dd;
    float acc[8] = {};
    int k = 0;
    for (; k + 2 <= c; k += 2) {
        float w0 = sw[w][k], w1 = sw[w][k + 1];
        const float* r0 = base + (size_t)sj[w][k] * Dd + lane;
        const float* r1 = base + (size_t)sj[w][k + 1] * Dd + lane;
        #pragma unroll
        for (int ch = 0; ch < 8; ch++) {
            acc[ch] += w0 * __ldg(r0 + ch * 32);
            acc[ch] += w1 * __ldg(r1 + ch * 32);
        }
    }
    if (k < c) {
        float w0 = sw[w][k];
        const float* r0 = base + (size_t)sj[w][k] * Dd + lane;
        #pragma unroll
        for (int ch = 0; ch < 8; ch++) acc[ch] += w0 * __ldg(r0 + ch * 32);
    }
    size_t obase = (size_t)i * (NHd * Dd) + h * Dd + lane;
    #pragma unroll
    for (int ch = 0; ch < 8; ch++) {
        float v = acc[ch] * dinv;
        v = (v > 0.0f) ? v : expm1f(v);
        split_store(v, hcat_h, hcat_l, obase + ch * 32);
    }
}

// ------------------------- sparse adj @ X, optional ReLU -------------------
__global__ void spmm_kernel(const int* __restrict__ nbr, const float* __restrict__ val,
                            const int* __restrict__ cnt, const float* __restrict__ X,
                            float* __restrict__ Y, int ncols, int do_relu) {
    int i = blockIdx.x;
    int t = threadIdx.x;
    int c = cnt[i];
    const int* jb = nbr + i * CAP;
    const float* vb = val + i * CAP;
    float a0 = 0.0f, a1 = 0.0f, a2 = 0.0f, a3 = 0.0f;
    int k = 0;
    for (; k + 4 <= c; k += 4) {
        a0 += vb[k]     * __ldg(X + (size_t)jb[k]     * ncols + t);
        a1 += vb[k + 1] * __ldg(X + (size_t)jb[k + 1] * ncols + t);
        a2 += vb[k + 2] * __ldg(X + (size_t)jb[k + 2] * ncols + t);
        a3 += vb[k + 3] * __ldg(X + (size_t)jb[k + 3] * ncols + t);
    }
    for (; k < c; k++)
        a0 += vb[k] * __ldg(X + (size_t)jb[k] * ncols + t);
    float acc = (a0 + a1) + (a2 + a3);
    if (do_relu) acc = fmaxf(acc, 0.0f);
    Y[(size_t)i * ncols + t] = acc;
}

// ------------------------- fused mu/logvar spmm ----------------------------
__global__ void spmm2_kernel(const int* __restrict__ nbr, const float* __restrict__ val,
                             const int* __restrict__ cnt, const float* __restrict__ X2,
                             const float* __restrict__ X3, float* __restrict__ mu,
                             float* __restrict__ logvar, float* __restrict__ mu_h,
                             float* __restrict__ mu_l) {
    int i = blockIdx.x;
    int t = threadIdx.x;
    int sel = t >> 5, col = t & 31;
    const float* X = sel ? X3 : X2;
    int c = cnt[i];
    const int* jb = nbr + i * CAP;
    const float* vb = val + i * CAP;
    float a0 = 0.0f, a1 = 0.0f, a2 = 0.0f, a3 = 0.0f;
    int k = 0;
    for (; k + 4 <= c; k += 4) {
        a0 += vb[k]     * __ldg(X + (size_t)jb[k]     * H2d + col);
        a1 += vb[k + 1] * __ldg(X + (size_t)jb[k + 1] * H2d + col);
        a2 += vb[k + 2] * __ldg(X + (size_t)jb[k + 2] * H2d + col);
        a3 += vb[k + 3] * __ldg(X + (size_t)jb[k + 3] * H2d + col);
    }
    for (; k < c; k++)
        a0 += vb[k] * __ldg(X + (size_t)jb[k] * H2d + col);
    float v = (a0 + a1) + (a2 + a3);
    size_t idx = (size_t)i * H2d + col;
    if (sel == 0) {
        mu[idx] = v;
        split_store(v, mu_h, mu_l, idx);
    } else {
        logvar[idx] = v;
    }
}

#define SYM(p, s) cudaGetSymbolAddress((void**)&p, s)

extern "C" void kernel_launch(void* const* d_in, const int* in_sizes, int n_in,
                              void* d_out, int out_size) {
    const float* x        = (const float*)d_in[0];
    const float* adj      = (const float*)d_in[1];
    const float* t_x      = (const float*)d_in[2];
    const float* t_adj    = (const float*)d_in[3];
    const float* tfidf    = (const float*)d_in[4];
    const float* gat_W    = (const float*)d_in[5];
    const float* gat_asrc = (const float*)d_in[6];
    const float* gat_adst = (const float*)d_in[7];
    const float* gat_fcW  = (const float*)d_in[8];
    const float* gat_fcb  = (const float*)d_in[9];
    const float* t_W      = (const float*)d_in[10];
    const float* t_asrc   = (const float*)d_in[11];
    const float* t_adst   = (const float*)d_in[12];
    const float* t_fcW    = (const float*)d_in[13];
    const float* t_fcb    = (const float*)d_in[14];
    const float* fus_W    = (const float*)d_in[15];
    const float* fus_b    = (const float*)d_in[16];
    const float* gc1_W    = (const float*)d_in[17];
    const float* gc2_W    = (const float*)d_in[18];
    const float* gc3_W    = (const float*)d_in[19];

    float* out    = (float*)d_out;
    float* mu     = out + (size_t)Nn * Nn;
    float* logvar = mu + (size_t)Nn * H2d;

    float *Wh_c, *Wh_t, *f_c, *g_c, *f_t, *g_t, *val_c, *val_t;
    float *tmp1, *h1, *tmp2a, *tmp2b, *P0, *P1, *P2;
    int *nbr_c, *cnt_c, *nbr_t, *cnt_t;
    float *gatW_h, *gatW_l, *tW_h, *tW_l, *fcWc_h, *fcWc_l, *fcWt_h, *fcWt_l;
    float *fusW_h, *fusW_l, *gc1W_h, *gc1W_l;
    float *hcatc_h, *hcatc_l, *hcatt_h, *hcatt_l, *gtext_h, *gtext_l;
    float *fused_h, *fused_l, *fusion_h, *fusion_l, *mu_h, *mu_l;
    SYM(Wh_c, g_Wh_c);  SYM(Wh_t, g_Wh_t);
    SYM(f_c, g_f_c);    SYM(g_c, g_g_c);   SYM(f_t, g_f_t);  SYM(g_t, g_g_t);
    SYM(nbr_c, g_nbr_c); SYM(val_c, g_val_c); SYM(cnt_c, g_cnt_c);
    SYM(nbr_t, g_nbr_t); SYM(val_t, g_val_t); SYM(cnt_t, g_cnt_t);
    SYM(tmp1, g_tmp1); SYM(h1, g_h1); SYM(tmp2a, g_tmp2a); SYM(tmp2b, g_tmp2b);
    SYM(P0, g_P0); SYM(P1, g_P1); SYM(P2, g_P2);
    SYM(gatW_h, g_gatW_h); SYM(gatW_l, g_gatW_l);
    SYM(tW_h, g_tW_h);     SYM(tW_l, g_tW_l);
    SYM(fcWc_h, g_fcWc_h); SYM(fcWc_l, g_fcWc_l);
    SYM(fcWt_h, g_fcWt_h); SYM(fcWt_l, g_fcWt_l);
    SYM(fusW_h, g_fusW_h); SYM(fusW_l, g_fusW_l);
    SYM(gc1W_h, g_gc1W_h); SYM(gc1W_l, g_gc1W_l);
    SYM(hcatc_h, g_hcatc_h); SYM(hcatc_l, g_hcatc_l);
    SYM(hcatt_h, g_hcatt_h); SYM(hcatt_l, g_hcatt_l);
    SYM(gtext_h, g_gtext_h); SYM(gtext_l, g_gtext_l);
    SYM(fused_h, g_fused_h); SYM(fused_l, g_fused_l);
    SYM(fusion_h, g_fusion_h); SYM(fusion_l, g_fusion_l);
    SYM(mu_h, g_mu_h); SYM(mu_l, g_mu_l);

    // 0) split WEIGHTS ONLY into tf32 hi/lo planes (x, t_x, tfidf stay raw)
    {
        SplitJobs6 jobs;
        jobs.j[0] = { gat_W,   gatW_h, gatW_l, NHd * Dd * Dd / 4 };
        jobs.j[1] = { t_W,     tW_h,   tW_l,   NHd * Dd * Dd / 4 };
        jobs.j[2] = { gat_fcW, fcWc_h, fcWc_l, NHd * Dd * Dd / 4 };
        jobs.j[3] = { t_fcW,   fcWt_h, fcWt_l, NHd * Dd * Dd / 4 };
        jobs.j[4] = { fus_W,   fusW_h, fusW_l, Dd * Dd / 4 };
        jobs.j[5] = { gc1_W,   gc1W_h, gc1W_l, Dd * H1d / 4 };
        split_all_kernel<<<dim3(128, 6), 256>>>(jobs);
    }

    // 1) both adjacencies -> CSR (one launch)
    build_csr2_kernel<<<Nn + Tt, 256>>>(adj, t_adj, nbr_c, val_c, cnt_c,
                                        nbr_t, val_t, cnt_t);

    // 2) per-head Wh for BOTH graphs, ONE launch, RAW A (x / t_x)
    {
        ZJobs8 jb;
        for (int h = 0; h < NHd; h++) {
            jb.z[h] = { x, nullptr,
                        gatW_h + (size_t)h * Dd * Dd, gatW_l + (size_t)h * Dd * Dd,
                        Wh_c + (size_t)h * Nn * Dd, nullptr, nullptr, nullptr,
                        Nn, Dd, Dd, Dd, Dd };
            jb.z[NHd + h] = { t_x, nullptr,
                        tW_h + (size_t)h * Dd * Dd, tW_l + (size_t)h * Dd * Dd,
                        Wh_t + (size_t)h * Tt * Dd, nullptr, nullptr, nullptr,
                        Tt, Dd, Dd, Dd, Dd };
        }
        mma_gemm_jobs_kernel<true><<<dim3(Dd / BNt, Nn / BMt, 8), 256>>>(jb);
    }

    // 3) attention projections f,g (both graphs)
    {
        int warps = NHd * (Nn + Tt);
        fg2_kernel<<<(warps * 32 + 255) / 256, 256>>>(
            Wh_c, gat_asrc, gat_adst, f_c, g_c,
            Wh_t, t_asrc, t_adst, f_t, g_t);
    }

    // 4) sparse attention + aggregation + ELU (both graphs)
    gat_attn2_kernel<<<(Nn + Tt) * NHd / 8, 256>>>(
        Wh_c, f_c, g_c, nbr_c, cnt_c, hcatc_h, hcatc_l,
        Wh_t, f_t, g_t, nbr_t, cnt_t, hcatt_h, hcatt_l);

    // 5) both fc GEMMs, split-K, ONE launch (6 z-jobs, pre-split A)
    {
        ZJobs8 jb;
        for (int c = 0; c < 2; c++)
            jb.z[c] = { hcatc_h + (size_t)c * 512, hcatc_l + (size_t)c * 512,
                        fcWc_h + (size_t)c * 512 * Dd, fcWc_l + (size_t)c * 512 * Dd,
                        P0 + (size_t)c * Nn * Dd, nullptr, nullptr, nullptr,
                        Nn, Dd, 512, NHd * Dd, Dd };
        for (int c = 0; c < 4; c++)
            jb.z[2 + c] = { hcatt_h + (size_t)c * 256, hcatt_l + (size_t)c * 256,
                        fcWt_h + (size_t)c * 256 * Dd, fcWt_l + (size_t)c * 256 * Dd,
                        P1 + (size_t)c * Tt * Dd, nullptr, nullptr, nullptr,
                        Tt, Dd, 256, NHd * Dd, Dd };
        for (int c = 6; c < 8; c++) jb.z[c] = jb.z[0];  // unused
        mma_gemm_jobs_kernel<false><<<dim3(Dd / BNt, Nn / BMt, 6), 256>>>(jb);
    }

    // 5b) reduce fc_t partials -> gtext hi/lo (+bias)
    reduce4_split_kernel<<<(Tt * Dd / 4 + 255) / 256, 256>>>(
        P1, t_fcb, gtext_h, gtext_l, Tt * Dd / 4, Dd / 4);

    // 6) c_text = tfidf^T @ gat_text — split-K 4 x 512, RAW A (tfidf)
    {
        dim3 grid(Dd / BNt, Nn / BMt, 4);
        mma_gemm_kernel<true, false, true><<<grid, 256>>>(
            tfidf, nullptr, gtext_h, gtext_l, nullptr, P2, nullptr, nullptr,
            Nn, Dd, 512, Nn, Dd,
            (size_t)512 * Nn, (size_t)512 * Dd, (size_t)Nn * Dd);
    }

    // 7) fused reduce: concept(P0)+bias, ctext(P2), sigmoid gate -> fused hi/lo
    fuse_reduce_kernel<<<(Nn * Dd / 4 + 255) / 256, 256>>>(
        P0, P2, gat_fcb, fused_h, fused_l, Nn * Dd / 4, Dd / 4);

    // 7b) fusion = fused @ fus_W + fus_b  (split epilogue)
    {
        dim3 grid(Dd / BNt, Nn / BMt, 1);
        mma_gemm_kernel<false, false, false><<<grid, 256>>>(
            fused_h, fused_l, fusW_h, fusW_l, fus_b, nullptr, fusion_h, fusion_l,
            Nn, Dd, Dd, Dd, Dd, 0, 0, 0);
    }

    // 8) GCN encoder
    {
        dim3 grid(H1d / BNt, Nn / BMt, 1);
        mma_gemm_kernel<false, false, false><<<grid, 256>>>(
            fusion_h, fusion_l, gc1W_h, gc1W_l, nullptr, tmp1, nullptr, nullptr,
            Nn, H1d, Dd, Dd, H1d, 0, 0, 0);
    }
    spmm_kernel<<<Nn, H1d>>>(nbr_c, val_c, cnt_c, tmp1, h1, H1d, 1);

    gc23_kernel<<<Nn / 64, 256>>>(h1, gc2_W, gc3_W, tmp2a, tmp2b);
    spmm2_kernel<<<Nn, 64>>>(nbr_c, val_c, cnt_c, tmp2a, tmp2b, mu, logvar, mu_h, mu_l);

    // 9) recon = mu @ mu^T
    {
        dim3 grid(Nn / BNt, Nn / BMt, 1);
        mma_gemm_kernel<false, true, false><<<grid, 256>>>(
            mu_h, mu_l, mu_h, mu_l, nullptr, out, nullptr, nullptr,
            Nn, Nn, H2d, H2d, H2d, 0, 0, 0);
    }
}

// round 15
// speedup vs baseline: 1.3709x; 1.0287x over previous
#include <cuda_runtime.h>
#include <math.h>
#include <stdint.h>

#define Nn   4096
#define Tt   2048
#define Dd   256
#define H1d  128
#define H2d  32
#define NHd  4
#define CAP  96
#define LRELU_ALPHA 0.2f

// ------------------------- scratch (__device__ globals) --------------------
__device__ float g_Wh_c[NHd * Nn * Dd];
__device__ float g_Wh_t[NHd * Tt * Dd];
__device__ float g_f_c[NHd * Nn], g_g_c[NHd * Nn];
__device__ float g_f_t[NHd * Tt], g_g_t[NHd * Tt];
__device__ int   g_nbr_c[Nn * CAP];
__device__ float g_val_c[Nn * CAP];
__device__ int   g_cnt_c[Nn];
__device__ int   g_nbr_t[Tt * CAP];
__device__ float g_val_t[Tt * CAP];
__device__ int   g_cnt_t[Tt];
__device__ float g_tmp1[Nn * H1d];
__device__ float g_h1[Nn * H1d];
__device__ float g_tmp2a[Nn * H2d];
__device__ float g_tmp2b[Nn * H2d];
// split-K partial buffers
__device__ float g_P0[2 * Nn * Dd];
__device__ float g_P1[4 * Tt * Dd];
__device__ float g_P2[4 * Nn * Dd];
// raw intermediates (consumers split in-register)
__device__ float g_hcatc[Nn * NHd * Dd];
__device__ float g_hcatt[Tt * NHd * Dd];
__device__ float g_fused[Nn * Dd];
__device__ float g_fusion[Nn * Dd];
// hi/lo planes (weights + gtext + mu)
__device__ float g_gatW_h[NHd * Dd * Dd], g_gatW_l[NHd * Dd * Dd];
__device__ float g_tW_h[NHd * Dd * Dd],   g_tW_l[NHd * Dd * Dd];
__device__ float g_fcWc_h[NHd * Dd * Dd], g_fcWc_l[NHd * Dd * Dd];
__device__ float g_fcWt_h[NHd * Dd * Dd], g_fcWt_l[NHd * Dd * Dd];
__device__ float g_fusW_h[Dd * Dd],     g_fusW_l[Dd * Dd];
__device__ float g_gc1W_h[Dd * H1d],    g_gc1W_l[Dd * H1d];
__device__ float g_gtext_h[Tt * Dd],    g_gtext_l[Tt * Dd];
__device__ float g_mu_h[Nn * H2d],      g_mu_l[Nn * H2d];

// ------------------------- tf32 helpers ------------------------------------
__device__ __forceinline__ void tf32_split_u(float v, uint32_t& h, uint32_t& l) {
    asm("cvt.rna.tf32.f32 %0, %1;" : "=r"(h) : "f"(v));
    float r = v - __uint_as_float(h);
    asm("cvt.rna.tf32.f32 %0, %1;" : "=r"(l) : "f"(r));
}
__device__ __forceinline__ void split_store(float v, float* hp, float* lp, size_t idx) {
    uint32_t h, l; tf32_split_u(v, h, l);
    hp[idx] = __uint_as_float(h); lp[idx] = __uint_as_float(l);
}

#define MMA_TF32(c, a, b)                                                         \
    asm volatile(                                                                  \
        "mma.sync.aligned.m16n8k8.row.col.f32.tf32.tf32.f32 "                      \
        "{%0,%1,%2,%3},{%4,%5,%6,%7},{%8,%9},{%0,%1,%2,%3};"                       \
        : "+f"((c)[0]), "+f"((c)[1]), "+f"((c)[2]), "+f"((c)[3])                   \
        : "r"((a)[0]), "r"((a)[1]), "r"((a)[2]), "r"((a)[3]),                      \
          "r"((b)[0]), "r"((b)[1]))

__device__ __forceinline__ void cp16(void* sp, const void* gp) {
    uint32_t s = (uint32_t)__cvta_generic_to_shared(sp);
    asm volatile("cp.async.cg.shared.global [%0], [%1], 16;" :: "r"(s), "l"(gp));
}

// ------------------------- split_all (weights -> hi/lo) --------------------
struct SplitJob { const float* src; float* hi; float* lo; int n4; };
struct SplitJobs6 { SplitJob j[6]; };
__global__ void split_all_kernel(SplitJobs6 jobs) {
    SplitJob jb = jobs.j[blockIdx.y];
    const float4* src = (const float4*)jb.src;
    float4* hi = (float4*)jb.hi;
    float4* lo = (float4*)jb.lo;
    for (int i = blockIdx.x * blockDim.x + threadIdx.x; i < jb.n4;
         i += gridDim.x * blockDim.x) {
        float4 v = src[i];
        uint32_t h, l;
        float4 vh, vl;
        tf32_split_u(v.x, h, l); vh.x = __uint_as_float(h); vl.x = __uint_as_float(l);
        tf32_split_u(v.y, h, l); vh.y = __uint_as_float(h); vl.y = __uint_as_float(l);
        tf32_split_u(v.z, h, l); vh.z = __uint_as_float(h); vl.z = __uint_as_float(l);
        tf32_split_u(v.w, h, l); vh.w = __uint_as_float(h); vl.w = __uint_as_float(l);
        hi[i] = vh; lo[i] = vl;
    }
}

// ------------------------- merged CSR build (both graphs) ------------------
__global__ void build_csr2_kernel(const float* __restrict__ adj,
                                  const float* __restrict__ t_adj,
                                  int* __restrict__ nbr_c, float* __restrict__ val_c,
                                  int* __restrict__ cnt_c,
                                  int* __restrict__ nbr_t, float* __restrict__ val_t,
                                  int* __restrict__ cnt_t) {
    int bi = blockIdx.x;
    const float* row;
    int n, i;
    int* nbr; float* val; int* cnt;
    if (bi < Nn) {
        i = bi; n = Nn; row = adj + (size_t)i * Nn;
        nbr = nbr_c; val = val_c; cnt = cnt_c;
    } else {
        i = bi - Nn; n = Tt; row = t_adj + (size_t)i * Tt;
        nbr = nbr_t; val = val_t; cnt = cnt_t;
    }
    int t = threadIdx.x, lane = t & 31, w = t >> 5;
    int strip = n >> 3;
    int s0 = w * strip;
    __shared__ int s_cnt[8];
    int my = 0;
    for (int b = s0; b < s0 + strip; b += 32) {
        bool p = row[b + lane] > 0.0f;
        unsigned m = __ballot_sync(0xffffffffu, p);
        my += __popc(m);
    }
    if (lane == 0) s_cnt[w] = my;
    __syncthreads();
    int off = 0;
    #pragma unroll
    for (int ww = 0; ww < 8; ww++) if (ww < w) off += s_cnt[ww];
    int tot = 0;
    #pragma unroll
    for (int ww = 0; ww < 8; ww++) tot += s_cnt[ww];
    for (int b = s0; b < s0 + strip; b += 32) {
        float v = row[b + lane];
        bool p = v > 0.0f;
        unsigned m = __ballot_sync(0xffffffffu, p);
        int pos = off + __popc(m & ((1u << lane) - 1u));
        if (p && pos < CAP) { nbr[i * CAP + pos] = b + lane; val[i * CAP + pos] = v; }
        off += __popc(m);
    }
    if (t == 0) cnt[i] = min(tot, CAP);
}

// ------------------------- GEMM core ---------------------------------------
// RA: A given as RAW fp32 (single plane, split at fragment load time).
#define BMt 128
#define BNt 64
#define BKt 16

struct ZJob {
    const float *Ah, *Al, *Bh, *Bl;
    float *C, *Ch, *Cl;
    const float* bias;
    int M, N, K, lda, ldb;
};
struct ZJobs8 { ZJob z[8]; };

template <bool TA, bool TB, bool RA>
__device__ __forceinline__ void gemm_body(
    const float* __restrict__ Ah, const float* __restrict__ Al,
    const float* __restrict__ Bh, const float* __restrict__ Bl,
    const float* __restrict__ bias, float* __restrict__ C,
    float* __restrict__ Ch, float* __restrict__ Cl,
    int M, int N, int K, int lda, int ldb, int bm, int bn) {
    constexpr int PA = RA ? 1 : 2;
    constexpr int AR = TA ? BKt : BMt;
    constexpr int AC = TA ? (BMt + 8) : (BKt + 4);
    constexpr int BR = TB ? BNt : BKt;
    constexpr int BC = TB ? (BKt + 4) : (BNt + 8);
    __shared__ float As[2][PA][AR][AC];
    __shared__ float Bs[2][2][BR][BC];

    const float* Abp[PA];
    Abp[0] = Ah;
    if (!RA) Abp[PA - 1] = Al;
    const float* Bbp[2] = { Bh, Bl };
    int t = threadIdx.x, lane = t & 31, w = t >> 5;
    int wm = (w & 3) * 32, wn = (w >> 2) * 32;
    int gid = lane >> 2, tig = lane & 3;

    float acc[2][4][4] = {};

    auto load_tile = [&](int s, int k0) {
        #pragma unroll
        for (int p = 0; p < PA; p++) {
            if (!TA) {
                #pragma unroll
                for (int j = 0; j < 2; j++) {
                    int idx = t + j * 256;
                    int row = idx >> 2;
                    int col = (idx & 3) * 4;
                    cp16(&As[s][p][row][col], Abp[p] + (size_t)(bm + row) * lda + k0 + col);
                }
            } else {
                #pragma unroll
                for (int j = 0; j < 2; j++) {
                    int idx = t + j * 256;
                    int row = idx >> 5;
                    int col = (idx & 31) * 4;
                    cp16(&As[s][p][row][col], Abp[p] + (size_t)(k0 + row) * lda + bm + col);
                }
            }
        }
        #pragma unroll
        for (int p = 0; p < 2; p++) {
            if (!TB) {
                int row = t >> 4;
                int col = (t & 15) * 4;
                cp16(&Bs[s][p][row][col], Bbp[p] + (size_t)(k0 + row) * ldb + bn + col);
            } else {
                int row = t >> 2;
                int col = (t & 3) * 4;
                cp16(&Bs[s][p][row][col], Bbp[p] + (size_t)(bn + row) * ldb + k0 + col);
            }
        }
    };

    auto Ae = [&](int s, int p, int k, int m) -> float {
        return TA ? As[s][p][k][m] : As[s][p][m][k];
    };
    auto Be = [&](int s, int p, int k, int nn) -> float {
        return TB ? Bs[s][p][nn][k] : Bs[s][p][k][nn];
    };

    int nk = K / BKt;
    load_tile(0, 0);
    asm volatile("cp.async.commit_group;");

    for (int kt = 0; kt < nk; kt++) {
        int s = kt & 1;
        if (kt + 1 < nk) {
            load_tile(s ^ 1, (kt + 1) * BKt);
            asm volatile("cp.async.commit_group;");
            asm volatile("cp.async.wait_group 1;");
        } else {
            asm volatile("cp.async.wait_group 0;");
        }
        __syncthreads();

        #pragma unroll
        for (int kk = 0; kk < BKt; kk += 8) {
            uint32_t ah[2][4], al[2][4], bh[4][2], bl[4][2];
            #pragma unroll
            for (int mt = 0; mt < 2; mt++) {
                int m0 = wm + mt * 16 + gid;
                if (RA) {
                    tf32_split_u(Ae(s, 0, kk + tig,     m0),     ah[mt][0], al[mt][0]);
                    tf32_split_u(Ae(s, 0, kk + tig,     m0 + 8), ah[mt][1], al[mt][1]);
                    tf32_split_u(Ae(s, 0, kk + tig + 4, m0),     ah[mt][2], al[mt][2]);
                    tf32_split_u(Ae(s, 0, kk + tig + 4, m0 + 8), ah[mt][3], al[mt][3]);
                } else {
                    ah[mt][0] = __float_as_uint(Ae(s, 0, kk + tig,     m0));
                    ah[mt][1] = __float_as_uint(Ae(s, 0, kk + tig,     m0 + 8));
                    ah[mt][2] = __float_as_uint(Ae(s, 0, kk + tig + 4, m0));
                    ah[mt][3] = __float_as_uint(Ae(s, 0, kk + tig + 4, m0 + 8));
                    al[mt][0] = __float_as_uint(Ae(s, PA - 1, kk + tig,     m0));
                    al[mt][1] = __float_as_uint(Ae(s, PA - 1, kk + tig,     m0 + 8));
                    al[mt][2] = __float_as_uint(Ae(s, PA - 1, kk + tig + 4, m0));
                    al[mt][3] = __float_as_uint(Ae(s, PA - 1, kk + tig + 4, m0 + 8));
                }
            }
            #pragma unroll
            for (int nt = 0; nt < 4; nt++) {
                int n0 = wn + nt * 8 + gid;
                bh[nt][0] = __float_as_uint(Be(s, 0, kk + tig,     n0));
                bh[nt][1] = __float_as_uint(Be(s, 0, kk + tig + 4, n0));
                bl[nt][0] = __float_as_uint(Be(s, 1, kk + tig,     n0));
                bl[nt][1] = __float_as_uint(Be(s, 1, kk + tig + 4, n0));
            }
            #pragma unroll
            for (int mt = 0; mt < 2; mt++)
                #pragma unroll
                for (int nt = 0; nt < 4; nt++) {
                    MMA_TF32(acc[mt][nt], al[mt], bh[nt]);
                    MMA_TF32(acc[mt][nt], ah[mt], bl[nt]);
                    MMA_TF32(acc[mt][nt], ah[mt], bh[nt]);
                }
        }
        __syncthreads();
    }

    #pragma unroll
    for (int mt = 0; mt < 2; mt++) {
        int row0 = bm + wm + mt * 16 + gid;
        #pragma unroll
        for (int nt = 0; nt < 4; nt++) {
            int col = bn + wn + nt * 8 + tig * 2;
            float bx = bias ? bias[col] : 0.0f;
            float by = bias ? bias[col + 1] : 0.0f;
            float v00 = acc[mt][nt][0] + bx, v01 = acc[mt][nt][1] + by;
            float v10 = acc[mt][nt][2] + bx, v11 = acc[mt][nt][3] + by;
            size_t i0 = (size_t)row0 * N + col;
            size_t i1 = (size_t)(row0 + 8) * N + col;
            if (C) {
                *reinterpret_cast<float2*>(&C[i0]) = make_float2(v00, v01);
                *reinterpret_cast<float2*>(&C[i1]) = make_float2(v10, v11);
            }
            if (Ch) {
                uint32_t h, l;
                float2 h0, l0, h1, l1;
                tf32_split_u(v00, h, l); h0.x = __uint_as_float(h); l0.x = __uint_as_float(l);
                tf32_split_u(v01, h, l); h0.y = __uint_as_float(h); l0.y = __uint_as_float(l);
                tf32_split_u(v10, h, l); h1.x = __uint_as_float(h); l1.x = __uint_as_float(l);
                tf32_split_u(v11, h, l); h1.y = __uint_as_float(h); l1.y = __uint_as_float(l);
                *reinterpret_cast<float2*>(&Ch[i0]) = h0;
                *reinterpret_cast<float2*>(&Cl[i0]) = l0;
                *reinterpret_cast<float2*>(&Ch[i1]) = h1;
                *reinterpret_cast<float2*>(&Cl[i1]) = l1;
            }
        }
    }
}

// single-job entry
template <bool TA, bool TB, bool RA>
__global__ void __launch_bounds__(256) mma_gemm_kernel(
    const float* __restrict__ Ah, const float* __restrict__ Al,
    const float* __restrict__ Bh, const float* __restrict__ Bl,
    const float* __restrict__ bias, float* __restrict__ C,
    float* __restrict__ Ch, float* __restrict__ Cl,
    int M, int N, int K, int lda, int ldb,
    size_t sA, size_t sB, size_t sC) {
    gemm_body<TA, TB, RA>(
        Ah + (size_t)blockIdx.z * sA, Al ? Al + (size_t)blockIdx.z * sA : nullptr,
        Bh + (size_t)blockIdx.z * sB, Bl + (size_t)blockIdx.z * sB,
        bias,
        C  ? C  + (size_t)blockIdx.z * sC : nullptr,
        Ch ? Ch + (size_t)blockIdx.z * sC : nullptr,
        Cl ? Cl + (size_t)blockIdx.z * sC : nullptr,
        M, N, K, lda, ldb,
        blockIdx.y * BMt, blockIdx.x * BNt);
}

// multi-job entry
template <bool RA>
__global__ void __launch_bounds__(256) mma_gemm_jobs_kernel(ZJobs8 jobs) {
    ZJob j = jobs.z[blockIdx.z];
    int bm = blockIdx.y * BMt, bn = blockIdx.x * BNt;
    if (bm >= j.M || bn >= j.N) return;
    gemm_body<false, false, RA>(j.Ah, j.Al, j.Bh, j.Bl, j.bias, j.C, j.Ch, j.Cl,
                                j.M, j.N, j.K, j.lda, j.ldb, bm, bn);
}

// ------------------------- split-K reduce: 4 partials -> split planes ------
__global__ void reduce4_split_kernel(const float* __restrict__ P,
                                     const float* __restrict__ bias,
                                     float* __restrict__ oh, float* __restrict__ ol,
                                     int MN4, int Ncols4) {
    int i = blockIdx.x * blockDim.x + threadIdx.x;
    if (i >= MN4) return;
    const float4* p = (const float4*)P;
    float4 a = p[i], b = p[i + MN4], c = p[i + 2 * MN4], d = p[i + 3 * MN4];
    float4 bv = ((const float4*)bias)[i % Ncols4];
    size_t base = (size_t)i * 4;
    split_store((a.x + b.x) + (c.x + d.x) + bv.x, oh, ol, base);
    split_store((a.y + b.y) + (c.y + d.y) + bv.y, oh, ol, base + 1);
    split_store((a.z + b.z) + (c.z + d.z) + bv.z, oh, ol, base + 2);
    split_store((a.w + b.w) + (c.w + d.w) + bv.w, oh, ol, base + 3);
}

// ------------- fused reduce -> RAW fused output ----------------------------
__global__ void fuse_reduce_kernel(const float* __restrict__ P0,
                                   const float* __restrict__ P2,
                                   const float* __restrict__ bias,
                                   float* __restrict__ o,
                                   int MN4, int Ncols4) {
    int i = blockIdx.x * blockDim.x + threadIdx.x;
    if (i >= MN4) return;
    const float4* p0 = (const float4*)P0;
    const float4* p2 = (const float4*)P2;
    float4 a = p0[i], b = p0[i + MN4];
    float4 c0 = p2[i], c1 = p2[i + MN4], c2 = p2[i + 2 * MN4], c3 = p2[i + 3 * MN4];
    float4 bv = ((const float4*)bias)[i % Ncols4];
    float con[4] = { a.x + b.x + bv.x, a.y + b.y + bv.y,
                     a.z + b.z + bv.z, a.w + b.w + bv.w };
    float ct[4] = { (c0.x + c1.x) + (c2.x + c3.x), (c0.y + c1.y) + (c2.y + c3.y),
                    (c0.z + c1.z) + (c2.z + c3.z), (c0.w + c1.w) + (c2.w + c3.w) };
    float4 r;
    float* rp = (float*)&r;
    #pragma unroll
    for (int u = 0; u < 4; u++) {
        float z = 1.0f / (1.0f + expf(-(con[u] + ct[u])));
        rp[u] = z * con[u] + (1.0f - z) * ct[u];
    }
    ((float4*)o)[i] = r;
}

// ------------------------- gc2 & gc3 fused SIMT GEMM -----------------------
__global__ void gc23_kernel(const float* __restrict__ A, const float* __restrict__ B2,
                            const float* __restrict__ B3, float* __restrict__ C2,
                            float* __restrict__ C3) {
    __shared__ __align__(16) float As[16][64];
    __shared__ __align__(16) float Bs[16][64];
    int bm = blockIdx.x * 64;
    int t = threadIdx.x, tx = t & 15, ty = t >> 4;
    float acc[4][4] = {};
    for (int k0 = 0; k0 < H1d; k0 += 16) {
        #pragma unroll
        for (int j = 0; j < 4; j++) {
            int li = t + j * 256;
            int r = li >> 4, c = li & 15;
            As[c][r] = A[(size_t)(bm + r) * H1d + k0 + c];
            int rb = li >> 6, cb = li & 63;
            Bs[rb][cb] = (cb < 32) ? B2[(k0 + rb) * H2d + cb]
                                   : B3[(k0 + rb) * H2d + cb - 32];
        }
        __syncthreads();
        #pragma unroll
        for (int k = 0; k < 16; k++) {
            float4 a4 = *reinterpret_cast<const float4*>(&As[k][ty << 2]);
            float4 b4 = *reinterpret_cast<const float4*>(&Bs[k][tx << 2]);
            float a[4] = {a4.x, a4.y, a4.z, a4.w};
            float b[4] = {b4.x, b4.y, b4.z, b4.w};
            #pragma unroll
            for (int u = 0; u < 4; u++)
                #pragma unroll
                for (int v = 0; v < 4; v++)
                    acc[u][v] += a[u] * b[v];
        }
        __syncthreads();
    }
    #pragma unroll
    for (int u = 0; u < 4; u++) {
        int row = bm + (ty << 2) + u;
        #pragma unroll
        for (int v = 0; v < 4; v++) {
            int col = (tx << 2) + v;
            if (col < 32) C2[(size_t)row * H2d + col] = acc[u][v];
            else          C3[(size_t)row * H2d + col - 32] = acc[u][v];
        }
    }
}

// ------------------------- merged f/g projections --------------------------
__global__ void fg2_kernel(const float* __restrict__ Wh_c, const float* __restrict__ asrc_c,
                           const float* __restrict__ adst_c, float* __restrict__ f_c,
                           float* __restrict__ g_c,
                           const float* __restrict__ Wh_t, const float* __restrict__ asrc_t,
                           const float* __restrict__ adst_t, float* __restrict__ f_t,
                           float* __restrict__ g_t) {
    int gw = (blockIdx.x * blockDim.x + threadIdx.x) >> 5;
    int lane = threadIdx.x & 31;
    const float* Wh; const float* asrc; const float* adst; float* f; float* g;
    int n;
    if (gw < NHd * Nn) {
        Wh = Wh_c; asrc = asrc_c; adst = adst_c; f = f_c; g = g_c; n = Nn;
    } else {
        gw -= NHd * Nn;
        if (gw >= NHd * Tt) return;
        Wh = Wh_t; asrc = asrc_t; adst = adst_t; f = f_t; g = g_t; n = Tt;
    }
    int h = gw / n, i = gw - h * n;
    const float* wp = Wh + ((size_t)h * n + i) * Dd;
    const float* as = asrc + h * Dd;
    const float* ad = adst + h * Dd;
    float accf = 0.0f, accg = 0.0f;
    #pragma unroll
    for (int c = 0; c < Dd / 32; c++) {
        float v = wp[lane + 32 * c];
        accf += v * as[lane + 32 * c];
        accg += v * ad[lane + 32 * c];
    }
    #pragma unroll
    for (int o = 16; o; o >>= 1) {
        accf += __shfl_down_sync(0xffffffffu, accf, o);
        accg += __shfl_down_sync(0xffffffffu, accg, o);
    }
    if (lane == 0) { f[gw] = accf; g[gw] = accg; }
}

// ------------------------- merged warp-per-(i,h) GAT attention (raw out) ---
__global__ void __launch_bounds__(256) gat_attn2_kernel(
    const float* __restrict__ Wh_c, const float* __restrict__ f_c,
    const float* __restrict__ g_c, const int* __restrict__ nbr_c,
    const int* __restrict__ cnt_c, float* __restrict__ hcatc,
    const float* __restrict__ Wh_t, const float* __restrict__ f_t,
    const float* __restrict__ g_t, const int* __restrict__ nbr_t,
    const int* __restrict__ cnt_t, float* __restrict__ hcatt) {
    int w = threadIdx.x >> 5, lane = threadIdx.x & 31;
    int gw = blockIdx.x * 8 + w;
    const float* Wh; const float* f; const float* g;
    const int* nbr; const int* cnt; float* hcat;
    int n;
    if (gw < Nn * NHd) {
        Wh = Wh_c; f = f_c; g = g_c; nbr = nbr_c; cnt = cnt_c;
        hcat = hcatc; n = Nn;
    } else {
        gw -= Nn * NHd;
        Wh = Wh_t; f = f_t; g = g_t; nbr = nbr_t; cnt = cnt_t;
        hcat = hcatt; n = Tt;
    }
    int i = gw >> 2, h = gw & 3;
    __shared__ int   sj[8][CAP];
    __shared__ float sw[8][CAP];
    int c = cnt[i];
    const int* jb = nbr + i * CAP;
    float fi = f[h * n + i];
    float m = -1e30f;
    for (int k = lane; k < c; k += 32) {
        int j = jb[k];
        sj[w][k] = j;
        float s = fi + g[h * n + j];
        s = (s >= 0.0f) ? s : LRELU_ALPHA * s;
        sw[w][k] = s;
        m = fmaxf(m, s);
    }
    #pragma unroll
    for (int o = 16; o; o >>= 1) m = fmaxf(m, __shfl_xor_sync(0xffffffffu, m, o));
    __syncwarp();
    float sum = 0.0f;
    for (int k = lane; k < c; k += 32) {
        float e = expf(sw[w][k] - m);
        sw[w][k] = e;
        sum += e;
    }
    #pragma unroll
    for (int o = 16; o; o >>= 1) sum += __shfl_xor_sync(0xffffffffu, sum, o);
    float dinv = 1.0f / sum;
    __syncwarp();
    const float* base = Wh + (size_t)h * n * Dd;
    float acc[8] = {};
    int k = 0;
    for (; k + 2 <= c; k += 2) {
        float w0 = sw[w][k], w1 = sw[w][k + 1];
        const float* r0 = base + (size_t)sj[w][k] * Dd + lane;
        const float* r1 = base + (size_t)sj[w][k + 1] * Dd + lane;
        #pragma unroll
        for (int ch = 0; ch < 8; ch++) {
            acc[ch] += w0 * __ldg(r0 + ch * 32);
            acc[ch] += w1 * __ldg(r1 + ch * 32);
        }
    }
    if (k < c) {
        float w0 = sw[w][k];
        const float* r0 = base + (size_t)sj[w][k] * Dd + lane;
        #pragma unroll
        for (int ch = 0; ch < 8; ch++) acc[ch] += w0 * __ldg(r0 + ch * 32);
    }
    size_t obase = (size_t)i * (NHd * Dd) + h * Dd + lane;
    #pragma unroll
    for (int ch = 0; ch < 8; ch++) {
        float v = acc[ch] * dinv;
        hcat[obase + ch * 32] = (v > 0.0f) ? v : expm1f(v);
    }
}

// ------------------------- sparse adj @ X, optional ReLU -------------------
__global__ void spmm_kernel(const int* __restrict__ nbr, const float* __restrict__ val,
                            const int* __restrict__ cnt, const float* __restrict__ X,
                            float* __restrict__ Y, int ncols, int do_relu) {
    int i = blockIdx.x;
    int t = threadIdx.x;
    int c = cnt[i];
    const int* jb = nbr + i * CAP;
    const float* vb = val + i * CAP;
    float a0 = 0.0f, a1 = 0.0f, a2 = 0.0f, a3 = 0.0f;
    int k = 0;
    for (; k + 4 <= c; k += 4) {
        a0 += vb[k]     * __ldg(X + (size_t)jb[k]     * ncols + t);
        a1 += vb[k + 1] * __ldg(X + (size_t)jb[k + 1] * ncols + t);
        a2 += vb[k + 2] * __ldg(X + (size_t)jb[k + 2] * ncols + t);
        a3 += vb[k + 3] * __ldg(X + (size_t)jb[k + 3] * ncols + t);
    }
    for (; k < c; k++)
        a0 += vb[k] * __ldg(X + (size_t)jb[k] * ncols + t);
    float acc = (a0 + a1) + (a2 + a3);
    if (do_relu) acc = fmaxf(acc, 0.0f);
    Y[(size_t)i * ncols + t] = acc;
}

// ------------------------- fused mu/logvar spmm ----------------------------
__global__ void spmm2_kernel(const int* __restrict__ nbr, const float* __restrict__ val,
                             const int* __restrict__ cnt, const float* __restrict__ X2,
                             const float* __restrict__ X3, float* __restrict__ mu,
                             float* __restrict__ logvar, float* __restrict__ mu_h,
                             float* __restrict__ mu_l) {
    int i = blockIdx.x;
    int t = threadIdx.x;
    int sel = t >> 5, col = t & 31;
    const float* X = sel ? X3 : X2;
    int c = cnt[i];
    const int* jb = nbr + i * CAP;
    const float* vb = val + i * CAP;
    float a0 = 0.0f, a1 = 0.0f, a2 = 0.0f, a3 = 0.0f;
    int k = 0;
    for (; k + 4 <= c; k += 4) {
        a0 += vb[k]     * __ldg(X + (size_t)jb[k]     * H2d + col);
        a1 += vb[k + 1] * __ldg(X + (size_t)jb[k + 1] * H2d + col);
        a2 += vb[k + 2] * __ldg(X + (size_t)jb[k + 2] * H2d + col);
        a3 += vb[k + 3] * __ldg(X + (size_t)jb[k + 3] * H2d + col);
    }
    for (; k < c; k++)
        a0 += vb[k] * __ldg(X + (size_t)jb[k] * H2d + col);
    float v = (a0 + a1) + (a2 + a3);
    size_t idx = (size_t)i * H2d + col;
    if (sel == 0) {
        mu[idx] = v;
        split_store(v, mu_h, mu_l, idx);
    } else {
        logvar[idx] = v;
    }
}

#define SYM(p, s) cudaGetSymbolAddress((void**)&p, s)

extern "C" void kernel_launch(void* const* d_in, const int* in_sizes, int n_in,
                              void* d_out, int out_size) {
    const float* x        = (const float*)d_in[0];
    const float* adj      = (const float*)d_in[1];
    const float* t_x      = (const float*)d_in[2];
    const float* t_adj    = (const float*)d_in[3];
    const float* tfidf    = (const float*)d_in[4];
    const float* gat_W    = (const float*)d_in[5];
    const float* gat_asrc = (const float*)d_in[6];
    const float* gat_adst = (const float*)d_in[7];
    const float* gat_fcW  = (const float*)d_in[8];
    const float* gat_fcb  = (const float*)d_in[9];
    const float* t_W      = (const float*)d_in[10];
    const float* t_asrc   = (const float*)d_in[11];
    const float* t_adst   = (const float*)d_in[12];
    const float* t_fcW    = (const float*)d_in[13];
    const float* t_fcb    = (const float*)d_in[14];
    const float* fus_W    = (const float*)d_in[15];
    const float* fus_b    = (const float*)d_in[16];
    const float* gc1_W    = (const float*)d_in[17];
    const float* gc2_W    = (const float*)d_in[18];
    const float* gc3_W    = (const float*)d_in[19];

    float* out    = (float*)d_out;
    float* mu     = out + (size_t)Nn * Nn;
    float* logvar = mu + (size_t)Nn * H2d;

    float *Wh_c, *Wh_t, *f_c, *g_c, *f_t, *g_t, *val_c, *val_t;
    float *tmp1, *h1, *tmp2a, *tmp2b, *P0, *P1, *P2;
    int *nbr_c, *cnt_c, *nbr_t, *cnt_t;
    float *gatW_h, *gatW_l, *tW_h, *tW_l, *fcWc_h, *fcWc_l, *fcWt_h, *fcWt_l;
    float *fusW_h, *fusW_l, *gc1W_h, *gc1W_l;
    float *hcatc, *hcatt, *gtext_h, *gtext_l;
    float *fused, *fusion, *mu_h, *mu_l;
    SYM(Wh_c, g_Wh_c);  SYM(Wh_t, g_Wh_t);
    SYM(f_c, g_f_c);    SYM(g_c, g_g_c);   SYM(f_t, g_f_t);  SYM(g_t, g_g_t);
    SYM(nbr_c, g_nbr_c); SYM(val_c, g_val_c); SYM(cnt_c, g_cnt_c);
    SYM(nbr_t, g_nbr_t); SYM(val_t, g_val_t); SYM(cnt_t, g_cnt_t);
    SYM(tmp1, g_tmp1); SYM(h1, g_h1); SYM(tmp2a, g_tmp2a); SYM(tmp2b, g_tmp2b);
    SYM(P0, g_P0); SYM(P1, g_P1); SYM(P2, g_P2);
    SYM(gatW_h, g_gatW_h); SYM(gatW_l, g_gatW_l);
    SYM(tW_h, g_tW_h);     SYM(tW_l, g_tW_l);
    SYM(fcWc_h, g_fcWc_h); SYM(fcWc_l, g_fcWc_l);
    SYM(fcWt_h, g_fcWt_h); SYM(fcWt_l, g_fcWt_l);
    SYM(fusW_h, g_fusW_h); SYM(fusW_l, g_fusW_l);
    SYM(gc1W_h, g_gc1W_h); SYM(gc1W_l, g_gc1W_l);
    SYM(hcatc, g_hcatc); SYM(hcatt, g_hcatt);
    SYM(gtext_h, g_gtext_h); SYM(gtext_l, g_gtext_l);
    SYM(fused, g_fused); SYM(fusion, g_fusion);
    SYM(mu_h, g_mu_h); SYM(mu_l, g_mu_l);

    // 0) split WEIGHTS ONLY into tf32 hi/lo planes
    {
        SplitJobs6 jobs;
        jobs.j[0] = { gat_W,   gatW_h, gatW_l, NHd * Dd * Dd / 4 };
        jobs.j[1] = { t_W,     tW_h,   tW_l,   NHd * Dd * Dd / 4 };
        jobs.j[2] = { gat_fcW, fcWc_h, fcWc_l, NHd * Dd * Dd / 4 };
        jobs.j[3] = { t_fcW,   fcWt_h, fcWt_l, NHd * Dd * Dd / 4 };
        jobs.j[4] = { fus_W,   fusW_h, fusW_l, Dd * Dd / 4 };
        jobs.j[5] = { gc1_W,   gc1W_h, gc1W_l, Dd * H1d / 4 };
        split_all_kernel<<<dim3(128, 6), 256>>>(jobs);
    }

    // 1) both adjacencies -> CSR (one launch)
    build_csr2_kernel<<<Nn + Tt, 256>>>(adj, t_adj, nbr_c, val_c, cnt_c,
                                        nbr_t, val_t, cnt_t);

    // 2) per-head Wh for BOTH graphs, ONE launch, RAW A (x / t_x)
    {
        ZJobs8 jb;
        for (int h = 0; h < NHd; h++) {
            jb.z[h] = { x, nullptr,
                        gatW_h + (size_t)h * Dd * Dd, gatW_l + (size_t)h * Dd * Dd,
                        Wh_c + (size_t)h * Nn * Dd, nullptr, nullptr, nullptr,
                        Nn, Dd, Dd, Dd, Dd };
            jb.z[NHd + h] = { t_x, nullptr,
                        tW_h + (size_t)h * Dd * Dd, tW_l + (size_t)h * Dd * Dd,
                        Wh_t + (size_t)h * Tt * Dd, nullptr, nullptr, nullptr,
                        Tt, Dd, Dd, Dd, Dd };
        }
        mma_gemm_jobs_kernel<true><<<dim3(Dd / BNt, Nn / BMt, 8), 256>>>(jb);
    }

    // 3) attention projections f,g (both graphs)
    {
        int warps = NHd * (Nn + Tt);
        fg2_kernel<<<(warps * 32 + 255) / 256, 256>>>(
            Wh_c, gat_asrc, gat_adst, f_c, g_c,
            Wh_t, t_asrc, t_adst, f_t, g_t);
    }

    // 4) sparse attention + aggregation + ELU (both graphs) -> RAW hcat
    gat_attn2_kernel<<<(Nn + Tt) * NHd / 8, 256>>>(
        Wh_c, f_c, g_c, nbr_c, cnt_c, hcatc,
        Wh_t, f_t, g_t, nbr_t, cnt_t, hcatt);

    // 5) both fc GEMMs, split-K, ONE launch (6 z-jobs, RAW A = hcat)
    {
        ZJobs8 jb;
        for (int c = 0; c < 2; c++)
            jb.z[c] = { hcatc + (size_t)c * 512, nullptr,
                        fcWc_h + (size_t)c * 512 * Dd, fcWc_l + (size_t)c * 512 * Dd,
                        P0 + (size_t)c * Nn * Dd, nullptr, nullptr, nullptr,
                        Nn, Dd, 512, NHd * Dd, Dd };
        for (int c = 0; c < 4; c++)
            jb.z[2 + c] = { hcatt + (size_t)c * 256, nullptr,
                        fcWt_h + (size_t)c * 256 * Dd, fcWt_l + (size_t)c * 256 * Dd,
                        P1 + (size_t)c * Tt * Dd, nullptr, nullptr, nullptr,
                        Tt, Dd, 256, NHd * Dd, Dd };
        for (int c = 6; c < 8; c++) jb.z[c] = jb.z[0];  // unused
        mma_gemm_jobs_kernel<true><<<dim3(Dd / BNt, Nn / BMt, 6), 256>>>(jb);
    }

    // 5b) reduce fc_t partials -> gtext hi/lo (+bias)  (B operand: keep split)
    reduce4_split_kernel<<<(Tt * Dd / 4 + 255) / 256, 256>>>(
        P1, t_fcb, gtext_h, gtext_l, Tt * Dd / 4, Dd / 4);

    // 6) c_text = tfidf^T @ gat_text — split-K 4 x 512, RAW A (tfidf)
    {
        dim3 grid(Dd / BNt, Nn / BMt, 4);
        mma_gemm_kernel<true, false, true><<<grid, 256>>>(
            tfidf, nullptr, gtext_h, gtext_l, nullptr, P2, nullptr, nullptr,
            Nn, Dd, 512, Nn, Dd,
            (size_t)512 * Nn, (size_t)512 * Dd, (size_t)Nn * Dd);
    }

    // 7) fused reduce: concept(P0)+bias, ctext(P2), gate -> RAW fused
    fuse_reduce_kernel<<<(Nn * Dd / 4 + 255) / 256, 256>>>(
        P0, P2, gat_fcb, fused, Nn * Dd / 4, Dd / 4);

    // 7b) fusion = fused @ fus_W + fus_b  (RAW A, RAW output)
    {
        dim3 grid(Dd / BNt, Nn / BMt, 1);
        mma_gemm_kernel<false, false, true><<<grid, 256>>>(
            fused, nullptr, fusW_h, fusW_l, fus_b, fusion, nullptr, nullptr,
            Nn, Dd, Dd, Dd, Dd, 0, 0, 0);
    }

    // 8) GCN encoder (RAW A = fusion)
    {
        dim3 grid(H1d / BNt, Nn / BMt, 1);
        mma_gemm_kernel<false, false, true><<<grid, 256>>>(
            fusion, nullptr, gc1W_h, gc1W_l, nullptr, tmp1, nullptr, nullptr,
            Nn, H1d, Dd, Dd, H1d, 0, 0, 0);
    }
    spmm_kernel<<<Nn, H1d>>>(nbr_c, val_c, cnt_c, tmp1, h1, H1d, 1);

    gc23_kernel<<<Nn / 64, 256>>>(h1, gc2_W, gc3_W, tmp2a, tmp2b);
    spmm2_kernel<<<Nn, 64>>>(nbr_c, val_c, cnt_c, tmp2a, tmp2b, mu, logvar, mu_h, mu_l);

    // 9) recon = mu @ mu^T  (mu planes tiny; keep pre-split)
    {
        dim3 grid(Nn / BNt, Nn / BMt, 1);
        mma_gemm_kernel<false, true, false><<<grid, 256>>>(
            mu_h, mu_l, mu_h, mu_l, nullptr, out, nullptr, nullptr,
            Nn, Nn, H2d, H2d, H2d, 0, 0, 0);
    }
}